// round 1
// baseline (speedup 1.0000x reference)
#include <cuda_runtime.h>
#include <cuda_bf16.h>
#include <cstdint>

// ---------------------------------------------------------------------------
// Problem constants
// ---------------------------------------------------------------------------
#define BATCH   4
#define SEQ     4096
#define TOKENS  (BATCH * SEQ)        // 16384
#define DMODEL  1024
#define DINNER  1024
#define NHEADS  16
#define HDIM    64                   // HEAD_DIM
#define DSTATE  16
#define DTRANK  16
#define CHUNK   64
#define NCHUNK  (SEQ / CHUNK)        // 64
#define PROJ    2576                 // 2*DINNER + 2*DSTATE*NHEADS + DTRANK

// proj column offsets
#define OFF_XP   0
#define OFF_Z    1024
#define OFF_B    2048
#define OFF_C    2304
#define OFF_DT   2560

// ---------------------------------------------------------------------------
// Scratch (device globals; no allocation allowed)
// ---------------------------------------------------------------------------
__device__ float g_proj[(size_t)TOKENS * PROJ];          // 169 MB
__device__ float g_dt[(size_t)TOKENS * NHEADS];          // softplus(dt)
__device__ float g_dacs[(size_t)TOKENS * NHEADS];        // cumsum(dA) within chunk
__device__ float g_y[(size_t)TOKENS * DINNER];           // y (intra, then +cross+skip)
__device__ float g_yg[(size_t)TOKENS * DINNER];          // gated/normed y
__device__ float g_cs[(size_t)BATCH * NCHUNK * NHEADS * DSTATE * HDIM];  // chunk_state
__device__ float g_hs[(size_t)BATCH * NCHUNK * NHEADS * DSTATE * HDIM];  // h entering chunk
__device__ float g_cdecay[(size_t)BATCH * NCHUNK * NHEADS];

// ---------------------------------------------------------------------------
// GEMM: C[M,N] = A[M,K] * B[N,K]^T   (both row-major, K contiguous)
// 128x128x16 tile, 256 threads, 8x8 per thread (4+4 split for LDS.128)
// M must be a multiple of 128, K a multiple of 16; N guarded.
// ---------------------------------------------------------------------------
__global__ void __launch_bounds__(256, 2)
gemm_nt(const float* __restrict__ A, const float* __restrict__ B,
        float* __restrict__ C, int M, int N, int K)
{
    constexpr int BK = 16;
    __shared__ float As[BK][128 + 4];
    __shared__ float Bs[BK][128 + 4];

    const int tid = threadIdx.x;
    const int tx  = tid & 15;
    const int ty  = tid >> 4;
    const int bm  = blockIdx.y * 128;
    const int bn  = blockIdx.x * 128;

    float acc[8][8];
#pragma unroll
    for (int i = 0; i < 8; ++i)
#pragma unroll
        for (int j = 0; j < 8; ++j) acc[i][j] = 0.f;

    for (int k0 = 0; k0 < K; k0 += BK) {
#pragma unroll
        for (int it = 0; it < 2; ++it) {
            int f   = tid + it * 256;           // 0..511
            int row = f >> 2;                   // 0..127
            int kv  = (f & 3) << 2;             // 0,4,8,12
            float4 va = *reinterpret_cast<const float4*>(
                A + (size_t)(bm + row) * K + k0 + kv);
            As[kv + 0][row] = va.x; As[kv + 1][row] = va.y;
            As[kv + 2][row] = va.z; As[kv + 3][row] = va.w;

            float4 vb = make_float4(0.f, 0.f, 0.f, 0.f);
            if (bn + row < N)
                vb = *reinterpret_cast<const float4*>(
                    B + (size_t)(bn + row) * K + k0 + kv);
            Bs[kv + 0][row] = vb.x; Bs[kv + 1][row] = vb.y;
            Bs[kv + 2][row] = vb.z; Bs[kv + 3][row] = vb.w;
        }
        __syncthreads();

#pragma unroll
        for (int kk = 0; kk < BK; ++kk) {
            float ra[8], rb[8];
#pragma unroll
            for (int i = 0; i < 4; ++i) {
                ra[i]     = As[kk][ty * 4 + i];
                ra[4 + i] = As[kk][64 + ty * 4 + i];
            }
#pragma unroll
            for (int j = 0; j < 4; ++j) {
                rb[j]     = Bs[kk][tx * 4 + j];
                rb[4 + j] = Bs[kk][64 + tx * 4 + j];
            }
#pragma unroll
            for (int i = 0; i < 8; ++i)
#pragma unroll
                for (int j = 0; j < 8; ++j)
                    acc[i][j] = fmaf(ra[i], rb[j], acc[i][j]);
        }
        __syncthreads();
    }

#pragma unroll
    for (int i = 0; i < 8; ++i) {
        int m = bm + ((i < 4) ? (ty * 4 + i) : (64 + ty * 4 + (i - 4)));
#pragma unroll
        for (int j = 0; j < 8; ++j) {
            int n = bn + ((j < 4) ? (tx * 4 + j) : (64 + tx * 4 + (j - 4)));
            if (n < N) C[(size_t)m * N + n] = acc[i][j];
        }
    }
}

// ---------------------------------------------------------------------------
// dt = softplus(dt_low @ dt_W^T + dt_b)     (one thread per (t,h))
// ---------------------------------------------------------------------------
__global__ void __launch_bounds__(256)
dt_kernel(const float* __restrict__ dt_W, const float* __restrict__ dt_b)
{
    int idx = blockIdx.x * 256 + threadIdx.x;     // t*16 + h
    if (idx >= TOKENS * NHEADS) return;
    int t = idx >> 4;
    int h = idx & 15;
    const float* row = g_proj + (size_t)t * PROJ + OFF_DT;
    float acc = dt_b[h];
#pragma unroll
    for (int r = 0; r < DTRANK; ++r)
        acc = fmaf(row[r], dt_W[h * DTRANK + r], acc);
    // softplus (stable)
    float sp = (acc > 20.f) ? acc : log1pf(expf(acc));
    g_dt[idx] = sp;
}

// ---------------------------------------------------------------------------
// Intra-chunk: scores -> y_intra, chunk_state, chunk_decay, dAcs
// one block per (b, c, h); 256 threads
// ---------------------------------------------------------------------------
__global__ void __launch_bounds__(256)
intra_kernel(const float* __restrict__ A_log)
{
    const int bid = blockIdx.x;        // (b*NCHUNK + c)*NHEADS + h
    const int h   = bid & 15;
    const int bc  = bid >> 4;          // b*NCHUNK + c
    const int t0  = bc * CHUNK;        // token base (S = NCHUNK*CHUNK)
    const int tid = threadIdx.x;

    __shared__ float xs[64][65];
    __shared__ float sc[64][65];
    __shared__ float Bsh[64][17];
    __shared__ float Csh[64][17];
    __shared__ float dts[64];
    __shared__ float dacs[64];
    __shared__ float wk[64];

    // loads
    for (int idx = tid; idx < 64 * 64; idx += 256) {
        int k = idx >> 6, p = idx & 63;
        xs[k][p] = g_proj[(size_t)(t0 + k) * PROJ + OFF_XP + h * HDIM + p];
    }
    for (int idx = tid; idx < 64 * 16; idx += 256) {
        int k = idx >> 4, n = idx & 15;
        Bsh[k][n] = g_proj[(size_t)(t0 + k) * PROJ + OFF_B + h * DSTATE + n];
        Csh[k][n] = g_proj[(size_t)(t0 + k) * PROJ + OFF_C + h * DSTATE + n];
    }
    if (tid < 64) dts[tid] = g_dt[(size_t)(t0 + tid) * NHEADS + h];
    __syncthreads();

    if (tid == 0) {
        float A = -expf(A_log[h]);
        float s = 0.f;
        for (int k = 0; k < 64; ++k) { s += dts[k] * A; dacs[k] = s; }
    }
    __syncthreads();

    // scores[i][j] = (C_i . B_j) * exp(dacs[i]-dacs[j]) * dt[j]  (j<=i)
    for (int idx = tid; idx < 64 * 64; idx += 256) {
        int i = idx >> 6, j = idx & 63;
        float v = 0.f;
        if (j <= i) {
            float d = 0.f;
#pragma unroll
            for (int n = 0; n < 16; ++n)
                d = fmaf(Csh[i][n], Bsh[j][n], d);
            v = d * expf(dacs[i] - dacs[j]) * dts[j];
        }
        sc[i][j] = v;
    }
    // wk[k] = dt[k]*exp(dacs[63]-dacs[k]); dAcs to global; chunk_decay
    __syncthreads();
    if (tid < 64) {
        wk[tid] = dts[tid] * expf(dacs[63] - dacs[tid]);
        g_dacs[(size_t)(t0 + tid) * NHEADS + h] = dacs[tid];
    }
    if (tid == 0) g_cdecay[bid] = expf(dacs[63]);
    __syncthreads();

    // y_intra[i][p] = sum_j sc[i][j] * xs[j][p]
    {
        int i  = tid >> 2;
        int p0 = (tid & 3) * 16;
        float acc[16];
#pragma unroll
        for (int pp = 0; pp < 16; ++pp) acc[pp] = 0.f;
        for (int j = 0; j < 64; ++j) {
            float s = sc[i][j];
#pragma unroll
            for (int pp = 0; pp < 16; ++pp)
                acc[pp] = fmaf(s, xs[j][p0 + pp], acc[pp]);
        }
        float* yrow = g_y + (size_t)(t0 + i) * DINNER + h * HDIM;
#pragma unroll
        for (int pp = 0; pp < 16; ++pp) yrow[p0 + pp] = acc[pp];
    }

    // chunk_state[n][p] = sum_k B[k][n] * wk[k] * x[k][p]
    for (int idx = tid; idx < DSTATE * HDIM; idx += 256) {
        int n = idx >> 6, p = idx & 63;
        float acc = 0.f;
        for (int k = 0; k < 64; ++k)
            acc = fmaf(Bsh[k][n] * wk[k], xs[k][p], acc);
        g_cs[(size_t)bid * (DSTATE * HDIM) + idx] = acc;
    }
}

// ---------------------------------------------------------------------------
// Sequential scan over chunks: h_states[c] = h before chunk c
// one block per (b, h); 256 threads x 4 elements of [N=16, P=64]
// ---------------------------------------------------------------------------
__global__ void __launch_bounds__(256)
scan_kernel()
{
    const int bh  = blockIdx.x;       // b*NHEADS + h
    const int b   = bh >> 4;
    const int h   = bh & 15;
    const int tid = threadIdx.x;

    float hv[4] = {0.f, 0.f, 0.f, 0.f};
    for (int c = 0; c < NCHUNK; ++c) {
        int    chid = (b * NCHUNK + c) * NHEADS + h;
        size_t base = (size_t)chid * (DSTATE * HDIM);
        float  d    = g_cdecay[chid];
#pragma unroll
        for (int j = 0; j < 4; ++j) {
            int e = tid + j * 256;
            g_hs[base + e] = hv[j];
            hv[j] = fmaf(d, hv[j], g_cs[base + e]);
        }
    }
}

// ---------------------------------------------------------------------------
// Cross-chunk: y += exp(dacs[i]) * (C_i @ h_state) + D[h] * x
// one block per (b, c, h); 256 threads
// ---------------------------------------------------------------------------
__global__ void __launch_bounds__(256)
cross_kernel(const float* __restrict__ D_param)
{
    const int bid = blockIdx.x;
    const int h   = bid & 15;
    const int bc  = bid >> 4;
    const int t0  = bc * CHUNK;
    const int tid = threadIdx.x;

    __shared__ float hs[16][65];
    __shared__ float Csh[64][17];
    __shared__ float dacs[64];

    for (int idx = tid; idx < DSTATE * HDIM; idx += 256) {
        int n = idx >> 6, p = idx & 63;
        hs[n][p] = g_hs[(size_t)bid * (DSTATE * HDIM) + idx];
    }
    for (int idx = tid; idx < 64 * 16; idx += 256) {
        int k = idx >> 4, n = idx & 15;
        Csh[k][n] = g_proj[(size_t)(t0 + k) * PROJ + OFF_C + h * DSTATE + n];
    }
    if (tid < 64) dacs[tid] = g_dacs[(size_t)(t0 + tid) * NHEADS + h];
    __syncthreads();

    int i  = tid >> 2;
    int p0 = (tid & 3) * 16;
    float ci[16];
#pragma unroll
    for (int n = 0; n < 16; ++n) ci[n] = Csh[i][n];
    float e  = expf(dacs[i]);
    float dp = D_param[h];

    size_t t = (size_t)(t0 + i);
    const float* xrow = g_proj + t * PROJ + OFF_XP + h * HDIM;
    float* yrow = g_y + t * DINNER + h * HDIM;
#pragma unroll
    for (int pp = 0; pp < 16; ++pp) {
        int p = p0 + pp;
        float a = 0.f;
#pragma unroll
        for (int n = 0; n < 16; ++n)
            a = fmaf(ci[n], hs[n][p], a);
        yrow[p] = yrow[p] + e * a + dp * xrow[p];
    }
}

// ---------------------------------------------------------------------------
// RMS norm + SiLU gate: yg = y / rms(y) * norm_w * silu(z)
// one block per token
// ---------------------------------------------------------------------------
__global__ void __launch_bounds__(256)
norm_kernel(const float* __restrict__ norm_w)
{
    const int t   = blockIdx.x;
    const int tid = threadIdx.x;

    float4 v = reinterpret_cast<const float4*>(g_y + (size_t)t * DINNER)[tid];
    float ss = v.x * v.x + v.y * v.y + v.z * v.z + v.w * v.w;
#pragma unroll
    for (int off = 16; off > 0; off >>= 1)
        ss += __shfl_xor_sync(0xffffffffu, ss, off);

    __shared__ float red[8];
    __shared__ float s_inv;
    if ((tid & 31) == 0) red[tid >> 5] = ss;
    __syncthreads();
    if (tid == 0) {
        float s = 0.f;
#pragma unroll
        for (int i = 0; i < 8; ++i) s += red[i];
        s_inv = rsqrtf(s * (1.f / DINNER) + 1e-6f);
    }
    __syncthreads();
    float inv = s_inv;

    const float* zrow = g_proj + (size_t)t * PROJ + OFF_Z;
    int c = tid * 4;
    float4 z4 = *reinterpret_cast<const float4*>(zrow + c);
    float4 w4 = *reinterpret_cast<const float4*>(norm_w + c);
    float4 o;
    o.x = v.x * inv * w4.x * (z4.x / (1.f + expf(-z4.x)));
    o.y = v.y * inv * w4.y * (z4.y / (1.f + expf(-z4.y)));
    o.z = v.z * inv * w4.z * (z4.z / (1.f + expf(-z4.z)));
    o.w = v.w * inv * w4.w * (z4.w / (1.f + expf(-z4.w)));
    reinterpret_cast<float4*>(g_yg + (size_t)t * DINNER)[tid] = o;
}

// ---------------------------------------------------------------------------
// Launch
// Inputs: x, W_in, dt_W, dt_b, A_log, D_param, W_out, norm_w
// ---------------------------------------------------------------------------
extern "C" void kernel_launch(void* const* d_in, const int* in_sizes, int n_in,
                              void* d_out, int out_size)
{
    const float* x      = (const float*)d_in[0];
    const float* W_in   = (const float*)d_in[1];
    const float* dt_W   = (const float*)d_in[2];
    const float* dt_b   = (const float*)d_in[3];
    const float* A_log  = (const float*)d_in[4];
    const float* D_par  = (const float*)d_in[5];
    const float* W_out  = (const float*)d_in[6];
    const float* norm_w = (const float*)d_in[7];
    float* out = (float*)d_out;

    float* proj_ptr = nullptr;
    float* yg_ptr   = nullptr;
    cudaGetSymbolAddress((void**)&proj_ptr, g_proj);
    cudaGetSymbolAddress((void**)&yg_ptr,   g_yg);

    // 1) proj = x @ W_in^T    [16384, 2576]
    {
        dim3 grid((PROJ + 127) / 128, TOKENS / 128);
        gemm_nt<<<grid, 256>>>(x, W_in, proj_ptr, TOKENS, PROJ, DMODEL);
    }
    // 2) dt
    dt_kernel<<<(TOKENS * NHEADS) / 256, 256>>>(dt_W, dt_b);
    // 3) intra-chunk
    intra_kernel<<<BATCH * NCHUNK * NHEADS, 256>>>(A_log);
    // 4) chunk scan
    scan_kernel<<<BATCH * NHEADS, 256>>>();
    // 5) cross-chunk + skip
    cross_kernel<<<BATCH * NCHUNK * NHEADS, 256>>>(D_par);
    // 6) RMS norm + gate
    norm_kernel<<<TOKENS, 256>>>(norm_w);
    // 7) out = yg @ W_out^T   [16384, 1024]
    {
        dim3 grid(DMODEL / 128, TOKENS / 128);
        gemm_nt<<<grid, 256>>>(yg_ptr, W_out, out, TOKENS, DMODEL, DINNER);
    }
}

// round 3
// speedup vs baseline: 1.9759x; 1.9759x over previous
#include <cuda_runtime.h>
#include <cuda_bf16.h>
#include <cstdint>

// ---------------------------------------------------------------------------
// Problem constants
// ---------------------------------------------------------------------------
#define BATCH   4
#define SEQ     4096
#define TOKENS  (BATCH * SEQ)        // 16384
#define DMODEL  1024
#define DINNER  1024
#define NHEADS  16
#define HDIM    64
#define DSTATE  16
#define DTRANK  16
#define CHUNK   64
#define NCHUNK  (SEQ / CHUNK)        // 64
#define PROJ    2576
#define PROJPAD 2688                 // 21 * 128

#define OFF_XP   0
#define OFF_Z    1024
#define OFF_B    2048
#define OFF_C    2304
#define OFF_DT   2560

// tcgen05 is an arch-SPECIFIC feature: only emit it in the sm_103a/f passes.
#if defined(__CUDA_ARCH_FEAT_SM103_ALL) || \
    (defined(__CUDA_ARCH_FAMILY_SPECIFIC__) && __CUDA_ARCH_FAMILY_SPECIFIC__ >= 1000) || \
    (defined(__CUDA_ARCH_SPECIFIC__) && __CUDA_ARCH_SPECIFIC__ >= 1000)
#define HAS_TCGEN05 1
#else
#define HAS_TCGEN05 0
#endif

// ---------------------------------------------------------------------------
// PTX helpers (guarded)
// ---------------------------------------------------------------------------
#if HAS_TCGEN05
__device__ __forceinline__ uint32_t smem_to_u32(const void* p) {
    uint32_t a;
    asm("{ .reg .u64 t; cvta.to.shared.u64 t, %1; cvt.u32.u64 %0, t; }" : "=r"(a) : "l"(p));
    return a;
}
__device__ __forceinline__ uint32_t elect_one_pred() {
    uint32_t pred;
    asm volatile("{\n\t.reg .pred p;\n\telect.sync _|p, 0xFFFFFFFF;\n\tselp.b32 %0, 1, 0, p;\n\t}" : "=r"(pred));
    return pred;
}
#define TCGEN05_ALLOC(smem_result_addr, nCols) \
    asm volatile("tcgen05.alloc.cta_group::1.sync.aligned.shared::cta.b32 [%0], %1;" \
        :: "r"((uint32_t)(smem_result_addr)), "r"((uint32_t)(nCols)) : "memory")
#define TCGEN05_DEALLOC(tmem_addr, nCols) \
    asm volatile("tcgen05.dealloc.cta_group::1.sync.aligned.b32 %0, %1;" :: "r"(tmem_addr), "r"((uint32_t)(nCols)))
#define TCGEN05_RELINQUISH() \
    asm volatile("tcgen05.relinquish_alloc_permit.cta_group::1.sync.aligned;")
#define TCGEN05_COMMIT(mbar) \
    asm volatile("tcgen05.commit.cta_group::1.mbarrier::arrive::one.shared::cluster.b64 [%0];" \
        :: "r"((uint32_t)(mbar)) : "memory")
#define TCGEN05_FENCE_AFTER()  asm volatile("tcgen05.fence::after_thread_sync;" ::: "memory")
#define TCGEN05_FENCE_BEFORE() asm volatile("tcgen05.fence::before_thread_sync;" ::: "memory")
#define TCGEN05_WAIT_LD()      asm volatile("tcgen05.wait::ld.sync.aligned;" ::: "memory")
#define MBARRIER_INIT(mbar, count) \
    asm volatile("mbarrier.init.shared.b64 [%0], %1;" :: "r"((uint32_t)(mbar)), "r"((uint32_t)(count)) : "memory")
#define FENCE_PROXY_ASYNC() asm volatile("fence.proxy.async.shared::cta;" ::: "memory")
#define STS128(a, r0, r1, r2, r3) \
    asm volatile("st.shared.v4.b32 [%0], {%1, %2, %3, %4};" :: "r"(a), "r"(r0), "r"(r1), "r"(r2), "r"(r3) : "memory")
#define MBARRIER_WAIT_PARITY(mbar, parity) do { \
    uint32_t _m = (uint32_t)(mbar); uint32_t _p = (uint32_t)(parity); uint32_t _d; \
    asm volatile("{\n\t.reg .pred p;\n\t" \
        "mbarrier.try_wait.parity.acquire.cta.shared::cta.b64 p, [%1], %2;\n\t" \
        "selp.b32 %0, 1, 0, p;\n\t}" : "=r"(_d) : "r"(_m), "r"(_p) : "memory"); \
    if (!_d) { \
        asm volatile("{\n\t.reg .pred P1;\n\t" \
            "WL_%=:\n\t" \
            "mbarrier.try_wait.parity.acquire.cta.shared::cta.b64 P1, [%0], %1, 0x989680;\n\t" \
            "@P1 bra.uni WD_%=;\n\t" \
            "bra.uni WL_%=;\n\t" \
            "WD_%=:\n\t}" :: "r"(_m), "r"(_p) : "memory"); \
    } } while (0)
#define TCGEN05_LD_32X32B_X32(r, tmem_addr) \
    asm volatile("tcgen05.ld.sync.aligned.32x32b.x32.b32 " \
        "{%0, %1, %2, %3, %4, %5, %6, %7, %8, %9, %10, %11, %12, %13, %14, %15, " \
        " %16, %17, %18, %19, %20, %21, %22, %23, %24, %25, %26, %27, %28, %29, %30, %31}, [%32];" \
        : "=r"((r)[0]),  "=r"((r)[1]),  "=r"((r)[2]),  "=r"((r)[3]), \
          "=r"((r)[4]),  "=r"((r)[5]),  "=r"((r)[6]),  "=r"((r)[7]), \
          "=r"((r)[8]),  "=r"((r)[9]),  "=r"((r)[10]), "=r"((r)[11]), \
          "=r"((r)[12]), "=r"((r)[13]), "=r"((r)[14]), "=r"((r)[15]), \
          "=r"((r)[16]), "=r"((r)[17]), "=r"((r)[18]), "=r"((r)[19]), \
          "=r"((r)[20]), "=r"((r)[21]), "=r"((r)[22]), "=r"((r)[23]), \
          "=r"((r)[24]), "=r"((r)[25]), "=r"((r)[26]), "=r"((r)[27]), \
          "=r"((r)[28]), "=r"((r)[29]), "=r"((r)[30]), "=r"((r)[31]) \
        : "r"(tmem_addr))

static constexpr uint64_t SMEM_DESC_BASE_SW128 =
    (uint64_t(2) << 61) | (uint64_t(1) << 46) | (uint64_t(64) << 32) | (uint64_t(1) << 16);
#define MAKE_SMEM_DESC(base_addr) (SMEM_DESC_BASE_SW128 | ((uint64_t)((base_addr) >> 4) & 0x3FFF))

// idesc: dtype=F32(bit4), atype=BF16(bit7), btype=BF16(bit10), N/8 @17, M/16 @24
#define MMA_IDESC_128x128 ((1u << 4) | (1u << 7) | (1u << 10) | (16u << 17) | (8u << 24))

__device__ __forceinline__ void mma_f16_ss(uint32_t d_tmem, uint64_t a_desc, uint64_t b_desc,
                                           uint32_t idesc, uint32_t enable)
{
    asm volatile(
        "{\n\t.reg .pred p;\n\t"
        "setp.ne.u32 p, %4, 0;\n\t"
        "tcgen05.mma.cta_group::1.kind::f16 [%0], %1, %2, %3, {%5, %5, %5, %5}, p;\n\t"
        "}"
        :: "r"(d_tmem), "l"(a_desc), "l"(b_desc), "r"(idesc), "r"(enable), "r"(0u)
        : "memory");
}
#endif  // HAS_TCGEN05

// ---------------------------------------------------------------------------
// Scratch (device globals; no allocation allowed)
// ---------------------------------------------------------------------------
__device__ float g_proj[(size_t)TOKENS * PROJ];
__device__ float g_dt[(size_t)TOKENS * NHEADS];
__device__ float g_dacs[(size_t)TOKENS * NHEADS];
__device__ float g_y[(size_t)TOKENS * DINNER];
__device__ float g_cs[(size_t)BATCH * NCHUNK * NHEADS * DSTATE * HDIM];
__device__ float g_hs[(size_t)BATCH * NCHUNK * NHEADS * DSTATE * HDIM];
__device__ float g_cdecay[(size_t)BATCH * NCHUNK * NHEADS];

__device__ __nv_bfloat16 g_xhi[(size_t)TOKENS * DMODEL];
__device__ __nv_bfloat16 g_xlo[(size_t)TOKENS * DMODEL];
__device__ __nv_bfloat16 g_winhi[(size_t)PROJPAD * DMODEL];
__device__ __nv_bfloat16 g_winlo[(size_t)PROJPAD * DMODEL];
__device__ __nv_bfloat16 g_wouthi[(size_t)DMODEL * DINNER];
__device__ __nv_bfloat16 g_woutlo[(size_t)DMODEL * DINNER];
__device__ __nv_bfloat16 g_yghi[(size_t)TOKENS * DINNER];
__device__ __nv_bfloat16 g_yglo[(size_t)TOKENS * DINNER];

// ---------------------------------------------------------------------------
// Split fp32 -> bf16 hi/lo
// ---------------------------------------------------------------------------
__global__ void __launch_bounds__(256)
split_kernel(const float* __restrict__ src, __nv_bfloat16* __restrict__ hi,
             __nv_bfloat16* __restrict__ lo, int n4)
{
    int i = blockIdx.x * 256 + threadIdx.x;
    if (i >= n4) return;
    float4 v = reinterpret_cast<const float4*>(src)[i];
    __nv_bfloat16 hx = __float2bfloat16(v.x), hy = __float2bfloat16(v.y);
    __nv_bfloat16 hz = __float2bfloat16(v.z), hw = __float2bfloat16(v.w);
    __nv_bfloat162 h01 = {hx, hy}, h23 = {hz, hw};
    __nv_bfloat162 l01 = {__float2bfloat16(v.x - __bfloat162float(hx)),
                          __float2bfloat16(v.y - __bfloat162float(hy))};
    __nv_bfloat162 l23 = {__float2bfloat16(v.z - __bfloat162float(hz)),
                          __float2bfloat16(v.w - __bfloat162float(hw))};
    reinterpret_cast<__nv_bfloat162*>(hi)[i * 2 + 0] = h01;
    reinterpret_cast<__nv_bfloat162*>(hi)[i * 2 + 1] = h23;
    reinterpret_cast<__nv_bfloat162*>(lo)[i * 2 + 0] = l01;
    reinterpret_cast<__nv_bfloat162*>(lo)[i * 2 + 1] = l23;
}

// split with zero-padding of rows >= rows_src
__global__ void __launch_bounds__(256)
split_pad_kernel(const float* __restrict__ src, __nv_bfloat16* __restrict__ hi,
                 __nv_bfloat16* __restrict__ lo, int rows_src, int n4, int K4)
{
    int i = blockIdx.x * 256 + threadIdx.x;
    if (i >= n4) return;
    int row = i / K4;
    float4 v = make_float4(0.f, 0.f, 0.f, 0.f);
    if (row < rows_src) v = reinterpret_cast<const float4*>(src)[i];
    __nv_bfloat16 hx = __float2bfloat16(v.x), hy = __float2bfloat16(v.y);
    __nv_bfloat16 hz = __float2bfloat16(v.z), hw = __float2bfloat16(v.w);
    __nv_bfloat162 h01 = {hx, hy}, h23 = {hz, hw};
    __nv_bfloat162 l01 = {__float2bfloat16(v.x - __bfloat162float(hx)),
                          __float2bfloat16(v.y - __bfloat162float(hy))};
    __nv_bfloat162 l23 = {__float2bfloat16(v.z - __bfloat162float(hz)),
                          __float2bfloat16(v.w - __bfloat162float(hw))};
    reinterpret_cast<__nv_bfloat162*>(hi)[i * 2 + 0] = h01;
    reinterpret_cast<__nv_bfloat162*>(hi)[i * 2 + 1] = h23;
    reinterpret_cast<__nv_bfloat162*>(lo)[i * 2 + 0] = l01;
    reinterpret_cast<__nv_bfloat162*>(lo)[i * 2 + 1] = l23;
}

// ---------------------------------------------------------------------------
// tcgen05 bf16-split GEMM:  C[M, Nout] (stride Nstride) = A * B^T
// A: [M, K] hi/lo bf16 row-major, B: [Npad, K] hi/lo bf16 row-major.
// Tile 128x128, K-chunks of 64, double-buffered SMEM, per-chunk commit.
// Generic-PTX pass gets a SIMT fallback body (never runs on GB300; the
// driver loads the exact sm_103a cubin).
// ---------------------------------------------------------------------------
#define GEMM_SMEM_BYTES (1024 + 2 * 65536 + 1024)

__global__ void __launch_bounds__(256, 1)
gemm_tc(const __nv_bfloat16* __restrict__ Ahi, const __nv_bfloat16* __restrict__ Alo,
        const __nv_bfloat16* __restrict__ Bhi, const __nv_bfloat16* __restrict__ Blo,
        float* __restrict__ C, int K, int Nstride, int Nout)
{
#if HAS_TCGEN05
    extern __shared__ char smem[];
    const uint32_t sbase = smem_to_u32(smem);
    const int tid = threadIdx.x;
    const int wid = tid >> 5;
    const int lid = tid & 31;
    const int bm = blockIdx.y * 128;
    const int bn = blockIdx.x * 128;

    const uint32_t TMEMP = sbase;
    const uint32_t MBAR0 = sbase + 8;
    const uint32_t MBAR1 = sbase + 16;
    const uint32_t BUF   = (sbase + 32 + 1023) & ~1023u;

    if (wid == 0) {
        TCGEN05_ALLOC(TMEMP, 128);
        TCGEN05_RELINQUISH();
    }
    if (tid == 0) { MBARRIER_INIT(MBAR0, 1); MBARRIER_INIT(MBAR1, 1); }
    __syncthreads();
    uint32_t tmem;
    asm volatile("ld.shared.b32 %0, [%1];" : "=r"(tmem) : "r"(TMEMP));

    const __nv_bfloat16* pAhi = Ahi + (size_t)bm * K;
    const __nv_bfloat16* pAlo = Alo + (size_t)bm * K;
    const __nv_bfloat16* pBhi = Bhi + (size_t)bn * K;
    const __nv_bfloat16* pBlo = Blo + (size_t)bn * K;

    const int NC = K >> 6;   // chunks of 64
    for (int c = 0; c < NC; ++c) {
        const uint32_t stage = BUF + (uint32_t)(c & 1) * 65536u;
        if (c >= 2) {
            MBARRIER_WAIT_PARITY((c & 1) ? MBAR1 : MBAR0, ((c >> 1) - 1) & 1);
        }
        const int k0 = c << 6;
#pragma unroll
        for (int it = 0; it < 16; ++it) {
            const __nv_bfloat16* src = (it < 4) ? pAhi : (it < 8) ? pAlo : (it < 12) ? pBhi : pBlo;
            int rem = ((it & 3) << 8) + tid;          // 0..1023
            int row = rem >> 3;
            int q   = rem & 7;
            uint4 v = *reinterpret_cast<const uint4*>(src + (size_t)row * K + k0 + q * 8);
            uint32_t boff = (uint32_t)(row * 128 + q * 16);
            uint32_t sw = boff ^ ((boff >> 3) & 0x70);
            STS128(stage + (uint32_t)(it >> 2) * 16384u + sw, v.x, v.y, v.z, v.w);
        }
        __syncthreads();

        if (wid == 0) {
            FENCE_PROXY_ASYNC();
            if (elect_one_pred()) {
                uint64_t dAhi = MAKE_SMEM_DESC(stage);
                uint64_t dAlo = MAKE_SMEM_DESC(stage + 16384);
                uint64_t dBhi = MAKE_SMEM_DESC(stage + 32768);
                uint64_t dBlo = MAKE_SMEM_DESC(stage + 49152);
#pragma unroll
                for (int ks = 0; ks < 4; ++ks) {
                    uint32_t en0 = (c == 0 && ks == 0) ? 0u : 1u;
                    mma_f16_ss(tmem, dAhi + ks * 2, dBhi + ks * 2, MMA_IDESC_128x128, en0);
                    mma_f16_ss(tmem, dAhi + ks * 2, dBlo + ks * 2, MMA_IDESC_128x128, 1u);
                    mma_f16_ss(tmem, dAlo + ks * 2, dBhi + ks * 2, MMA_IDESC_128x128, 1u);
                }
                TCGEN05_COMMIT((c & 1) ? MBAR1 : MBAR0);
            }
        }
    }

    // drain last two chunks
    MBARRIER_WAIT_PARITY(MBAR0, ((NC - 2) >> 1) & 1);
    MBARRIER_WAIT_PARITY(MBAR1, ((NC - 1) >> 1) & 1);
    TCGEN05_FENCE_AFTER();

    if (wid < 4) {
        int row = bm + wid * 32 + lid;
        float* crow = C + (size_t)row * Nstride + bn;
#pragma unroll
        for (int g = 0; g < 4; ++g) {
            uint32_t r[32];
            TCGEN05_LD_32X32B_X32(r, tmem + g * 32);
            TCGEN05_WAIT_LD();
            int n0 = bn + g * 32;
            if (n0 + 32 <= Nout) {
#pragma unroll
                for (int j = 0; j < 32; j += 4) {
                    float4 v = make_float4(__uint_as_float(r[j]), __uint_as_float(r[j + 1]),
                                           __uint_as_float(r[j + 2]), __uint_as_float(r[j + 3]));
                    *reinterpret_cast<float4*>(crow + g * 32 + j) = v;
                }
            } else {
                for (int j = 0; j < 32; ++j)
                    if (n0 + j < Nout) crow[g * 32 + j] = __uint_as_float(r[j]);
            }
        }
        TCGEN05_FENCE_BEFORE();
    }
    __syncthreads();
    if (wid == 0) TCGEN05_DEALLOC(tmem, 128);

#else   // ---------------- SIMT fallback (generic PTX pass only) -----------
    extern __shared__ char smem[];
    float* As = reinterpret_cast<float*>(smem);                 // [16][132]
    float* Bs = As + 16 * 132;                                  // [16][132]

    const int tid = threadIdx.x;
    const int tx  = tid & 15;
    const int ty  = tid >> 4;
    const int bm  = blockIdx.y * 128;
    const int bn  = blockIdx.x * 128;

    float acc[8][8];
#pragma unroll
    for (int i = 0; i < 8; ++i)
#pragma unroll
        for (int j = 0; j < 8; ++j) acc[i][j] = 0.f;

    for (int k0 = 0; k0 < K; k0 += 16) {
        for (int idx = tid; idx < 128 * 16; idx += 256) {
            int row = idx >> 4, kk = idx & 15;
            size_t ea = (size_t)(bm + row) * K + k0 + kk;
            size_t eb = (size_t)(bn + row) * K + k0 + kk;
            As[kk * 132 + row] = __bfloat162float(Ahi[ea]) + __bfloat162float(Alo[ea]);
            Bs[kk * 132 + row] = __bfloat162float(Bhi[eb]) + __bfloat162float(Blo[eb]);
        }
        __syncthreads();
#pragma unroll
        for (int kk = 0; kk < 16; ++kk) {
            float ra[8], rb[8];
#pragma unroll
            for (int i = 0; i < 4; ++i) {
                ra[i]     = As[kk * 132 + ty * 4 + i];
                ra[4 + i] = As[kk * 132 + 64 + ty * 4 + i];
                rb[i]     = Bs[kk * 132 + tx * 4 + i];
                rb[4 + i] = Bs[kk * 132 + 64 + tx * 4 + i];
            }
#pragma unroll
            for (int i = 0; i < 8; ++i)
#pragma unroll
                for (int j = 0; j < 8; ++j)
                    acc[i][j] = fmaf(ra[i], rb[j], acc[i][j]);
        }
        __syncthreads();
    }
#pragma unroll
    for (int i = 0; i < 8; ++i) {
        int m = bm + ((i < 4) ? (ty * 4 + i) : (64 + ty * 4 + (i - 4)));
#pragma unroll
        for (int j = 0; j < 8; ++j) {
            int n = bn + ((j < 4) ? (tx * 4 + j) : (64 + tx * 4 + (j - 4)));
            if (n < Nout) C[(size_t)m * Nstride + n] = acc[i][j];
        }
    }
#endif
}

// ---------------------------------------------------------------------------
// dt = softplus(dt_low @ dt_W^T + dt_b)
// ---------------------------------------------------------------------------
__global__ void __launch_bounds__(256)
dt_kernel(const float* __restrict__ dt_W, const float* __restrict__ dt_b)
{
    int idx = blockIdx.x * 256 + threadIdx.x;
    if (idx >= TOKENS * NHEADS) return;
    int t = idx >> 4;
    int h = idx & 15;
    const float* row = g_proj + (size_t)t * PROJ + OFF_DT;
    float acc = dt_b[h];
#pragma unroll
    for (int r = 0; r < DTRANK; ++r)
        acc = fmaf(row[r], dt_W[h * DTRANK + r], acc);
    float sp = (acc > 20.f) ? acc : log1pf(expf(acc));
    g_dt[idx] = sp;
}

// ---------------------------------------------------------------------------
// Intra-chunk
// ---------------------------------------------------------------------------
__global__ void __launch_bounds__(256)
intra_kernel(const float* __restrict__ A_log)
{
    const int bid = blockIdx.x;
    const int h   = bid & 15;
    const int bc  = bid >> 4;
    const int t0  = bc * CHUNK;
    const int tid = threadIdx.x;

    __shared__ float xs[64][65];
    __shared__ float sc[64][65];
    __shared__ float Bsh[64][17];
    __shared__ float Csh[64][17];
    __shared__ float dts[64];
    __shared__ float dacs[64];
    __shared__ float wk[64];

    for (int idx = tid; idx < 64 * 64; idx += 256) {
        int k = idx >> 6, p = idx & 63;
        xs[k][p] = g_proj[(size_t)(t0 + k) * PROJ + OFF_XP + h * HDIM + p];
    }
    for (int idx = tid; idx < 64 * 16; idx += 256) {
        int k = idx >> 4, n = idx & 15;
        Bsh[k][n] = g_proj[(size_t)(t0 + k) * PROJ + OFF_B + h * DSTATE + n];
        Csh[k][n] = g_proj[(size_t)(t0 + k) * PROJ + OFF_C + h * DSTATE + n];
    }
    if (tid < 64) dts[tid] = g_dt[(size_t)(t0 + tid) * NHEADS + h];
    __syncthreads();

    if (tid == 0) {
        float A = -expf(A_log[h]);
        float s = 0.f;
        for (int k = 0; k < 64; ++k) { s += dts[k] * A; dacs[k] = s; }
    }
    __syncthreads();

    for (int idx = tid; idx < 64 * 64; idx += 256) {
        int i = idx >> 6, j = idx & 63;
        float v = 0.f;
        if (j <= i) {
            float d = 0.f;
#pragma unroll
            for (int n = 0; n < 16; ++n)
                d = fmaf(Csh[i][n], Bsh[j][n], d);
            v = d * expf(dacs[i] - dacs[j]) * dts[j];
        }
        sc[i][j] = v;
    }
    __syncthreads();
    if (tid < 64) {
        wk[tid] = dts[tid] * expf(dacs[63] - dacs[tid]);
        g_dacs[(size_t)(t0 + tid) * NHEADS + h] = dacs[tid];
    }
    if (tid == 0) g_cdecay[bid] = expf(dacs[63]);
    __syncthreads();

    {
        int i  = tid >> 2;
        int p0 = (tid & 3) * 16;
        float acc[16];
#pragma unroll
        for (int pp = 0; pp < 16; ++pp) acc[pp] = 0.f;
        for (int j = 0; j < 64; ++j) {
            float s = sc[i][j];
#pragma unroll
            for (int pp = 0; pp < 16; ++pp)
                acc[pp] = fmaf(s, xs[j][p0 + pp], acc[pp]);
        }
        float* yrow = g_y + (size_t)(t0 + i) * DINNER + h * HDIM;
#pragma unroll
        for (int pp = 0; pp < 16; ++pp) yrow[p0 + pp] = acc[pp];
    }

    for (int idx = tid; idx < DSTATE * HDIM; idx += 256) {
        int n = idx >> 6, p = idx & 63;
        float acc = 0.f;
        for (int k = 0; k < 64; ++k)
            acc = fmaf(Bsh[k][n] * wk[k], xs[k][p], acc);
        g_cs[(size_t)bid * (DSTATE * HDIM) + idx] = acc;
    }
}

// ---------------------------------------------------------------------------
// Sequential scan over chunks
// ---------------------------------------------------------------------------
__global__ void __launch_bounds__(256)
scan_kernel()
{
    const int bh  = blockIdx.x;
    const int b   = bh >> 4;
    const int h   = bh & 15;
    const int tid = threadIdx.x;

    float hv[4] = {0.f, 0.f, 0.f, 0.f};
    for (int c = 0; c < NCHUNK; ++c) {
        int    chid = (b * NCHUNK + c) * NHEADS + h;
        size_t base = (size_t)chid * (DSTATE * HDIM);
        float  d    = g_cdecay[chid];
#pragma unroll
        for (int j = 0; j < 4; ++j) {
            int e = tid + j * 256;
            g_hs[base + e] = hv[j];
            hv[j] = fmaf(d, hv[j], g_cs[base + e]);
        }
    }
}

// ---------------------------------------------------------------------------
// Cross-chunk + skip
// ---------------------------------------------------------------------------
__global__ void __launch_bounds__(256)
cross_kernel(const float* __restrict__ D_param)
{
    const int bid = blockIdx.x;
    const int h   = bid & 15;
    const int bc  = bid >> 4;
    const int t0  = bc * CHUNK;
    const int tid = threadIdx.x;

    __shared__ float hs[16][65];
    __shared__ float Csh[64][17];
    __shared__ float dacs[64];

    for (int idx = tid; idx < DSTATE * HDIM; idx += 256) {
        int n = idx >> 6, p = idx & 63;
        hs[n][p] = g_hs[(size_t)bid * (DSTATE * HDIM) + idx];
    }
    for (int idx = tid; idx < 64 * 16; idx += 256) {
        int k = idx >> 4, n = idx & 15;
        Csh[k][n] = g_proj[(size_t)(t0 + k) * PROJ + OFF_C + h * DSTATE + n];
    }
    if (tid < 64) dacs[tid] = g_dacs[(size_t)(t0 + tid) * NHEADS + h];
    __syncthreads();

    int i  = tid >> 2;
    int p0 = (tid & 3) * 16;
    float ci[16];
#pragma unroll
    for (int n = 0; n < 16; ++n) ci[n] = Csh[i][n];
    float e  = expf(dacs[i]);
    float dp = D_param[h];

    size_t t = (size_t)(t0 + i);
    const float* xrow = g_proj + t * PROJ + OFF_XP + h * HDIM;
    float* yrow = g_y + t * DINNER + h * HDIM;
#pragma unroll
    for (int pp = 0; pp < 16; ++pp) {
        int p = p0 + pp;
        float a = 0.f;
#pragma unroll
        for (int n = 0; n < 16; ++n)
            a = fmaf(ci[n], hs[n][p], a);
        yrow[p] = yrow[p] + e * a + dp * xrow[p];
    }
}

// ---------------------------------------------------------------------------
// RMS norm + SiLU gate -> yg (bf16 hi/lo for the out GEMM)
// ---------------------------------------------------------------------------
__global__ void __launch_bounds__(256)
norm_kernel(const float* __restrict__ norm_w)
{
    const int t   = blockIdx.x;
    const int tid = threadIdx.x;

    float4 v = reinterpret_cast<const float4*>(g_y + (size_t)t * DINNER)[tid];
    float ss = v.x * v.x + v.y * v.y + v.z * v.z + v.w * v.w;
#pragma unroll
    for (int off = 16; off > 0; off >>= 1)
        ss += __shfl_xor_sync(0xffffffffu, ss, off);

    __shared__ float red[8];
    __shared__ float s_inv;
    if ((tid & 31) == 0) red[tid >> 5] = ss;
    __syncthreads();
    if (tid == 0) {
        float s = 0.f;
#pragma unroll
        for (int i = 0; i < 8; ++i) s += red[i];
        s_inv = rsqrtf(s * (1.f / DINNER) + 1e-6f);
    }
    __syncthreads();
    float inv = s_inv;

    const float* zrow = g_proj + (size_t)t * PROJ + OFF_Z;
    int c = tid * 4;
    float4 z4 = *reinterpret_cast<const float4*>(zrow + c);
    float4 w4 = *reinterpret_cast<const float4*>(norm_w + c);
    float4 o;
    o.x = v.x * inv * w4.x * (z4.x / (1.f + expf(-z4.x)));
    o.y = v.y * inv * w4.y * (z4.y / (1.f + expf(-z4.y)));
    o.z = v.z * inv * w4.z * (z4.z / (1.f + expf(-z4.z)));
    o.w = v.w * inv * w4.w * (z4.w / (1.f + expf(-z4.w)));

    __nv_bfloat16 hx = __float2bfloat16(o.x), hy = __float2bfloat16(o.y);
    __nv_bfloat16 hz = __float2bfloat16(o.z), hw = __float2bfloat16(o.w);
    __nv_bfloat162 h01 = {hx, hy}, h23 = {hz, hw};
    __nv_bfloat162 l01 = {__float2bfloat16(o.x - __bfloat162float(hx)),
                          __float2bfloat16(o.y - __bfloat162float(hy))};
    __nv_bfloat162 l23 = {__float2bfloat16(o.z - __bfloat162float(hz)),
                          __float2bfloat16(o.w - __bfloat162float(hw))};
    size_t base2 = ((size_t)t * DINNER + c) >> 1;
    reinterpret_cast<__nv_bfloat162*>(g_yghi)[base2 + 0] = h01;
    reinterpret_cast<__nv_bfloat162*>(g_yghi)[base2 + 1] = h23;
    reinterpret_cast<__nv_bfloat162*>(g_yglo)[base2 + 0] = l01;
    reinterpret_cast<__nv_bfloat162*>(g_yglo)[base2 + 1] = l23;
}

// ---------------------------------------------------------------------------
// Launch
// ---------------------------------------------------------------------------
extern "C" void kernel_launch(void* const* d_in, const int* in_sizes, int n_in,
                              void* d_out, int out_size)
{
    const float* x      = (const float*)d_in[0];
    const float* W_in   = (const float*)d_in[1];
    const float* dt_W   = (const float*)d_in[2];
    const float* dt_b   = (const float*)d_in[3];
    const float* A_log  = (const float*)d_in[4];
    const float* D_par  = (const float*)d_in[5];
    const float* W_out  = (const float*)d_in[6];
    const float* norm_w = (const float*)d_in[7];
    float* out = (float*)d_out;

    float* proj_ptr = nullptr;
    __nv_bfloat16 *xhi, *xlo, *winhi, *winlo, *wouthi, *woutlo, *yghi, *yglo;
    cudaGetSymbolAddress((void**)&proj_ptr, g_proj);
    cudaGetSymbolAddress((void**)&xhi, g_xhi);
    cudaGetSymbolAddress((void**)&xlo, g_xlo);
    cudaGetSymbolAddress((void**)&winhi, g_winhi);
    cudaGetSymbolAddress((void**)&winlo, g_winlo);
    cudaGetSymbolAddress((void**)&wouthi, g_wouthi);
    cudaGetSymbolAddress((void**)&woutlo, g_woutlo);
    cudaGetSymbolAddress((void**)&yghi, g_yghi);
    cudaGetSymbolAddress((void**)&yglo, g_yglo);

    cudaFuncSetAttribute(gemm_tc, cudaFuncAttributeMaxDynamicSharedMemorySize, GEMM_SMEM_BYTES);

    // 0) conversions
    {
        int n4 = TOKENS * DMODEL / 4;
        split_kernel<<<(n4 + 255) / 256, 256>>>(x, xhi, xlo, n4);
    }
    {
        int n4 = PROJPAD * DMODEL / 4;
        split_pad_kernel<<<(n4 + 255) / 256, 256>>>(W_in, winhi, winlo, PROJ, n4, DMODEL / 4);
    }
    {
        int n4 = DMODEL * DINNER / 4;
        split_kernel<<<(n4 + 255) / 256, 256>>>(W_out, wouthi, woutlo, n4);
    }

    // 1) proj = x @ W_in^T   [16384, 2576]
    {
        dim3 grid(PROJPAD / 128, TOKENS / 128);
        gemm_tc<<<grid, 256, GEMM_SMEM_BYTES>>>(xhi, xlo, winhi, winlo,
                                                proj_ptr, DMODEL, PROJ, PROJ);
    }
    // 2) dt
    dt_kernel<<<(TOKENS * NHEADS) / 256, 256>>>(dt_W, dt_b);
    // 3) intra-chunk
    intra_kernel<<<BATCH * NCHUNK * NHEADS, 256>>>(A_log);
    // 4) chunk scan
    scan_kernel<<<BATCH * NHEADS, 256>>>();
    // 5) cross-chunk + skip
    cross_kernel<<<BATCH * NCHUNK * NHEADS, 256>>>(D_par);
    // 6) RMS norm + gate -> bf16 hi/lo
    norm_kernel<<<TOKENS, 256>>>(norm_w);
    // 7) out = yg @ W_out^T  [16384, 1024]
    {
        dim3 grid(DMODEL / 128, TOKENS / 128);
        gemm_tc<<<grid, 256, GEMM_SMEM_BYTES>>>(yghi, yglo, wouthi, woutlo,
                                                out, DINNER, DMODEL, DMODEL);
    }
}

// round 4
// speedup vs baseline: 2.3626x; 1.1957x over previous
#include <cuda_runtime.h>
#include <cuda_bf16.h>
#include <cstdint>

// ---------------------------------------------------------------------------
// Problem constants
// ---------------------------------------------------------------------------
#define BATCH   4
#define SEQ     4096
#define TOKENS  (BATCH * SEQ)        // 16384
#define DMODEL  1024
#define DINNER  1024
#define NHEADS  16
#define HDIM    64
#define DSTATE  16
#define DTRANK  16
#define CHUNK   64
#define NCHUNK  (SEQ / CHUNK)        // 64
#define PROJ    2576
#define PROJPAD 2688                 // 21 * 128

#define OFF_XP   0
#define OFF_Z    1024
#define OFF_B    2048
#define OFF_C    2304
#define OFF_DT   2560

// tcgen05 is an arch-SPECIFIC feature: only emit it in the sm_103a/f passes.
#if defined(__CUDA_ARCH_FEAT_SM103_ALL) || \
    (defined(__CUDA_ARCH_FAMILY_SPECIFIC__) && __CUDA_ARCH_FAMILY_SPECIFIC__ >= 1000) || \
    (defined(__CUDA_ARCH_SPECIFIC__) && __CUDA_ARCH_SPECIFIC__ >= 1000)
#define HAS_TCGEN05 1
#else
#define HAS_TCGEN05 0
#endif

// ---------------------------------------------------------------------------
// PTX helpers (guarded)
// ---------------------------------------------------------------------------
#if HAS_TCGEN05
__device__ __forceinline__ uint32_t smem_to_u32(const void* p) {
    uint32_t a;
    asm("{ .reg .u64 t; cvta.to.shared.u64 t, %1; cvt.u32.u64 %0, t; }" : "=r"(a) : "l"(p));
    return a;
}
__device__ __forceinline__ uint32_t elect_one_pred() {
    uint32_t pred;
    asm volatile("{\n\t.reg .pred p;\n\telect.sync _|p, 0xFFFFFFFF;\n\tselp.b32 %0, 1, 0, p;\n\t}" : "=r"(pred));
    return pred;
}
#define TCGEN05_ALLOC(smem_result_addr, nCols) \
    asm volatile("tcgen05.alloc.cta_group::1.sync.aligned.shared::cta.b32 [%0], %1;" \
        :: "r"((uint32_t)(smem_result_addr)), "r"((uint32_t)(nCols)) : "memory")
#define TCGEN05_DEALLOC(tmem_addr, nCols) \
    asm volatile("tcgen05.dealloc.cta_group::1.sync.aligned.b32 %0, %1;" :: "r"(tmem_addr), "r"((uint32_t)(nCols)))
#define TCGEN05_RELINQUISH() \
    asm volatile("tcgen05.relinquish_alloc_permit.cta_group::1.sync.aligned;")
#define TCGEN05_COMMIT(mbar) \
    asm volatile("tcgen05.commit.cta_group::1.mbarrier::arrive::one.shared::cluster.b64 [%0];" \
        :: "r"((uint32_t)(mbar)) : "memory")
#define TCGEN05_FENCE_AFTER()  asm volatile("tcgen05.fence::after_thread_sync;" ::: "memory")
#define TCGEN05_FENCE_BEFORE() asm volatile("tcgen05.fence::before_thread_sync;" ::: "memory")
#define TCGEN05_WAIT_LD()      asm volatile("tcgen05.wait::ld.sync.aligned;" ::: "memory")
#define MBARRIER_INIT(mbar, count) \
    asm volatile("mbarrier.init.shared.b64 [%0], %1;" :: "r"((uint32_t)(mbar)), "r"((uint32_t)(count)) : "memory")
#define FENCE_PROXY_ASYNC() asm volatile("fence.proxy.async.shared::cta;" ::: "memory")
#define STS128(a, r0, r1, r2, r3) \
    asm volatile("st.shared.v4.b32 [%0], {%1, %2, %3, %4};" :: "r"(a), "r"(r0), "r"(r1), "r"(r2), "r"(r3) : "memory")
#define MBARRIER_WAIT_PARITY(mbar, parity) do { \
    uint32_t _m = (uint32_t)(mbar); uint32_t _p = (uint32_t)(parity); uint32_t _d; \
    asm volatile("{\n\t.reg .pred p;\n\t" \
        "mbarrier.try_wait.parity.acquire.cta.shared::cta.b64 p, [%1], %2;\n\t" \
        "selp.b32 %0, 1, 0, p;\n\t}" : "=r"(_d) : "r"(_m), "r"(_p) : "memory"); \
    if (!_d) { \
        asm volatile("{\n\t.reg .pred P1;\n\t" \
            "WL_%=:\n\t" \
            "mbarrier.try_wait.parity.acquire.cta.shared::cta.b64 P1, [%0], %1, 0x989680;\n\t" \
            "@P1 bra.uni WD_%=;\n\t" \
            "bra.uni WL_%=;\n\t" \
            "WD_%=:\n\t}" :: "r"(_m), "r"(_p) : "memory"); \
    } } while (0)
#define TCGEN05_LD_32X32B_X32(r, tmem_addr) \
    asm volatile("tcgen05.ld.sync.aligned.32x32b.x32.b32 " \
        "{%0, %1, %2, %3, %4, %5, %6, %7, %8, %9, %10, %11, %12, %13, %14, %15, " \
        " %16, %17, %18, %19, %20, %21, %22, %23, %24, %25, %26, %27, %28, %29, %30, %31}, [%32];" \
        : "=r"((r)[0]),  "=r"((r)[1]),  "=r"((r)[2]),  "=r"((r)[3]), \
          "=r"((r)[4]),  "=r"((r)[5]),  "=r"((r)[6]),  "=r"((r)[7]), \
          "=r"((r)[8]),  "=r"((r)[9]),  "=r"((r)[10]), "=r"((r)[11]), \
          "=r"((r)[12]), "=r"((r)[13]), "=r"((r)[14]), "=r"((r)[15]), \
          "=r"((r)[16]), "=r"((r)[17]), "=r"((r)[18]), "=r"((r)[19]), \
          "=r"((r)[20]), "=r"((r)[21]), "=r"((r)[22]), "=r"((r)[23]), \
          "=r"((r)[24]), "=r"((r)[25]), "=r"((r)[26]), "=r"((r)[27]), \
          "=r"((r)[28]), "=r"((r)[29]), "=r"((r)[30]), "=r"((r)[31]) \
        : "r"(tmem_addr))

static constexpr uint64_t SMEM_DESC_BASE_SW128 =
    (uint64_t(2) << 61) | (uint64_t(1) << 46) | (uint64_t(64) << 32) | (uint64_t(1) << 16);
#define MAKE_SMEM_DESC(base_addr) (SMEM_DESC_BASE_SW128 | ((uint64_t)((base_addr) >> 4) & 0x3FFF))

// idesc: dtype=F32(bit4), atype=BF16(bit7), btype=BF16(bit10), N/8 @17, M/16 @24
#define MMA_IDESC_128x128 ((1u << 4) | (1u << 7) | (1u << 10) | (16u << 17) | (8u << 24))

__device__ __forceinline__ void mma_f16_ss(uint32_t d_tmem, uint64_t a_desc, uint64_t b_desc,
                                           uint32_t idesc, uint32_t enable)
{
    asm volatile(
        "{\n\t.reg .pred p;\n\t"
        "setp.ne.u32 p, %4, 0;\n\t"
        "tcgen05.mma.cta_group::1.kind::f16 [%0], %1, %2, %3, {%5, %5, %5, %5}, p;\n\t"
        "}"
        :: "r"(d_tmem), "l"(a_desc), "l"(b_desc), "r"(idesc), "r"(enable), "r"(0u)
        : "memory");
}
#endif  // HAS_TCGEN05

// ---------------------------------------------------------------------------
// Scratch (device globals; no allocation allowed)
// ---------------------------------------------------------------------------
__device__ float g_proj[(size_t)TOKENS * PROJ];
__device__ float g_dacs[(size_t)TOKENS * NHEADS];
__device__ float g_y[(size_t)TOKENS * DINNER];
__device__ float g_cs[(size_t)BATCH * NCHUNK * NHEADS * DSTATE * HDIM];
__device__ float g_hs[(size_t)BATCH * NCHUNK * NHEADS * DSTATE * HDIM];
__device__ float g_cdecay[(size_t)BATCH * NCHUNK * NHEADS];

__device__ __nv_bfloat16 g_xhi[(size_t)TOKENS * DMODEL];
__device__ __nv_bfloat16 g_xlo[(size_t)TOKENS * DMODEL];
__device__ __nv_bfloat16 g_winhi[(size_t)PROJPAD * DMODEL];
__device__ __nv_bfloat16 g_winlo[(size_t)PROJPAD * DMODEL];
__device__ __nv_bfloat16 g_wouthi[(size_t)DMODEL * DINNER];
__device__ __nv_bfloat16 g_woutlo[(size_t)DMODEL * DINNER];
__device__ __nv_bfloat16 g_yghi[(size_t)TOKENS * DINNER];
__device__ __nv_bfloat16 g_yglo[(size_t)TOKENS * DINNER];

// ---------------------------------------------------------------------------
// Split fp32 -> bf16 hi/lo
// ---------------------------------------------------------------------------
__global__ void __launch_bounds__(256)
split_kernel(const float* __restrict__ src, __nv_bfloat16* __restrict__ hi,
             __nv_bfloat16* __restrict__ lo, int n4)
{
    int i = blockIdx.x * 256 + threadIdx.x;
    if (i >= n4) return;
    float4 v = reinterpret_cast<const float4*>(src)[i];
    __nv_bfloat16 hx = __float2bfloat16(v.x), hy = __float2bfloat16(v.y);
    __nv_bfloat16 hz = __float2bfloat16(v.z), hw = __float2bfloat16(v.w);
    __nv_bfloat162 h01 = {hx, hy}, h23 = {hz, hw};
    __nv_bfloat162 l01 = {__float2bfloat16(v.x - __bfloat162float(hx)),
                          __float2bfloat16(v.y - __bfloat162float(hy))};
    __nv_bfloat162 l23 = {__float2bfloat16(v.z - __bfloat162float(hz)),
                          __float2bfloat16(v.w - __bfloat162float(hw))};
    reinterpret_cast<__nv_bfloat162*>(hi)[i * 2 + 0] = h01;
    reinterpret_cast<__nv_bfloat162*>(hi)[i * 2 + 1] = h23;
    reinterpret_cast<__nv_bfloat162*>(lo)[i * 2 + 0] = l01;
    reinterpret_cast<__nv_bfloat162*>(lo)[i * 2 + 1] = l23;
}

__global__ void __launch_bounds__(256)
split_pad_kernel(const float* __restrict__ src, __nv_bfloat16* __restrict__ hi,
                 __nv_bfloat16* __restrict__ lo, int rows_src, int n4, int K4)
{
    int i = blockIdx.x * 256 + threadIdx.x;
    if (i >= n4) return;
    int row = i / K4;
    float4 v = make_float4(0.f, 0.f, 0.f, 0.f);
    if (row < rows_src) v = reinterpret_cast<const float4*>(src)[i];
    __nv_bfloat16 hx = __float2bfloat16(v.x), hy = __float2bfloat16(v.y);
    __nv_bfloat16 hz = __float2bfloat16(v.z), hw = __float2bfloat16(v.w);
    __nv_bfloat162 h01 = {hx, hy}, h23 = {hz, hw};
    __nv_bfloat162 l01 = {__float2bfloat16(v.x - __bfloat162float(hx)),
                          __float2bfloat16(v.y - __bfloat162float(hy))};
    __nv_bfloat162 l23 = {__float2bfloat16(v.z - __bfloat162float(hz)),
                          __float2bfloat16(v.w - __bfloat162float(hw))};
    reinterpret_cast<__nv_bfloat162*>(hi)[i * 2 + 0] = h01;
    reinterpret_cast<__nv_bfloat162*>(hi)[i * 2 + 1] = h23;
    reinterpret_cast<__nv_bfloat162*>(lo)[i * 2 + 0] = l01;
    reinterpret_cast<__nv_bfloat162*>(lo)[i * 2 + 1] = l23;
}

// ---------------------------------------------------------------------------
// tcgen05 bf16-split GEMM:  C[M, Nout] (stride Nstride) = A * B^T
// Tile 256x128 (two M-atoms of 128), K-chunks of 64, double-buffered SMEM.
// Stage layout: Ahi[256x64] @0, Alo @32768, Bhi[128x64] @65536, Blo @81920.
// ---------------------------------------------------------------------------
#define STAGE_BYTES 98304
#define GEMM_SMEM_BYTES (1024 + 2 * STAGE_BYTES + 1024)

__global__ void __launch_bounds__(256, 1)
gemm_tc(const __nv_bfloat16* __restrict__ Ahi, const __nv_bfloat16* __restrict__ Alo,
        const __nv_bfloat16* __restrict__ Bhi, const __nv_bfloat16* __restrict__ Blo,
        float* __restrict__ C, int K, int Nstride, int Nout)
{
#if HAS_TCGEN05
    extern __shared__ char smem[];
    const uint32_t sbase = smem_to_u32(smem);
    const int tid = threadIdx.x;
    const int wid = tid >> 5;
    const int lid = tid & 31;
    const int bm = blockIdx.y * 256;
    const int bn = blockIdx.x * 128;

    const uint32_t TMEMP = sbase;
    const uint32_t MBAR0 = sbase + 8;
    const uint32_t MBAR1 = sbase + 16;
    const uint32_t BUF   = (sbase + 32 + 1023) & ~1023u;

    if (wid == 0) {
        TCGEN05_ALLOC(TMEMP, 256);
        TCGEN05_RELINQUISH();
    }
    if (tid == 0) { MBARRIER_INIT(MBAR0, 1); MBARRIER_INIT(MBAR1, 1); }
    __syncthreads();
    uint32_t tmem;
    asm volatile("ld.shared.b32 %0, [%1];" : "=r"(tmem) : "r"(TMEMP));

    const __nv_bfloat16* pAhi = Ahi + (size_t)bm * K;
    const __nv_bfloat16* pAlo = Alo + (size_t)bm * K;
    const __nv_bfloat16* pBhi = Bhi + (size_t)bn * K;
    const __nv_bfloat16* pBlo = Blo + (size_t)bn * K;

    const int NC = K >> 6;   // chunks of 64
    for (int c = 0; c < NC; ++c) {
        const uint32_t stage = BUF + (uint32_t)(c & 1) * (uint32_t)STAGE_BYTES;
        if (c >= 2) {
            MBARRIER_WAIT_PARITY((c & 1) ? MBAR1 : MBAR0, ((c >> 1) - 1) & 1);
        }
        const int k0 = c << 6;
        // A tiles: 256 rows x 64 bf16, hi & lo
#pragma unroll
        for (int it = 0; it < 8; ++it) {
            int u = it * 256 + tid;            // 0..2047
            int row = u >> 3;                  // 0..255
            int q   = u & 7;
            uint4 vh = *reinterpret_cast<const uint4*>(pAhi + (size_t)row * K + k0 + q * 8);
            uint4 vl = *reinterpret_cast<const uint4*>(pAlo + (size_t)row * K + k0 + q * 8);
            uint32_t boff = (uint32_t)(row * 128 + q * 16);
            uint32_t sw = boff ^ ((boff >> 3) & 0x70);
            STS128(stage + sw,          vh.x, vh.y, vh.z, vh.w);
            STS128(stage + 32768u + sw, vl.x, vl.y, vl.z, vl.w);
        }
        // B tiles: 128 rows x 64 bf16, hi & lo
#pragma unroll
        for (int it = 0; it < 4; ++it) {
            int u = it * 256 + tid;            // 0..1023
            int row = u >> 3;                  // 0..127
            int q   = u & 7;
            uint4 vh = *reinterpret_cast<const uint4*>(pBhi + (size_t)row * K + k0 + q * 8);
            uint4 vl = *reinterpret_cast<const uint4*>(pBlo + (size_t)row * K + k0 + q * 8);
            uint32_t boff = (uint32_t)(row * 128 + q * 16);
            uint32_t sw = boff ^ ((boff >> 3) & 0x70);
            STS128(stage + 65536u + sw, vh.x, vh.y, vh.z, vh.w);
            STS128(stage + 81920u + sw, vl.x, vl.y, vl.z, vl.w);
        }
        __syncthreads();

        if (wid == 0) {
            FENCE_PROXY_ASYNC();
            if (elect_one_pred()) {
                uint64_t dA0h = MAKE_SMEM_DESC(stage);
                uint64_t dA1h = MAKE_SMEM_DESC(stage + 16384);
                uint64_t dA0l = MAKE_SMEM_DESC(stage + 32768);
                uint64_t dA1l = MAKE_SMEM_DESC(stage + 49152);
                uint64_t dBh  = MAKE_SMEM_DESC(stage + 65536);
                uint64_t dBl  = MAKE_SMEM_DESC(stage + 81920);
#pragma unroll
                for (int ks = 0; ks < 4; ++ks) {
                    uint32_t en0 = (c == 0 && ks == 0) ? 0u : 1u;
                    // M-tile 0
                    mma_f16_ss(tmem,       dA0h + ks * 2, dBh + ks * 2, MMA_IDESC_128x128, en0);
                    mma_f16_ss(tmem,       dA0h + ks * 2, dBl + ks * 2, MMA_IDESC_128x128, 1u);
                    mma_f16_ss(tmem,       dA0l + ks * 2, dBh + ks * 2, MMA_IDESC_128x128, 1u);
                    // M-tile 1
                    mma_f16_ss(tmem + 128, dA1h + ks * 2, dBh + ks * 2, MMA_IDESC_128x128, en0);
                    mma_f16_ss(tmem + 128, dA1h + ks * 2, dBl + ks * 2, MMA_IDESC_128x128, 1u);
                    mma_f16_ss(tmem + 128, dA1l + ks * 2, dBh + ks * 2, MMA_IDESC_128x128, 1u);
                }
                TCGEN05_COMMIT((c & 1) ? MBAR1 : MBAR0);
            }
        }
    }

    MBARRIER_WAIT_PARITY(MBAR0, ((NC - 2) >> 1) & 1);
    MBARRIER_WAIT_PARITY(MBAR1, ((NC - 1) >> 1) & 1);
    TCGEN05_FENCE_AFTER();

    {
        int mt  = wid >> 2;                       // 0 or 1
        int row = bm + mt * 128 + (wid & 3) * 32 + lid;
        float* crow = C + (size_t)row * Nstride + bn;
        uint32_t tcol = tmem + (uint32_t)(mt * 128);
#pragma unroll
        for (int g = 0; g < 4; ++g) {
            uint32_t r[32];
            TCGEN05_LD_32X32B_X32(r, tcol + g * 32);
            TCGEN05_WAIT_LD();
            int n0 = bn + g * 32;
            if (n0 + 32 <= Nout) {
#pragma unroll
                for (int j = 0; j < 32; j += 4) {
                    float4 v = make_float4(__uint_as_float(r[j]), __uint_as_float(r[j + 1]),
                                           __uint_as_float(r[j + 2]), __uint_as_float(r[j + 3]));
                    *reinterpret_cast<float4*>(crow + g * 32 + j) = v;
                }
            } else {
                for (int j = 0; j < 32; ++j)
                    if (n0 + j < Nout) crow[g * 32 + j] = __uint_as_float(r[j]);
            }
        }
        TCGEN05_FENCE_BEFORE();
    }
    __syncthreads();
    if (wid == 0) TCGEN05_DEALLOC(tmem, 256);

#else   // ---------------- SIMT fallback (generic PTX pass only; never runs) --
    const int tid = threadIdx.x;
    const int bm  = blockIdx.y * 256;
    const int bn  = blockIdx.x * 128;
    for (int e = tid; e < 256 * 128; e += 256) {
        int i = e >> 7, j = e & 127;
        if (bn + j >= Nout) continue;
        float acc = 0.f;
        for (int k = 0; k < K; ++k) {
            float a = __bfloat162float(Ahi[(size_t)(bm + i) * K + k]) +
                      __bfloat162float(Alo[(size_t)(bm + i) * K + k]);
            float b = __bfloat162float(Bhi[(size_t)(bn + j) * K + k]) +
                      __bfloat162float(Blo[(size_t)(bn + j) * K + k]);
            acc = fmaf(a, b, acc);
        }
        C[(size_t)(bm + i) * Nstride + bn + j] = acc;
    }
#endif
}

// ---------------------------------------------------------------------------
// Intra-chunk (dt folded in): dt -> dacs -> scores -> y_intra, chunk_state
// one block per (b, c, h); 256 threads
// ---------------------------------------------------------------------------
__global__ void __launch_bounds__(256)
intra_kernel(const float* __restrict__ dt_W, const float* __restrict__ dt_b,
             const float* __restrict__ A_log)
{
    const int bid = blockIdx.x;        // (b*NCHUNK + c)*NHEADS + h
    const int h   = bid & 15;
    const int bc  = bid >> 4;
    const int t0  = bc * CHUNK;
    const int tid = threadIdx.x;
    const int wid = tid >> 5;
    const int lid = tid & 31;

    __shared__ float xs[64][68];
    __shared__ float sc[64][68];
    __shared__ float Bsh[64][17];
    __shared__ float Csh[64][17];
    __shared__ float dts[64];
    __shared__ float dacs[64];
    __shared__ float wk[64];

    // loads
    for (int idx = tid; idx < 64 * 64; idx += 256) {
        int k = idx >> 6, p = idx & 63;
        xs[k][p] = g_proj[(size_t)(t0 + k) * PROJ + OFF_XP + h * HDIM + p];
    }
    for (int idx = tid; idx < 64 * 16; idx += 256) {
        int k = idx >> 4, n = idx & 15;
        Bsh[k][n] = g_proj[(size_t)(t0 + k) * PROJ + OFF_B + h * DSTATE + n];
        Csh[k][n] = g_proj[(size_t)(t0 + k) * PROJ + OFF_C + h * DSTATE + n];
    }
    // dt for this chunk: threads 0..63
    if (tid < 64) {
        const float* row = g_proj + (size_t)(t0 + tid) * PROJ + OFF_DT;
        float acc = dt_b[h];
#pragma unroll
        for (int r = 0; r < DTRANK; ++r)
            acc = fmaf(row[r], dt_W[h * DTRANK + r], acc);
        dts[tid] = (acc > 20.f) ? acc : log1pf(expf(acc));
    }
    __syncthreads();

    // parallel cumsum of dA (warp 0, 2 elems per lane)
    if (wid == 0) {
        float A  = -expf(A_log[h]);
        float v1 = dts[2 * lid + 1] * A;
        float s  = dts[2 * lid] * A + v1;
#pragma unroll
        for (int off = 1; off < 32; off <<= 1) {
            float t = __shfl_up_sync(0xffffffffu, s, off);
            if (lid >= off) s += t;
        }
        dacs[2 * lid + 1] = s;
        dacs[2 * lid]     = s - v1;
    }
    __syncthreads();

    if (tid < 64) {
        wk[tid] = dts[tid] * expf(dacs[63] - dacs[tid]);
        g_dacs[(size_t)(t0 + tid) * NHEADS + h] = dacs[tid];
    }
    if (tid == 0) g_cdecay[bid] = expf(dacs[63]);
    __syncthreads();

    // scores: thread owns row i = tid>>2, 16 j's
    {
        int i  = tid >> 2;
        int j0 = (tid & 3) * 16;
        float ci[16];
#pragma unroll
        for (int n = 0; n < 16; ++n) ci[n] = Csh[i][n];
        float di = dacs[i];
#pragma unroll
        for (int jj = 0; jj < 16; ++jj) {
            int j = j0 + jj;
            float v = 0.f;
            if (j <= i) {
                float d = 0.f;
#pragma unroll
                for (int n = 0; n < 16; ++n)
                    d = fmaf(ci[n], Bsh[j][n], d);
                v = d * expf(di - dacs[j]) * dts[j];
            }
            sc[i][j] = v;
        }
    }
    __syncthreads();

    // y_intra: 4x4 register blocking; thread (a,b): i in 4a.., p in 4b..
    {
        int a = tid >> 4;
        int b = tid & 15;
        int i0 = a * 4, p0 = b * 4;
        float acc[4][4];
#pragma unroll
        for (int q = 0; q < 4; ++q)
#pragma unroll
            for (int r = 0; r < 4; ++r) acc[q][r] = 0.f;
        for (int kk = 0; kk < 64; ++kk) {
            float xr0 = xs[kk][p0 + 0], xr1 = xs[kk][p0 + 1];
            float xr2 = xs[kk][p0 + 2], xr3 = xs[kk][p0 + 3];
#pragma unroll
            for (int q = 0; q < 4; ++q) {
                float s = sc[i0 + q][kk];
                acc[q][0] = fmaf(s, xr0, acc[q][0]);
                acc[q][1] = fmaf(s, xr1, acc[q][1]);
                acc[q][2] = fmaf(s, xr2, acc[q][2]);
                acc[q][3] = fmaf(s, xr3, acc[q][3]);
            }
        }
#pragma unroll
        for (int q = 0; q < 4; ++q) {
            float4 v = make_float4(acc[q][0], acc[q][1], acc[q][2], acc[q][3]);
            *reinterpret_cast<float4*>(
                g_y + (size_t)(t0 + i0 + q) * DINNER + h * HDIM + p0) = v;
        }
    }

    // chunk_state[n][p] = sum_k B[k][n] * wk[k] * x[k][p]
    for (int idx = tid; idx < DSTATE * HDIM; idx += 256) {
        int n = idx >> 6, p = idx & 63;
        float acc = 0.f;
        for (int k = 0; k < 64; ++k)
            acc = fmaf(Bsh[k][n] * wk[k], xs[k][p], acc);
        g_cs[(size_t)bid * (DSTATE * HDIM) + idx] = acc;
    }
}

// ---------------------------------------------------------------------------
// Sequential scan over chunks (software-pipelined loads)
// ---------------------------------------------------------------------------
__global__ void __launch_bounds__(256)
scan_kernel()
{
    const int bh  = blockIdx.x;
    const int b   = bh >> 4;
    const int h   = bh & 15;
    const int tid = threadIdx.x;

    float hv[4] = {0.f, 0.f, 0.f, 0.f};
    int    chid0 = (b * NCHUNK + 0) * NHEADS + h;
    size_t base  = (size_t)chid0 * (DSTATE * HDIM);
    float  cur[4];
#pragma unroll
    for (int j = 0; j < 4; ++j) cur[j] = g_cs[base + tid + j * 256];
    float d = g_cdecay[chid0];

    for (int c = 0; c < NCHUNK; ++c) {
        int    chid = (b * NCHUNK + c) * NHEADS + h;
        size_t bs   = (size_t)chid * (DSTATE * HDIM);
        float nxt[4];
        float dn = 0.f;
        if (c + 1 < NCHUNK) {
            size_t bn2 = bs + DSTATE * HDIM * NHEADS;
#pragma unroll
            for (int j = 0; j < 4; ++j) nxt[j] = g_cs[bn2 + tid + j * 256];
            dn = g_cdecay[chid + NHEADS];
        }
#pragma unroll
        for (int j = 0; j < 4; ++j) {
            g_hs[bs + tid + j * 256] = hv[j];
            hv[j] = fmaf(d, hv[j], cur[j]);
        }
        if (c + 1 < NCHUNK) {
#pragma unroll
            for (int j = 0; j < 4; ++j) cur[j] = nxt[j];
            d = dn;
        }
    }
}

// ---------------------------------------------------------------------------
// Cross-chunk + skip
// ---------------------------------------------------------------------------
__global__ void __launch_bounds__(256)
cross_kernel(const float* __restrict__ D_param)
{
    const int bid = blockIdx.x;
    const int h   = bid & 15;
    const int bc  = bid >> 4;
    const int t0  = bc * CHUNK;
    const int tid = threadIdx.x;

    __shared__ float hs[16][65];
    __shared__ float Csh[64][17];
    __shared__ float dacs[64];

    for (int idx = tid; idx < DSTATE * HDIM; idx += 256) {
        int n = idx >> 6, p = idx & 63;
        hs[n][p] = g_hs[(size_t)bid * (DSTATE * HDIM) + idx];
    }
    for (int idx = tid; idx < 64 * 16; idx += 256) {
        int k = idx >> 4, n = idx & 15;
        Csh[k][n] = g_proj[(size_t)(t0 + k) * PROJ + OFF_C + h * DSTATE + n];
    }
    if (tid < 64) dacs[tid] = g_dacs[(size_t)(t0 + tid) * NHEADS + h];
    __syncthreads();

    int i  = tid >> 2;
    int p0 = (tid & 3) * 16;
    float ci[16];
#pragma unroll
    for (int n = 0; n < 16; ++n) ci[n] = Csh[i][n];
    float e  = expf(dacs[i]);
    float dp = D_param[h];

    size_t t = (size_t)(t0 + i);
    const float* xrow = g_proj + t * PROJ + OFF_XP + h * HDIM;
    float* yrow = g_y + t * DINNER + h * HDIM;
#pragma unroll
    for (int pp = 0; pp < 16; ++pp) {
        int p = p0 + pp;
        float a = 0.f;
#pragma unroll
        for (int n = 0; n < 16; ++n)
            a = fmaf(ci[n], hs[n][p], a);
        yrow[p] = yrow[p] + e * a + dp * xrow[p];
    }
}

// ---------------------------------------------------------------------------
// RMS norm + SiLU gate -> yg (bf16 hi/lo for the out GEMM)
// ---------------------------------------------------------------------------
__global__ void __launch_bounds__(256)
norm_kernel(const float* __restrict__ norm_w)
{
    const int t   = blockIdx.x;
    const int tid = threadIdx.x;

    float4 v = reinterpret_cast<const float4*>(g_y + (size_t)t * DINNER)[tid];
    float ss = v.x * v.x + v.y * v.y + v.z * v.z + v.w * v.w;
#pragma unroll
    for (int off = 16; off > 0; off >>= 1)
        ss += __shfl_xor_sync(0xffffffffu, ss, off);

    __shared__ float red[8];
    __shared__ float s_inv;
    if ((tid & 31) == 0) red[tid >> 5] = ss;
    __syncthreads();
    if (tid == 0) {
        float s = 0.f;
#pragma unroll
        for (int i = 0; i < 8; ++i) s += red[i];
        s_inv = rsqrtf(s * (1.f / DINNER) + 1e-6f);
    }
    __syncthreads();
    float inv = s_inv;

    const float* zrow = g_proj + (size_t)t * PROJ + OFF_Z;
    int c = tid * 4;
    float4 z4 = *reinterpret_cast<const float4*>(zrow + c);
    float4 w4 = *reinterpret_cast<const float4*>(norm_w + c);
    float4 o;
    o.x = v.x * inv * w4.x * (z4.x / (1.f + expf(-z4.x)));
    o.y = v.y * inv * w4.y * (z4.y / (1.f + expf(-z4.y)));
    o.z = v.z * inv * w4.z * (z4.z / (1.f + expf(-z4.z)));
    o.w = v.w * inv * w4.w * (z4.w / (1.f + expf(-z4.w)));

    __nv_bfloat16 hx = __float2bfloat16(o.x), hy = __float2bfloat16(o.y);
    __nv_bfloat16 hz = __float2bfloat16(o.z), hw = __float2bfloat16(o.w);
    __nv_bfloat162 h01 = {hx, hy}, h23 = {hz, hw};
    __nv_bfloat162 l01 = {__float2bfloat16(o.x - __bfloat162float(hx)),
                          __float2bfloat16(o.y - __bfloat162float(hy))};
    __nv_bfloat162 l23 = {__float2bfloat16(o.z - __bfloat162float(hz)),
                          __float2bfloat16(o.w - __bfloat162float(hw))};
    size_t base2 = ((size_t)t * DINNER + c) >> 1;
    reinterpret_cast<__nv_bfloat162*>(g_yghi)[base2 + 0] = h01;
    reinterpret_cast<__nv_bfloat162*>(g_yghi)[base2 + 1] = h23;
    reinterpret_cast<__nv_bfloat162*>(g_yglo)[base2 + 0] = l01;
    reinterpret_cast<__nv_bfloat162*>(g_yglo)[base2 + 1] = l23;
}

// ---------------------------------------------------------------------------
// Launch — ordered so intra_kernel is launch #4 (profiled slot)
// ---------------------------------------------------------------------------
extern "C" void kernel_launch(void* const* d_in, const int* in_sizes, int n_in,
                              void* d_out, int out_size)
{
    const float* x      = (const float*)d_in[0];
    const float* W_in   = (const float*)d_in[1];
    const float* dt_W   = (const float*)d_in[2];
    const float* dt_b   = (const float*)d_in[3];
    const float* A_log  = (const float*)d_in[4];
    const float* D_par  = (const float*)d_in[5];
    const float* W_out  = (const float*)d_in[6];
    const float* norm_w = (const float*)d_in[7];
    float* out = (float*)d_out;

    float* proj_ptr = nullptr;
    __nv_bfloat16 *xhi, *xlo, *winhi, *winlo, *wouthi, *woutlo, *yghi, *yglo;
    cudaGetSymbolAddress((void**)&proj_ptr, g_proj);
    cudaGetSymbolAddress((void**)&xhi, g_xhi);
    cudaGetSymbolAddress((void**)&xlo, g_xlo);
    cudaGetSymbolAddress((void**)&winhi, g_winhi);
    cudaGetSymbolAddress((void**)&winlo, g_winlo);
    cudaGetSymbolAddress((void**)&wouthi, g_wouthi);
    cudaGetSymbolAddress((void**)&woutlo, g_woutlo);
    cudaGetSymbolAddress((void**)&yghi, g_yghi);
    cudaGetSymbolAddress((void**)&yglo, g_yglo);

    cudaFuncSetAttribute(gemm_tc, cudaFuncAttributeMaxDynamicSharedMemorySize, GEMM_SMEM_BYTES);

    // 1) split x
    {
        int n4 = TOKENS * DMODEL / 4;
        split_kernel<<<(n4 + 255) / 256, 256>>>(x, xhi, xlo, n4);
    }
    // 2) split W_in (padded)
    {
        int n4 = PROJPAD * DMODEL / 4;
        split_pad_kernel<<<(n4 + 255) / 256, 256>>>(W_in, winhi, winlo, PROJ, n4, DMODEL / 4);
    }
    // 3) proj = x @ W_in^T   [16384, 2576]
    {
        dim3 grid(PROJPAD / 128, TOKENS / 256);
        gemm_tc<<<grid, 256, GEMM_SMEM_BYTES>>>(xhi, xlo, winhi, winlo,
                                                proj_ptr, DMODEL, PROJ, PROJ);
    }
    // 4) intra-chunk (+dt)  <- profiled slot
    intra_kernel<<<BATCH * NCHUNK * NHEADS, 256>>>(dt_W, dt_b, A_log);
    // 5) chunk scan
    scan_kernel<<<BATCH * NHEADS, 256>>>();
    // 6) cross-chunk + skip
    cross_kernel<<<BATCH * NCHUNK * NHEADS, 256>>>(D_par);
    // 7) RMS norm + gate -> bf16 hi/lo
    norm_kernel<<<TOKENS, 256>>>(norm_w);
    // 8) split W_out
    {
        int n4 = DMODEL * DINNER / 4;
        split_kernel<<<(n4 + 255) / 256, 256>>>(W_out, wouthi, woutlo, n4);
    }
    // 9) out = yg @ W_out^T  [16384, 1024]
    {
        dim3 grid(DMODEL / 128, TOKENS / 256);
        gemm_tc<<<grid, 256, GEMM_SMEM_BYTES>>>(yghi, yglo, wouthi, woutlo,
                                                out, DINNER, DMODEL, DMODEL);
    }
}

// round 5
// speedup vs baseline: 4.2146x; 1.7839x over previous
#include <cuda_runtime.h>
#include <cuda_bf16.h>
#include <cstdint>

// ---------------------------------------------------------------------------
// Problem constants
// ---------------------------------------------------------------------------
#define BATCH   4
#define SEQ     4096
#define TOKENS  (BATCH * SEQ)        // 16384
#define DMODEL  1024
#define DINNER  1024
#define NHEADS  16
#define HDIM    64
#define DSTATE  16
#define DTRANK  16
#define CHUNK   64
#define NCHUNK  (SEQ / CHUNK)        // 64
#define PROJ    2576
#define PROJPAD 2688                 // 21 * 128

#define OFF_XP   0
#define OFF_Z    1024
#define OFF_B    2048
#define OFF_C    2304
#define OFF_DT   2560

// tcgen05 is an arch-SPECIFIC feature: only emit it in the sm_103a/f passes.
#if defined(__CUDA_ARCH_FEAT_SM103_ALL) || \
    (defined(__CUDA_ARCH_FAMILY_SPECIFIC__) && __CUDA_ARCH_FAMILY_SPECIFIC__ >= 1000) || \
    (defined(__CUDA_ARCH_SPECIFIC__) && __CUDA_ARCH_SPECIFIC__ >= 1000)
#define HAS_TCGEN05 1
#else
#define HAS_TCGEN05 0
#endif

// ---------------------------------------------------------------------------
// PTX helpers (guarded)
// ---------------------------------------------------------------------------
#if HAS_TCGEN05
__device__ __forceinline__ uint32_t smem_to_u32(const void* p) {
    uint32_t a;
    asm("{ .reg .u64 t; cvta.to.shared.u64 t, %1; cvt.u32.u64 %0, t; }" : "=r"(a) : "l"(p));
    return a;
}
__device__ __forceinline__ uint32_t elect_one_pred() {
    uint32_t pred;
    asm volatile("{\n\t.reg .pred p;\n\telect.sync _|p, 0xFFFFFFFF;\n\tselp.b32 %0, 1, 0, p;\n\t}" : "=r"(pred));
    return pred;
}
#define TCGEN05_ALLOC(smem_result_addr, nCols) \
    asm volatile("tcgen05.alloc.cta_group::1.sync.aligned.shared::cta.b32 [%0], %1;" \
        :: "r"((uint32_t)(smem_result_addr)), "r"((uint32_t)(nCols)) : "memory")
#define TCGEN05_DEALLOC(tmem_addr, nCols) \
    asm volatile("tcgen05.dealloc.cta_group::1.sync.aligned.b32 %0, %1;" :: "r"(tmem_addr), "r"((uint32_t)(nCols)))
#define TCGEN05_RELINQUISH() \
    asm volatile("tcgen05.relinquish_alloc_permit.cta_group::1.sync.aligned;")
#define TCGEN05_COMMIT(mbar) \
    asm volatile("tcgen05.commit.cta_group::1.mbarrier::arrive::one.shared::cluster.b64 [%0];" \
        :: "r"((uint32_t)(mbar)) : "memory")
#define TCGEN05_FENCE_AFTER()  asm volatile("tcgen05.fence::after_thread_sync;" ::: "memory")
#define TCGEN05_FENCE_BEFORE() asm volatile("tcgen05.fence::before_thread_sync;" ::: "memory")
#define TCGEN05_WAIT_LD()      asm volatile("tcgen05.wait::ld.sync.aligned;" ::: "memory")
#define MBARRIER_INIT(mbar, count) \
    asm volatile("mbarrier.init.shared.b64 [%0], %1;" :: "r"((uint32_t)(mbar)), "r"((uint32_t)(count)) : "memory")
#define FENCE_PROXY_ASYNC() asm volatile("fence.proxy.async.shared::cta;" ::: "memory")
#define STS128(a, r0, r1, r2, r3) \
    asm volatile("st.shared.v4.b32 [%0], {%1, %2, %3, %4};" :: "r"(a), "r"(r0), "r"(r1), "r"(r2), "r"(r3) : "memory")
#define MBARRIER_WAIT_PARITY(mbar, parity) do { \
    uint32_t _m = (uint32_t)(mbar); uint32_t _p = (uint32_t)(parity); uint32_t _d; \
    asm volatile("{\n\t.reg .pred p;\n\t" \
        "mbarrier.try_wait.parity.acquire.cta.shared::cta.b64 p, [%1], %2;\n\t" \
        "selp.b32 %0, 1, 0, p;\n\t}" : "=r"(_d) : "r"(_m), "r"(_p) : "memory"); \
    if (!_d) { \
        asm volatile("{\n\t.reg .pred P1;\n\t" \
            "WL_%=:\n\t" \
            "mbarrier.try_wait.parity.acquire.cta.shared::cta.b64 P1, [%0], %1, 0x989680;\n\t" \
            "@P1 bra.uni WD_%=;\n\t" \
            "bra.uni WL_%=;\n\t" \
            "WD_%=:\n\t}" :: "r"(_m), "r"(_p) : "memory"); \
    } } while (0)
#define TCGEN05_LD_32X32B_X32(r, tmem_addr) \
    asm volatile("tcgen05.ld.sync.aligned.32x32b.x32.b32 " \
        "{%0, %1, %2, %3, %4, %5, %6, %7, %8, %9, %10, %11, %12, %13, %14, %15, " \
        " %16, %17, %18, %19, %20, %21, %22, %23, %24, %25, %26, %27, %28, %29, %30, %31}, [%32];" \
        : "=r"((r)[0]),  "=r"((r)[1]),  "=r"((r)[2]),  "=r"((r)[3]), \
          "=r"((r)[4]),  "=r"((r)[5]),  "=r"((r)[6]),  "=r"((r)[7]), \
          "=r"((r)[8]),  "=r"((r)[9]),  "=r"((r)[10]), "=r"((r)[11]), \
          "=r"((r)[12]), "=r"((r)[13]), "=r"((r)[14]), "=r"((r)[15]), \
          "=r"((r)[16]), "=r"((r)[17]), "=r"((r)[18]), "=r"((r)[19]), \
          "=r"((r)[20]), "=r"((r)[21]), "=r"((r)[22]), "=r"((r)[23]), \
          "=r"((r)[24]), "=r"((r)[25]), "=r"((r)[26]), "=r"((r)[27]), \
          "=r"((r)[28]), "=r"((r)[29]), "=r"((r)[30]), "=r"((r)[31]) \
        : "r"(tmem_addr))

static constexpr uint64_t SMEM_DESC_BASE_SW128 =
    (uint64_t(2) << 61) | (uint64_t(1) << 46) | (uint64_t(64) << 32) | (uint64_t(1) << 16);
#define MAKE_SMEM_DESC(base_addr) (SMEM_DESC_BASE_SW128 | ((uint64_t)((base_addr) >> 4) & 0x3FFF))

// idesc: dtype=F32(bit4), atype=BF16(bit7), btype=BF16(bit10), N/8 @17, M/16 @24
#define MMA_IDESC_128x128 ((1u << 4) | (1u << 7) | (1u << 10) | (16u << 17) | (8u << 24))

__device__ __forceinline__ void mma_f16_ss(uint32_t d_tmem, uint64_t a_desc, uint64_t b_desc,
                                           uint32_t idesc, uint32_t enable)
{
    asm volatile(
        "{\n\t.reg .pred p;\n\t"
        "setp.ne.u32 p, %4, 0;\n\t"
        "tcgen05.mma.cta_group::1.kind::f16 [%0], %1, %2, %3, {%5, %5, %5, %5}, p;\n\t"
        "}"
        :: "r"(d_tmem), "l"(a_desc), "l"(b_desc), "r"(idesc), "r"(enable), "r"(0u)
        : "memory");
}
#endif  // HAS_TCGEN05

// ---------------------------------------------------------------------------
// Scratch (device globals; no allocation allowed)
// ---------------------------------------------------------------------------
__device__ float g_proj[(size_t)TOKENS * PROJ];
__device__ float g_dacs[(size_t)TOKENS * NHEADS];
__device__ float g_y[(size_t)TOKENS * DINNER];
__device__ float g_cs[(size_t)BATCH * NCHUNK * NHEADS * DSTATE * HDIM];
__device__ float g_hs[(size_t)BATCH * NCHUNK * NHEADS * DSTATE * HDIM];
__device__ float g_cdecay[(size_t)BATCH * NCHUNK * NHEADS];

__device__ __nv_bfloat16 g_xhi[(size_t)TOKENS * DMODEL];
__device__ __nv_bfloat16 g_xlo[(size_t)TOKENS * DMODEL];
__device__ __nv_bfloat16 g_winhi[(size_t)PROJPAD * DMODEL];
__device__ __nv_bfloat16 g_winlo[(size_t)PROJPAD * DMODEL];
__device__ __nv_bfloat16 g_wouthi[(size_t)DMODEL * DINNER];
__device__ __nv_bfloat16 g_woutlo[(size_t)DMODEL * DINNER];
__device__ __nv_bfloat16 g_yghi[(size_t)TOKENS * DINNER];
__device__ __nv_bfloat16 g_yglo[(size_t)TOKENS * DINNER];

// ---------------------------------------------------------------------------
// Split fp32 -> bf16 hi/lo
// ---------------------------------------------------------------------------
__global__ void __launch_bounds__(256)
split_kernel(const float* __restrict__ src, __nv_bfloat16* __restrict__ hi,
             __nv_bfloat16* __restrict__ lo, int n4)
{
    int i = blockIdx.x * 256 + threadIdx.x;
    if (i >= n4) return;
    float4 v = reinterpret_cast<const float4*>(src)[i];
    __nv_bfloat16 hx = __float2bfloat16(v.x), hy = __float2bfloat16(v.y);
    __nv_bfloat16 hz = __float2bfloat16(v.z), hw = __float2bfloat16(v.w);
    __nv_bfloat162 h01 = {hx, hy}, h23 = {hz, hw};
    __nv_bfloat162 l01 = {__float2bfloat16(v.x - __bfloat162float(hx)),
                          __float2bfloat16(v.y - __bfloat162float(hy))};
    __nv_bfloat162 l23 = {__float2bfloat16(v.z - __bfloat162float(hz)),
                          __float2bfloat16(v.w - __bfloat162float(hw))};
    reinterpret_cast<__nv_bfloat162*>(hi)[i * 2 + 0] = h01;
    reinterpret_cast<__nv_bfloat162*>(hi)[i * 2 + 1] = h23;
    reinterpret_cast<__nv_bfloat162*>(lo)[i * 2 + 0] = l01;
    reinterpret_cast<__nv_bfloat162*>(lo)[i * 2 + 1] = l23;
}

__global__ void __launch_bounds__(256)
split_pad_kernel(const float* __restrict__ src, __nv_bfloat16* __restrict__ hi,
                 __nv_bfloat16* __restrict__ lo, int rows_src, int n4, int K4)
{
    int i = blockIdx.x * 256 + threadIdx.x;
    if (i >= n4) return;
    int row = i / K4;
    float4 v = make_float4(0.f, 0.f, 0.f, 0.f);
    if (row < rows_src) v = reinterpret_cast<const float4*>(src)[i];
    __nv_bfloat16 hx = __float2bfloat16(v.x), hy = __float2bfloat16(v.y);
    __nv_bfloat16 hz = __float2bfloat16(v.z), hw = __float2bfloat16(v.w);
    __nv_bfloat162 h01 = {hx, hy}, h23 = {hz, hw};
    __nv_bfloat162 l01 = {__float2bfloat16(v.x - __bfloat162float(hx)),
                          __float2bfloat16(v.y - __bfloat162float(hy))};
    __nv_bfloat162 l23 = {__float2bfloat16(v.z - __bfloat162float(hz)),
                          __float2bfloat16(v.w - __bfloat162float(hw))};
    reinterpret_cast<__nv_bfloat162*>(hi)[i * 2 + 0] = h01;
    reinterpret_cast<__nv_bfloat162*>(hi)[i * 2 + 1] = h23;
    reinterpret_cast<__nv_bfloat162*>(lo)[i * 2 + 0] = l01;
    reinterpret_cast<__nv_bfloat162*>(lo)[i * 2 + 1] = l23;
}

// ---------------------------------------------------------------------------
// tcgen05 bf16-split GEMM:  C[M, Nout] (stride Nstride) = A * B^T
// Tile 256x128 (two M-atoms of 128), K-chunks of 64, double-buffered SMEM.
// ---------------------------------------------------------------------------
#define STAGE_BYTES 98304
#define GEMM_SMEM_BYTES (1024 + 2 * STAGE_BYTES + 1024)

__global__ void __launch_bounds__(256, 1)
gemm_tc(const __nv_bfloat16* __restrict__ Ahi, const __nv_bfloat16* __restrict__ Alo,
        const __nv_bfloat16* __restrict__ Bhi, const __nv_bfloat16* __restrict__ Blo,
        float* __restrict__ C, int K, int Nstride, int Nout)
{
#if HAS_TCGEN05
    extern __shared__ char smem[];
    const uint32_t sbase = smem_to_u32(smem);
    const int tid = threadIdx.x;
    const int wid = tid >> 5;
    const int lid = tid & 31;
    const int bm = blockIdx.y * 256;
    const int bn = blockIdx.x * 128;

    const uint32_t TMEMP = sbase;
    const uint32_t MBAR0 = sbase + 8;
    const uint32_t MBAR1 = sbase + 16;
    const uint32_t BUF   = (sbase + 32 + 1023) & ~1023u;

    if (wid == 0) {
        TCGEN05_ALLOC(TMEMP, 256);
        TCGEN05_RELINQUISH();
    }
    if (tid == 0) { MBARRIER_INIT(MBAR0, 1); MBARRIER_INIT(MBAR1, 1); }
    __syncthreads();
    uint32_t tmem;
    asm volatile("ld.shared.b32 %0, [%1];" : "=r"(tmem) : "r"(TMEMP));

    const __nv_bfloat16* pAhi = Ahi + (size_t)bm * K;
    const __nv_bfloat16* pAlo = Alo + (size_t)bm * K;
    const __nv_bfloat16* pBhi = Bhi + (size_t)bn * K;
    const __nv_bfloat16* pBlo = Blo + (size_t)bn * K;

    const int NC = K >> 6;   // chunks of 64
    for (int c = 0; c < NC; ++c) {
        const uint32_t stage = BUF + (uint32_t)(c & 1) * (uint32_t)STAGE_BYTES;
        if (c >= 2) {
            MBARRIER_WAIT_PARITY((c & 1) ? MBAR1 : MBAR0, ((c >> 1) - 1) & 1);
        }
        const int k0 = c << 6;
#pragma unroll
        for (int it = 0; it < 8; ++it) {
            int u = it * 256 + tid;            // 0..2047
            int row = u >> 3;                  // 0..255
            int q   = u & 7;
            uint4 vh = *reinterpret_cast<const uint4*>(pAhi + (size_t)row * K + k0 + q * 8);
            uint4 vl = *reinterpret_cast<const uint4*>(pAlo + (size_t)row * K + k0 + q * 8);
            uint32_t boff = (uint32_t)(row * 128 + q * 16);
            uint32_t sw = boff ^ ((boff >> 3) & 0x70);
            STS128(stage + sw,          vh.x, vh.y, vh.z, vh.w);
            STS128(stage + 32768u + sw, vl.x, vl.y, vl.z, vl.w);
        }
#pragma unroll
        for (int it = 0; it < 4; ++it) {
            int u = it * 256 + tid;            // 0..1023
            int row = u >> 3;                  // 0..127
            int q   = u & 7;
            uint4 vh = *reinterpret_cast<const uint4*>(pBhi + (size_t)row * K + k0 + q * 8);
            uint4 vl = *reinterpret_cast<const uint4*>(pBlo + (size_t)row * K + k0 + q * 8);
            uint32_t boff = (uint32_t)(row * 128 + q * 16);
            uint32_t sw = boff ^ ((boff >> 3) & 0x70);
            STS128(stage + 65536u + sw, vh.x, vh.y, vh.z, vh.w);
            STS128(stage + 81920u + sw, vl.x, vl.y, vl.z, vl.w);
        }
        __syncthreads();

        if (wid == 0) {
            FENCE_PROXY_ASYNC();
            if (elect_one_pred()) {
                uint64_t dA0h = MAKE_SMEM_DESC(stage);
                uint64_t dA1h = MAKE_SMEM_DESC(stage + 16384);
                uint64_t dA0l = MAKE_SMEM_DESC(stage + 32768);
                uint64_t dA1l = MAKE_SMEM_DESC(stage + 49152);
                uint64_t dBh  = MAKE_SMEM_DESC(stage + 65536);
                uint64_t dBl  = MAKE_SMEM_DESC(stage + 81920);
#pragma unroll
                for (int ks = 0; ks < 4; ++ks) {
                    uint32_t en0 = (c == 0 && ks == 0) ? 0u : 1u;
                    mma_f16_ss(tmem,       dA0h + ks * 2, dBh + ks * 2, MMA_IDESC_128x128, en0);
                    mma_f16_ss(tmem,       dA0h + ks * 2, dBl + ks * 2, MMA_IDESC_128x128, 1u);
                    mma_f16_ss(tmem,       dA0l + ks * 2, dBh + ks * 2, MMA_IDESC_128x128, 1u);
                    mma_f16_ss(tmem + 128, dA1h + ks * 2, dBh + ks * 2, MMA_IDESC_128x128, en0);
                    mma_f16_ss(tmem + 128, dA1h + ks * 2, dBl + ks * 2, MMA_IDESC_128x128, 1u);
                    mma_f16_ss(tmem + 128, dA1l + ks * 2, dBh + ks * 2, MMA_IDESC_128x128, 1u);
                }
                TCGEN05_COMMIT((c & 1) ? MBAR1 : MBAR0);
            }
        }
    }

    MBARRIER_WAIT_PARITY(MBAR0, ((NC - 2) >> 1) & 1);
    MBARRIER_WAIT_PARITY(MBAR1, ((NC - 1) >> 1) & 1);
    TCGEN05_FENCE_AFTER();

    {
        int mt  = wid >> 2;                       // 0 or 1
        int row = bm + mt * 128 + (wid & 3) * 32 + lid;
        float* crow = C + (size_t)row * Nstride + bn;
        uint32_t tcol = tmem + (uint32_t)(mt * 128);
#pragma unroll
        for (int g = 0; g < 4; ++g) {
            uint32_t r[32];
            TCGEN05_LD_32X32B_X32(r, tcol + g * 32);
            TCGEN05_WAIT_LD();
            int n0 = bn + g * 32;
            if (n0 + 32 <= Nout) {
#pragma unroll
                for (int j = 0; j < 32; j += 4) {
                    float4 v = make_float4(__uint_as_float(r[j]), __uint_as_float(r[j + 1]),
                                           __uint_as_float(r[j + 2]), __uint_as_float(r[j + 3]));
                    *reinterpret_cast<float4*>(crow + g * 32 + j) = v;
                }
            } else {
                for (int j = 0; j < 32; ++j)
                    if (n0 + j < Nout) crow[g * 32 + j] = __uint_as_float(r[j]);
            }
        }
        TCGEN05_FENCE_BEFORE();
    }
    __syncthreads();
    if (wid == 0) TCGEN05_DEALLOC(tmem, 256);

#else   // ---------------- SIMT fallback (generic PTX pass only; never runs) --
    const int tid = threadIdx.x;
    const int bm  = blockIdx.y * 256;
    const int bn  = blockIdx.x * 128;
    for (int e = tid; e < 256 * 128; e += 256) {
        int i = e >> 7, j = e & 127;
        if (bn + j >= Nout) continue;
        float acc = 0.f;
        for (int k = 0; k < K; ++k) {
            float a = __bfloat162float(Ahi[(size_t)(bm + i) * K + k]) +
                      __bfloat162float(Alo[(size_t)(bm + i) * K + k]);
            float b = __bfloat162float(Bhi[(size_t)(bn + j) * K + k]) +
                      __bfloat162float(Blo[(size_t)(bn + j) * K + k]);
            acc = fmaf(a, b, acc);
        }
        C[(size_t)(bm + i) * Nstride + bn + j] = acc;
    }
#endif
}

// ---------------------------------------------------------------------------
// Intra-chunk (dt folded in): dt -> dacs -> scores -> y_intra, chunk_state
// one block per (b, c, h); 256 threads; 2 CTAs/SM
// ---------------------------------------------------------------------------
__global__ void __launch_bounds__(256, 2)
intra_kernel(const float* __restrict__ dt_W, const float* __restrict__ dt_b,
             const float* __restrict__ A_log)
{
    const int bid = blockIdx.x;        // (b*NCHUNK + c)*NHEADS + h
    const int h   = bid & 15;
    const int bc  = bid >> 4;
    const int t0  = bc * CHUNK;
    const int tid = threadIdx.x;
    const int wid = tid >> 5;
    const int lid = tid & 31;

    __shared__ float xs[64][68];
    __shared__ float sc[64][68];
    __shared__ float Bsh[64][20];
    __shared__ float Csh[64][20];   // reused as bw after scores
    __shared__ float dts[64];
    __shared__ float dacs[64];
    __shared__ float wk[64];

    // vectorized loads: xs = 64 rows x 16 float4
    for (int idx = tid; idx < 64 * 16; idx += 256) {
        int k = idx >> 4, p4 = idx & 15;
        float4 v = *reinterpret_cast<const float4*>(
            g_proj + (size_t)(t0 + k) * PROJ + OFF_XP + h * HDIM + p4 * 4);
        *reinterpret_cast<float4*>(&xs[k][p4 * 4]) = v;
    }
    // B, C: 64 rows x 4 float4 each (exactly 256 threads)
    {
        int k = tid >> 2, n4 = tid & 3;
        float4 vb = *reinterpret_cast<const float4*>(
            g_proj + (size_t)(t0 + k) * PROJ + OFF_B + h * DSTATE + n4 * 4);
        float4 vc = *reinterpret_cast<const float4*>(
            g_proj + (size_t)(t0 + k) * PROJ + OFF_C + h * DSTATE + n4 * 4);
        *reinterpret_cast<float4*>(&Bsh[k][n4 * 4]) = vb;
        *reinterpret_cast<float4*>(&Csh[k][n4 * 4]) = vc;
    }
    // dt for this chunk: threads 0..63
    if (tid < 64) {
        const float* row = g_proj + (size_t)(t0 + tid) * PROJ + OFF_DT;
        float acc = dt_b[h];
#pragma unroll
        for (int r = 0; r < DTRANK; ++r)
            acc = fmaf(row[r], dt_W[h * DTRANK + r], acc);
        dts[tid] = (acc > 20.f) ? acc : log1pf(expf(acc));
    }
    __syncthreads();

    // parallel cumsum of dA (warp 0, 2 elems per lane)
    if (wid == 0) {
        float A  = -expf(A_log[h]);
        float v1 = dts[2 * lid + 1] * A;
        float s  = dts[2 * lid] * A + v1;
#pragma unroll
        for (int off = 1; off < 32; off <<= 1) {
            float t = __shfl_up_sync(0xffffffffu, s, off);
            if (lid >= off) s += t;
        }
        dacs[2 * lid + 1] = s;
        dacs[2 * lid]     = s - v1;
    }
    __syncthreads();

    if (tid < 64) {
        wk[tid] = dts[tid] * expf(dacs[63] - dacs[tid]);
        g_dacs[(size_t)(t0 + tid) * NHEADS + h] = dacs[tid];
    }
    if (tid == 0) g_cdecay[bid] = expf(dacs[63]);
    __syncthreads();

    // scores: thread owns row i = tid>>2, 16 j's (zeros above diagonal)
    {
        int i  = tid >> 2;
        int j0 = (tid & 3) * 16;
        float ci[16];
#pragma unroll
        for (int n = 0; n < 16; ++n) ci[n] = Csh[i][n];
        float di = dacs[i];
#pragma unroll
        for (int jj = 0; jj < 16; ++jj) {
            int j = j0 + jj;
            float v = 0.f;
            if (j <= i) {
                float d = 0.f;
#pragma unroll
                for (int n = 0; n < 16; ++n)
                    d = fmaf(ci[n], Bsh[j][n], d);
                v = d * expf(di - dacs[j]) * dts[j];
            }
            sc[i][j] = v;
        }
    }
    __syncthreads();

    // bw[k][n] = B[k][n] * wk[k]  (overwrite Csh, dead after scores)
    for (int idx = tid; idx < 64 * 16; idx += 256) {
        int k = idx >> 4, n = idx & 15;
        Csh[k][n] = Bsh[k][n] * wk[k];
    }
    __syncthreads();

    // y_intra: 4x4 register blocking, causal-truncated k loop
    {
        int a  = tid >> 4;
        int b  = tid & 15;
        int i0 = a * 4, p0 = b * 4;
        float acc[4][4];
#pragma unroll
        for (int q = 0; q < 4; ++q)
#pragma unroll
            for (int r = 0; r < 4; ++r) acc[q][r] = 0.f;
        const int kmax = i0 + 4;          // sc[i][k] = 0 for k > i
        for (int kk = 0; kk < kmax; ++kk) {
            float4 xr = *reinterpret_cast<const float4*>(&xs[kk][p0]);
#pragma unroll
            for (int q = 0; q < 4; ++q) {
                float s = sc[i0 + q][kk];
                acc[q][0] = fmaf(s, xr.x, acc[q][0]);
                acc[q][1] = fmaf(s, xr.y, acc[q][1]);
                acc[q][2] = fmaf(s, xr.z, acc[q][2]);
                acc[q][3] = fmaf(s, xr.w, acc[q][3]);
            }
        }
#pragma unroll
        for (int q = 0; q < 4; ++q) {
            float4 v = make_float4(acc[q][0], acc[q][1], acc[q][2], acc[q][3]);
            *reinterpret_cast<float4*>(
                g_y + (size_t)(t0 + i0 + q) * DINNER + h * HDIM + p0) = v;
        }
    }

    // chunk_state[n][p] = sum_k bw[k][n] * x[k][p]; thread = (n, 4 p's)
    {
        int n  = tid >> 4;
        int p0 = (tid & 15) * 4;
        float4 acc = make_float4(0.f, 0.f, 0.f, 0.f);
        for (int k = 0; k < 64; ++k) {
            float bwv = Csh[k][n];
            float4 xr = *reinterpret_cast<const float4*>(&xs[k][p0]);
            acc.x = fmaf(bwv, xr.x, acc.x);
            acc.y = fmaf(bwv, xr.y, acc.y);
            acc.z = fmaf(bwv, xr.z, acc.z);
            acc.w = fmaf(bwv, xr.w, acc.w);
        }
        *reinterpret_cast<float4*>(
            g_cs + (size_t)bid * (DSTATE * HDIM) + n * HDIM + p0) = acc;
    }
}

// ---------------------------------------------------------------------------
// Sequential scan over chunks (software-pipelined loads)
// ---------------------------------------------------------------------------
__global__ void __launch_bounds__(256)
scan_kernel()
{
    const int bh  = blockIdx.x;
    const int b   = bh >> 4;
    const int h   = bh & 15;
    const int tid = threadIdx.x;

    float hv[4] = {0.f, 0.f, 0.f, 0.f};
    int    chid0 = (b * NCHUNK + 0) * NHEADS + h;
    size_t base  = (size_t)chid0 * (DSTATE * HDIM);
    float  cur[4];
#pragma unroll
    for (int j = 0; j < 4; ++j) cur[j] = g_cs[base + tid + j * 256];
    float d = g_cdecay[chid0];

    for (int c = 0; c < NCHUNK; ++c) {
        int    chid = (b * NCHUNK + c) * NHEADS + h;
        size_t bs   = (size_t)chid * (DSTATE * HDIM);
        float nxt[4];
        float dn = 0.f;
        if (c + 1 < NCHUNK) {
            size_t bn2 = bs + DSTATE * HDIM * NHEADS;
#pragma unroll
            for (int j = 0; j < 4; ++j) nxt[j] = g_cs[bn2 + tid + j * 256];
            dn = g_cdecay[chid + NHEADS];
        }
#pragma unroll
        for (int j = 0; j < 4; ++j) {
            g_hs[bs + tid + j * 256] = hv[j];
            hv[j] = fmaf(d, hv[j], cur[j]);
        }
        if (c + 1 < NCHUNK) {
#pragma unroll
            for (int j = 0; j < 4; ++j) cur[j] = nxt[j];
            d = dn;
        }
    }
}

// ---------------------------------------------------------------------------
// Cross-chunk + skip
// ---------------------------------------------------------------------------
__global__ void __launch_bounds__(256, 2)
cross_kernel(const float* __restrict__ D_param)
{
    const int bid = blockIdx.x;
    const int h   = bid & 15;
    const int bc  = bid >> 4;
    const int t0  = bc * CHUNK;
    const int tid = threadIdx.x;

    __shared__ float hs[16][68];
    __shared__ float Csh[64][20];
    __shared__ float dacs[64];

    // hs: 16 x 16 float4 (exactly 256 threads)
    {
        int n = tid >> 4, pg = tid & 15;
        float4 v = *reinterpret_cast<const float4*>(
            g_hs + (size_t)bid * (DSTATE * HDIM) + n * HDIM + pg * 4);
        *reinterpret_cast<float4*>(&hs[n][pg * 4]) = v;
    }
    // C: 64 rows x 4 float4
    {
        int k = tid >> 2, n4 = tid & 3;
        float4 vc = *reinterpret_cast<const float4*>(
            g_proj + (size_t)(t0 + k) * PROJ + OFF_C + h * DSTATE + n4 * 4);
        *reinterpret_cast<float4*>(&Csh[k][n4 * 4]) = vc;
    }
    if (tid < 64) dacs[tid] = g_dacs[(size_t)(t0 + tid) * NHEADS + h];
    __syncthreads();

    int i  = tid >> 2;
    int p0 = (tid & 3) * 16;
    float ci[16];
#pragma unroll
    for (int n = 0; n < 16; ++n) ci[n] = Csh[i][n];
    float e  = expf(dacs[i]);
    float dp = D_param[h];

    size_t t = (size_t)(t0 + i);
    const float* xrow = g_proj + t * PROJ + OFF_XP + h * HDIM;
    float* yrow = g_y + t * DINNER + h * HDIM;
#pragma unroll
    for (int g4 = 0; g4 < 4; ++g4) {
        int p = p0 + g4 * 4;
        float4 yv = *reinterpret_cast<const float4*>(yrow + p);
        float4 xv = *reinterpret_cast<const float4*>(xrow + p);
        float a0 = 0.f, a1 = 0.f, a2 = 0.f, a3 = 0.f;
#pragma unroll
        for (int n = 0; n < 16; ++n) {
            float c = ci[n];
            a0 = fmaf(c, hs[n][p + 0], a0);
            a1 = fmaf(c, hs[n][p + 1], a1);
            a2 = fmaf(c, hs[n][p + 2], a2);
            a3 = fmaf(c, hs[n][p + 3], a3);
        }
        float4 o;
        o.x = yv.x + e * a0 + dp * xv.x;
        o.y = yv.y + e * a1 + dp * xv.y;
        o.z = yv.z + e * a2 + dp * xv.z;
        o.w = yv.w + e * a3 + dp * xv.w;
        *reinterpret_cast<float4*>(yrow + p) = o;
    }
}

// ---------------------------------------------------------------------------
// RMS norm + SiLU gate -> yg (bf16 hi/lo for the out GEMM)
// ---------------------------------------------------------------------------
__global__ void __launch_bounds__(256)
norm_kernel(const float* __restrict__ norm_w)
{
    const int t   = blockIdx.x;
    const int tid = threadIdx.x;

    float4 v = reinterpret_cast<const float4*>(g_y + (size_t)t * DINNER)[tid];
    float ss = v.x * v.x + v.y * v.y + v.z * v.z + v.w * v.w;
#pragma unroll
    for (int off = 16; off > 0; off >>= 1)
        ss += __shfl_xor_sync(0xffffffffu, ss, off);

    __shared__ float red[8];
    __shared__ float s_inv;
    if ((tid & 31) == 0) red[tid >> 5] = ss;
    __syncthreads();
    if (tid == 0) {
        float s = 0.f;
#pragma unroll
        for (int i = 0; i < 8; ++i) s += red[i];
        s_inv = rsqrtf(s * (1.f / DINNER) + 1e-6f);
    }
    __syncthreads();
    float inv = s_inv;

    const float* zrow = g_proj + (size_t)t * PROJ + OFF_Z;
    int c = tid * 4;
    float4 z4 = *reinterpret_cast<const float4*>(zrow + c);
    float4 w4 = *reinterpret_cast<const float4*>(norm_w + c);
    float4 o;
    o.x = v.x * inv * w4.x * (z4.x / (1.f + expf(-z4.x)));
    o.y = v.y * inv * w4.y * (z4.y / (1.f + expf(-z4.y)));
    o.z = v.z * inv * w4.z * (z4.z / (1.f + expf(-z4.z)));
    o.w = v.w * inv * w4.w * (z4.w / (1.f + expf(-z4.w)));

    __nv_bfloat16 hx = __float2bfloat16(o.x), hy = __float2bfloat16(o.y);
    __nv_bfloat16 hz = __float2bfloat16(o.z), hw = __float2bfloat16(o.w);
    __nv_bfloat162 h01 = {hx, hy}, h23 = {hz, hw};
    __nv_bfloat162 l01 = {__float2bfloat16(o.x - __bfloat162float(hx)),
                          __float2bfloat16(o.y - __bfloat162float(hy))};
    __nv_bfloat162 l23 = {__float2bfloat16(o.z - __bfloat162float(hz)),
                          __float2bfloat16(o.w - __bfloat162float(hw))};
    size_t base2 = ((size_t)t * DINNER + c) >> 1;
    reinterpret_cast<__nv_bfloat162*>(g_yghi)[base2 + 0] = h01;
    reinterpret_cast<__nv_bfloat162*>(g_yghi)[base2 + 1] = h23;
    reinterpret_cast<__nv_bfloat162*>(g_yglo)[base2 + 0] = l01;
    reinterpret_cast<__nv_bfloat162*>(g_yglo)[base2 + 1] = l23;
}

// ---------------------------------------------------------------------------
// Launch — intra_kernel stays at launch #4 (profiled slot)
// ---------------------------------------------------------------------------
extern "C" void kernel_launch(void* const* d_in, const int* in_sizes, int n_in,
                              void* d_out, int out_size)
{
    const float* x      = (const float*)d_in[0];
    const float* W_in   = (const float*)d_in[1];
    const float* dt_W   = (const float*)d_in[2];
    const float* dt_b   = (const float*)d_in[3];
    const float* A_log  = (const float*)d_in[4];
    const float* D_par  = (const float*)d_in[5];
    const float* W_out  = (const float*)d_in[6];
    const float* norm_w = (const float*)d_in[7];
    float* out = (float*)d_out;

    float* proj_ptr = nullptr;
    __nv_bfloat16 *xhi, *xlo, *winhi, *winlo, *wouthi, *woutlo, *yghi, *yglo;
    cudaGetSymbolAddress((void**)&proj_ptr, g_proj);
    cudaGetSymbolAddress((void**)&xhi, g_xhi);
    cudaGetSymbolAddress((void**)&xlo, g_xlo);
    cudaGetSymbolAddress((void**)&winhi, g_winhi);
    cudaGetSymbolAddress((void**)&winlo, g_winlo);
    cudaGetSymbolAddress((void**)&wouthi, g_wouthi);
    cudaGetSymbolAddress((void**)&woutlo, g_woutlo);
    cudaGetSymbolAddress((void**)&yghi, g_yghi);
    cudaGetSymbolAddress((void**)&yglo, g_yglo);

    cudaFuncSetAttribute(gemm_tc, cudaFuncAttributeMaxDynamicSharedMemorySize, GEMM_SMEM_BYTES);

    // 1) split x
    {
        int n4 = TOKENS * DMODEL / 4;
        split_kernel<<<(n4 + 255) / 256, 256>>>(x, xhi, xlo, n4);
    }
    // 2) split W_in (padded)
    {
        int n4 = PROJPAD * DMODEL / 4;
        split_pad_kernel<<<(n4 + 255) / 256, 256>>>(W_in, winhi, winlo, PROJ, n4, DMODEL / 4);
    }
    // 3) proj = x @ W_in^T   [16384, 2576]
    {
        dim3 grid(PROJPAD / 128, TOKENS / 256);
        gemm_tc<<<grid, 256, GEMM_SMEM_BYTES>>>(xhi, xlo, winhi, winlo,
                                                proj_ptr, DMODEL, PROJ, PROJ);
    }
    // 4) intra-chunk (+dt)  <- profiled slot
    intra_kernel<<<BATCH * NCHUNK * NHEADS, 256>>>(dt_W, dt_b, A_log);
    // 5) chunk scan
    scan_kernel<<<BATCH * NHEADS, 256>>>();
    // 6) cross-chunk + skip
    cross_kernel<<<BATCH * NCHUNK * NHEADS, 256>>>(D_par);
    // 7) RMS norm + gate -> bf16 hi/lo
    norm_kernel<<<TOKENS, 256>>>(norm_w);
    // 8) split W_out
    {
        int n4 = DMODEL * DINNER / 4;
        split_kernel<<<(n4 + 255) / 256, 256>>>(W_out, wouthi, woutlo, n4);
    }
    // 9) out = yg @ W_out^T  [16384, 1024]
    {
        dim3 grid(DMODEL / 128, TOKENS / 256);
        gemm_tc<<<grid, 256, GEMM_SMEM_BYTES>>>(yghi, yglo, wouthi, woutlo,
                                                out, DINNER, DMODEL, DMODEL);
    }
}

// round 7
// speedup vs baseline: 4.4729x; 1.0613x over previous
#include <cuda_runtime.h>
#include <cuda_bf16.h>
#include <cstdint>

// ---------------------------------------------------------------------------
// Problem constants
// ---------------------------------------------------------------------------
#define BATCH   4
#define SEQ     4096
#define TOKENS  (BATCH * SEQ)        // 16384
#define DMODEL  1024
#define DINNER  1024
#define NHEADS  16
#define HDIM    64
#define DSTATE  16
#define DTRANK  16
#define CHUNK   64
#define NCHUNK  (SEQ / CHUNK)        // 64
#define PROJ    2576
#define PROJPAD 2688                 // 21 * 128

#define OFF_XP   0
#define OFF_Z    1024
#define OFF_B    2048
#define OFF_C    2304
#define OFF_DT   2560

// Packed-operand block offsets (bytes). A-pack: 256-row tiles; B-pack: 128-row.
// Both GEMMs have K=1024 -> exactly 16 chunks of 64 columns.
#define APK_BLK(mt, ch) ((((size_t)(mt) * 16) + (size_t)(ch)) * 32768)
#define BPK_BLK(nt, ch) ((((size_t)(nt) * 16) + (size_t)(ch)) * 16384)
#define SW128(o) ((o) ^ (((o) >> 3) & 0x70))

// tcgen05 is an arch-SPECIFIC feature: only emit it in the sm_103a/f passes.
#if defined(__CUDA_ARCH_FEAT_SM103_ALL) || \
    (defined(__CUDA_ARCH_FAMILY_SPECIFIC__) && __CUDA_ARCH_FAMILY_SPECIFIC__ >= 1000) || \
    (defined(__CUDA_ARCH_SPECIFIC__) && __CUDA_ARCH_SPECIFIC__ >= 1000)
#define HAS_TCGEN05 1
#else
#define HAS_TCGEN05 0
#endif

// ---------------------------------------------------------------------------
// PTX helpers (guarded)
// ---------------------------------------------------------------------------
#if HAS_TCGEN05
__device__ __forceinline__ uint32_t smem_to_u32(const void* p) {
    uint32_t a;
    asm("{ .reg .u64 t; cvta.to.shared.u64 t, %1; cvt.u32.u64 %0, t; }" : "=r"(a) : "l"(p));
    return a;
}
__device__ __forceinline__ uint32_t elect_one_pred() {
    uint32_t pred;
    asm volatile("{\n\t.reg .pred p;\n\telect.sync _|p, 0xFFFFFFFF;\n\tselp.b32 %0, 1, 0, p;\n\t}" : "=r"(pred));
    return pred;
}
#define TCGEN05_ALLOC(smem_result_addr, nCols) \
    asm volatile("tcgen05.alloc.cta_group::1.sync.aligned.shared::cta.b32 [%0], %1;" \
        :: "r"((uint32_t)(smem_result_addr)), "r"((uint32_t)(nCols)) : "memory")
#define TCGEN05_DEALLOC(tmem_addr, nCols) \
    asm volatile("tcgen05.dealloc.cta_group::1.sync.aligned.b32 %0, %1;" :: "r"(tmem_addr), "r"((uint32_t)(nCols)))
#define TCGEN05_RELINQUISH() \
    asm volatile("tcgen05.relinquish_alloc_permit.cta_group::1.sync.aligned;")
#define TCGEN05_COMMIT(mbar) \
    asm volatile("tcgen05.commit.cta_group::1.mbarrier::arrive::one.shared::cluster.b64 [%0];" \
        :: "r"((uint32_t)(mbar)) : "memory")
#define TCGEN05_FENCE_AFTER()  asm volatile("tcgen05.fence::after_thread_sync;" ::: "memory")
#define TCGEN05_FENCE_BEFORE() asm volatile("tcgen05.fence::before_thread_sync;" ::: "memory")
#define TCGEN05_WAIT_LD()      asm volatile("tcgen05.wait::ld.sync.aligned;" ::: "memory")
#define MBARRIER_INIT(mbar, count) \
    asm volatile("mbarrier.init.shared.b64 [%0], %1;" :: "r"((uint32_t)(mbar)), "r"((uint32_t)(count)) : "memory")
#define FENCE_PROXY_ASYNC() asm volatile("fence.proxy.async.shared::cta;" ::: "memory")
#define STS128(a, r0, r1, r2, r3) \
    asm volatile("st.shared.v4.b32 [%0], {%1, %2, %3, %4};" :: "r"(a), "r"(r0), "r"(r1), "r"(r2), "r"(r3) : "memory")
#define MBARRIER_WAIT_PARITY(mbar, parity) do { \
    uint32_t _m = (uint32_t)(mbar); uint32_t _p = (uint32_t)(parity); uint32_t _d; \
    asm volatile("{\n\t.reg .pred p;\n\t" \
        "mbarrier.try_wait.parity.acquire.cta.shared::cta.b64 p, [%1], %2;\n\t" \
        "selp.b32 %0, 1, 0, p;\n\t}" : "=r"(_d) : "r"(_m), "r"(_p) : "memory"); \
    if (!_d) { \
        asm volatile("{\n\t.reg .pred P1;\n\t" \
            "WL_%=:\n\t" \
            "mbarrier.try_wait.parity.acquire.cta.shared::cta.b64 P1, [%0], %1, 0x989680;\n\t" \
            "@P1 bra.uni WD_%=;\n\t" \
            "bra.uni WL_%=;\n\t" \
            "WD_%=:\n\t}" :: "r"(_m), "r"(_p) : "memory"); \
    } } while (0)
#define TCGEN05_LD_32X32B_X32(r, tmem_addr) \
    asm volatile("tcgen05.ld.sync.aligned.32x32b.x32.b32 " \
        "{%0, %1, %2, %3, %4, %5, %6, %7, %8, %9, %10, %11, %12, %13, %14, %15, " \
        " %16, %17, %18, %19, %20, %21, %22, %23, %24, %25, %26, %27, %28, %29, %30, %31}, [%32];" \
        : "=r"((r)[0]),  "=r"((r)[1]),  "=r"((r)[2]),  "=r"((r)[3]), \
          "=r"((r)[4]),  "=r"((r)[5]),  "=r"((r)[6]),  "=r"((r)[7]), \
          "=r"((r)[8]),  "=r"((r)[9]),  "=r"((r)[10]), "=r"((r)[11]), \
          "=r"((r)[12]), "=r"((r)[13]), "=r"((r)[14]), "=r"((r)[15]), \
          "=r"((r)[16]), "=r"((r)[17]), "=r"((r)[18]), "=r"((r)[19]), \
          "=r"((r)[20]), "=r"((r)[21]), "=r"((r)[22]), "=r"((r)[23]), \
          "=r"((r)[24]), "=r"((r)[25]), "=r"((r)[26]), "=r"((r)[27]), \
          "=r"((r)[28]), "=r"((r)[29]), "=r"((r)[30]), "=r"((r)[31]) \
        : "r"(tmem_addr))

static constexpr uint64_t SMEM_DESC_BASE_SW128 =
    (uint64_t(2) << 61) | (uint64_t(1) << 46) | (uint64_t(64) << 32) | (uint64_t(1) << 16);
#define MAKE_SMEM_DESC(base_addr) (SMEM_DESC_BASE_SW128 | ((uint64_t)((base_addr) >> 4) & 0x3FFF))

// idesc: dtype=F32(bit4), atype=BF16(bit7), btype=BF16(bit10), N/8 @17, M/16 @24
#define MMA_IDESC_128x128 ((1u << 4) | (1u << 7) | (1u << 10) | (16u << 17) | (8u << 24))

__device__ __forceinline__ void mma_f16_ss(uint32_t d_tmem, uint64_t a_desc, uint64_t b_desc,
                                           uint32_t idesc, uint32_t enable)
{
    asm volatile(
        "{\n\t.reg .pred p;\n\t"
        "setp.ne.u32 p, %4, 0;\n\t"
        "tcgen05.mma.cta_group::1.kind::f16 [%0], %1, %2, %3, {%5, %5, %5, %5}, p;\n\t"
        "}"
        :: "r"(d_tmem), "l"(a_desc), "l"(b_desc), "r"(idesc), "r"(enable), "r"(0u)
        : "memory");
}
#endif  // HAS_TCGEN05

// ---------------------------------------------------------------------------
// Scratch (device globals; no allocation allowed)
// ---------------------------------------------------------------------------
__device__ float g_proj[(size_t)TOKENS * PROJ];
__device__ float g_dacs[(size_t)TOKENS * NHEADS];
__device__ float g_y[(size_t)TOKENS * DINNER];
__device__ float g_cs[(size_t)BATCH * NCHUNK * NHEADS * DSTATE * HDIM];
__device__ float g_hs[(size_t)BATCH * NCHUNK * NHEADS * DSTATE * HDIM];
__device__ float g_cdecay[(size_t)BATCH * NCHUNK * NHEADS];

__device__ __align__(1024) uint8_t g_xhi[(size_t)TOKENS * DMODEL * 2];
__device__ __align__(1024) uint8_t g_xlo[(size_t)TOKENS * DMODEL * 2];
__device__ __align__(1024) uint8_t g_winhi[(size_t)PROJPAD * DMODEL * 2];
__device__ __align__(1024) uint8_t g_winlo[(size_t)PROJPAD * DMODEL * 2];
__device__ __align__(1024) uint8_t g_wouthi[(size_t)DMODEL * DINNER * 2];
__device__ __align__(1024) uint8_t g_woutlo[(size_t)DMODEL * DINNER * 2];
__device__ __align__(1024) uint8_t g_yghi[(size_t)TOKENS * DINNER * 2];
__device__ __align__(1024) uint8_t g_yglo[(size_t)TOKENS * DINNER * 2];

// ---------------------------------------------------------------------------
// hi/lo split helper
// ---------------------------------------------------------------------------
__device__ __forceinline__ void split4(float4 v, uint2& h, uint2& l)
{
    __nv_bfloat16 hx = __float2bfloat16(v.x), hy = __float2bfloat16(v.y);
    __nv_bfloat16 hz = __float2bfloat16(v.z), hw = __float2bfloat16(v.w);
    __nv_bfloat162 h01 = {hx, hy}, h23 = {hz, hw};
    __nv_bfloat162 l01 = {__float2bfloat16(v.x - __bfloat162float(hx)),
                          __float2bfloat16(v.y - __bfloat162float(hy))};
    __nv_bfloat162 l23 = {__float2bfloat16(v.z - __bfloat162float(hz)),
                          __float2bfloat16(v.w - __bfloat162float(hw))};
    h.x = *reinterpret_cast<uint32_t*>(&h01);
    h.y = *reinterpret_cast<uint32_t*>(&h23);
    l.x = *reinterpret_cast<uint32_t*>(&l01);
    l.y = *reinterpret_cast<uint32_t*>(&l23);
}

// Pack activations (256-row A tiles): src [rows][1024] fp32 -> swizzled blocks
__global__ void __launch_bounds__(256)
split_pack_A(const float* __restrict__ src, uint8_t* __restrict__ hi,
             uint8_t* __restrict__ lo, int n4)
{
    int i = blockIdx.x * 256 + threadIdx.x;
    if (i >= n4) return;
    int t  = i >> 8;
    int k0 = (i & 255) * 4;
    float4 v = reinterpret_cast<const float4*>(src)[i];
    uint2 h, l;
    split4(v, h, l);
    size_t  blk = APK_BLK(t >> 8, k0 >> 6);
    uint32_t off = (uint32_t)((t & 255) * 128 + (k0 & 63) * 2);
    off = SW128(off);
    *reinterpret_cast<uint2*>(hi + blk + off) = h;
    *reinterpret_cast<uint2*>(lo + blk + off) = l;
}

// Pack weights (128-row B tiles) with zero row padding
__global__ void __launch_bounds__(256)
split_pack_B(const float* __restrict__ src, uint8_t* __restrict__ hi,
             uint8_t* __restrict__ lo, int rows_src, int n4)
{
    int i = blockIdx.x * 256 + threadIdx.x;
    if (i >= n4) return;
    int r  = i >> 8;
    int k0 = (i & 255) * 4;
    float4 v = make_float4(0.f, 0.f, 0.f, 0.f);
    if (r < rows_src) v = reinterpret_cast<const float4*>(src)[i];
    uint2 h, l;
    split4(v, h, l);
    size_t  blk = BPK_BLK(r >> 7, k0 >> 6);
    uint32_t off = (uint32_t)((r & 127) * 128 + (k0 & 63) * 2);
    off = SW128(off);
    *reinterpret_cast<uint2*>(hi + blk + off) = h;
    *reinterpret_cast<uint2*>(lo + blk + off) = l;
}

// ---------------------------------------------------------------------------
// tcgen05 bf16-split GEMM, packed operands, LINEAR LDG->STS staging (proven
// round-5 sync structure), 256x128 tile, K-chunks of 64, double-buffered.
// Stage layout: Ahi @0 (32K), Alo @32768, Bhi @65536 (16K), Blo @81920.
// ---------------------------------------------------------------------------
#define STAGE_BYTES 98304
#define GEMM_SMEM_BYTES (2048 + 2 * STAGE_BYTES)

__global__ void __launch_bounds__(256, 1)
gemm_tc(const uint8_t* __restrict__ Ahi, const uint8_t* __restrict__ Alo,
        const uint8_t* __restrict__ Bhi, const uint8_t* __restrict__ Blo,
        float* __restrict__ C, int NC, int Nstride, int Nout)
{
#if HAS_TCGEN05
    extern __shared__ char smem[];
    const uint32_t sbase = smem_to_u32(smem);
    const int tid = threadIdx.x;
    const int wid = tid >> 5;
    const int lid = tid & 31;
    const int bm = blockIdx.y * 256;
    const int bn = blockIdx.x * 128;

    const uint32_t TMEMP = sbase;
    const uint32_t DONE0 = sbase + 8;
    const uint32_t DONE1 = sbase + 16;
    const uint32_t BUF   = (sbase + 32 + 1023) & ~1023u;

    if (wid == 0) {
        TCGEN05_ALLOC(TMEMP, 256);
        TCGEN05_RELINQUISH();
    }
    if (tid == 0) { MBARRIER_INIT(DONE0, 1); MBARRIER_INIT(DONE1, 1); }
    __syncthreads();
    uint32_t tmem;
    asm volatile("ld.shared.b32 %0, [%1];" : "=r"(tmem) : "r"(TMEMP));

    for (int c = 0; c < NC; ++c) {
        const int st = c & 1;
        const uint32_t stage = BUF + (uint32_t)st * (uint32_t)STAGE_BYTES;
        const uint32_t done  = st ? DONE1 : DONE0;
        if (c >= 2) MBARRIER_WAIT_PARITY(done, ((c >> 1) - 1) & 1);

        // linear coalesced copies from packed gmem (image already swizzled)
        const uint4* sAh = reinterpret_cast<const uint4*>(Ahi + APK_BLK(blockIdx.y, c));
        const uint4* sAl = reinterpret_cast<const uint4*>(Alo + APK_BLK(blockIdx.y, c));
        const uint4* sBh = reinterpret_cast<const uint4*>(Bhi + BPK_BLK(blockIdx.x, c));
        const uint4* sBl = reinterpret_cast<const uint4*>(Blo + BPK_BLK(blockIdx.x, c));
#pragma unroll
        for (int it = 0; it < 8; ++it) {
            int u = it * 256 + tid;            // 0..2047 uint4s of A
            uint4 vh = sAh[u];
            uint4 vl = sAl[u];
            STS128(stage + (uint32_t)u * 16u,           vh.x, vh.y, vh.z, vh.w);
            STS128(stage + 32768u + (uint32_t)u * 16u,  vl.x, vl.y, vl.z, vl.w);
        }
#pragma unroll
        for (int it = 0; it < 4; ++it) {
            int u = it * 256 + tid;            // 0..1023 uint4s of B
            uint4 vh = sBh[u];
            uint4 vl = sBl[u];
            STS128(stage + 65536u + (uint32_t)u * 16u, vh.x, vh.y, vh.z, vh.w);
            STS128(stage + 81920u + (uint32_t)u * 16u, vl.x, vl.y, vl.z, vl.w);
        }
        __syncthreads();

        if (wid == 0) {
            FENCE_PROXY_ASYNC();
            if (elect_one_pred()) {
                uint64_t dA0h = MAKE_SMEM_DESC(stage);
                uint64_t dA1h = MAKE_SMEM_DESC(stage + 16384);
                uint64_t dA0l = MAKE_SMEM_DESC(stage + 32768);
                uint64_t dA1l = MAKE_SMEM_DESC(stage + 49152);
                uint64_t dBh  = MAKE_SMEM_DESC(stage + 65536);
                uint64_t dBl  = MAKE_SMEM_DESC(stage + 81920);
#pragma unroll
                for (int ks = 0; ks < 4; ++ks) {
                    uint32_t en0 = (c == 0 && ks == 0) ? 0u : 1u;
                    mma_f16_ss(tmem,       dA0h + ks * 2, dBh + ks * 2, MMA_IDESC_128x128, en0);
                    mma_f16_ss(tmem,       dA0h + ks * 2, dBl + ks * 2, MMA_IDESC_128x128, 1u);
                    mma_f16_ss(tmem,       dA0l + ks * 2, dBh + ks * 2, MMA_IDESC_128x128, 1u);
                    mma_f16_ss(tmem + 128, dA1h + ks * 2, dBh + ks * 2, MMA_IDESC_128x128, en0);
                    mma_f16_ss(tmem + 128, dA1h + ks * 2, dBl + ks * 2, MMA_IDESC_128x128, 1u);
                    mma_f16_ss(tmem + 128, dA1l + ks * 2, dBh + ks * 2, MMA_IDESC_128x128, 1u);
                }
                TCGEN05_COMMIT(done);
            }
        }
    }

    MBARRIER_WAIT_PARITY(DONE0, ((NC - 2) >> 1) & 1);
    MBARRIER_WAIT_PARITY(DONE1, ((NC - 1) >> 1) & 1);
    TCGEN05_FENCE_AFTER();

    {
        int mt  = wid >> 2;                       // 0 or 1
        int row = bm + mt * 128 + (wid & 3) * 32 + lid;
        float* crow = C + (size_t)row * Nstride + bn;
        uint32_t tcol = tmem + (uint32_t)(mt * 128);
#pragma unroll
        for (int g = 0; g < 4; ++g) {
            uint32_t r[32];
            TCGEN05_LD_32X32B_X32(r, tcol + g * 32);
            TCGEN05_WAIT_LD();
            int n0 = bn + g * 32;
            if (n0 + 32 <= Nout) {
#pragma unroll
                for (int j = 0; j < 32; j += 4) {
                    float4 v = make_float4(__uint_as_float(r[j]), __uint_as_float(r[j + 1]),
                                           __uint_as_float(r[j + 2]), __uint_as_float(r[j + 3]));
                    *reinterpret_cast<float4*>(crow + g * 32 + j) = v;
                }
            } else {
                for (int j = 0; j < 32; ++j)
                    if (n0 + j < Nout) crow[g * 32 + j] = __uint_as_float(r[j]);
            }
        }
        TCGEN05_FENCE_BEFORE();
    }
    __syncthreads();
    if (wid == 0) TCGEN05_DEALLOC(tmem, 256);

#else   // ---------------- SIMT fallback (generic PTX pass only; never runs) --
    const int tid = threadIdx.x;
    const int bm  = blockIdx.y * 256;
    const int bn  = blockIdx.x * 128;
    const int K   = NC * 64;
    for (int e = tid; e < 256 * 128; e += 256) {
        int i = e >> 7, j = e & 127;
        int m = bm + i, n = bn + j;
        if (n >= Nout) continue;
        float acc = 0.f;
        for (int k = 0; k < K; ++k) {
            size_t ablk = APK_BLK(m >> 8, k >> 6);
            uint32_t aoff = SW128((uint32_t)((m & 255) * 128 + (k & 63) * 2));
            size_t bblk = BPK_BLK(n >> 7, k >> 6);
            uint32_t boff = SW128((uint32_t)((n & 127) * 128 + (k & 63) * 2));
            float a = __bfloat162float(*(const __nv_bfloat16*)(Ahi + ablk + aoff)) +
                      __bfloat162float(*(const __nv_bfloat16*)(Alo + ablk + aoff));
            float b = __bfloat162float(*(const __nv_bfloat16*)(Bhi + bblk + boff)) +
                      __bfloat162float(*(const __nv_bfloat16*)(Blo + bblk + boff));
            acc = fmaf(a, b, acc);
        }
        C[(size_t)m * Nstride + n] = acc;
    }
#endif
}

// ---------------------------------------------------------------------------
// Intra-chunk (dt folded in): dt -> dacs -> scores(T) -> y_intra, chunk_state
// ---------------------------------------------------------------------------
__global__ void __launch_bounds__(256, 3)
intra_kernel(const float* __restrict__ dt_W, const float* __restrict__ dt_b,
             const float* __restrict__ A_log)
{
    const int bid = blockIdx.x;        // (b*NCHUNK + c)*NHEADS + h
    const int h   = bid & 15;
    const int bc  = bid >> 4;
    const int t0  = bc * CHUNK;
    const int tid = threadIdx.x;
    const int wid = tid >> 5;
    const int lid = tid & 31;

    __shared__ float xs[64][68];
    __shared__ float scT[64][68];      // scT[k][i] = scores[i][k]
    __shared__ float Bsh[64][20];
    __shared__ float Csh[64][20];      // reused as bw after scores
    __shared__ float dts[64];
    __shared__ float dacs[64];
    __shared__ float wk[64];

    for (int idx = tid; idx < 64 * 16; idx += 256) {
        int k = idx >> 4, p4 = idx & 15;
        float4 v = *reinterpret_cast<const float4*>(
            g_proj + (size_t)(t0 + k) * PROJ + OFF_XP + h * HDIM + p4 * 4);
        *reinterpret_cast<float4*>(&xs[k][p4 * 4]) = v;
    }
    {
        int k = tid >> 2, n4 = tid & 3;
        float4 vb = *reinterpret_cast<const float4*>(
            g_proj + (size_t)(t0 + k) * PROJ + OFF_B + h * DSTATE + n4 * 4);
        float4 vc = *reinterpret_cast<const float4*>(
            g_proj + (size_t)(t0 + k) * PROJ + OFF_C + h * DSTATE + n4 * 4);
        *reinterpret_cast<float4*>(&Bsh[k][n4 * 4]) = vb;
        *reinterpret_cast<float4*>(&Csh[k][n4 * 4]) = vc;
    }
    if (tid < 64) {
        const float* row = g_proj + (size_t)(t0 + tid) * PROJ + OFF_DT;
        float acc = dt_b[h];
#pragma unroll
        for (int r = 0; r < DTRANK; ++r)
            acc = fmaf(row[r], dt_W[h * DTRANK + r], acc);
        dts[tid] = (acc > 20.f) ? acc : log1pf(expf(acc));
    }
    __syncthreads();

    if (wid == 0) {
        float A  = -expf(A_log[h]);
        float v1 = dts[2 * lid + 1] * A;
        float s  = dts[2 * lid] * A + v1;
#pragma unroll
        for (int off = 1; off < 32; off <<= 1) {
            float t = __shfl_up_sync(0xffffffffu, s, off);
            if (lid >= off) s += t;
        }
        dacs[2 * lid + 1] = s;
        dacs[2 * lid]     = s - v1;
    }
    __syncthreads();

    if (tid < 64) {
        wk[tid] = dts[tid] * expf(dacs[63] - dacs[tid]);
        g_dacs[(size_t)(t0 + tid) * NHEADS + h] = dacs[tid];
    }
    if (tid == 0) g_cdecay[bid] = expf(dacs[63]);
    __syncthreads();

    // scores: thread owns row i = tid&63, columns j0..j0+15; writes transposed
    {
        int i  = tid & 63;
        int j0 = (tid >> 6) * 16;
        float ci[16];
#pragma unroll
        for (int n = 0; n < 16; ++n) ci[n] = Csh[i][n];
        float di = dacs[i];
#pragma unroll
        for (int jj = 0; jj < 16; ++jj) {
            int j = j0 + jj;
            float v = 0.f;
            if (j <= i) {
                float d = 0.f;
#pragma unroll
                for (int n = 0; n < 16; ++n)
                    d = fmaf(ci[n], Bsh[j][n], d);
                v = d * expf(di - dacs[j]) * dts[j];
            }
            scT[j][i] = v;
        }
    }
    __syncthreads();

    // bw[k][n] = B[k][n] * wk[k]  (overwrite Csh, dead after scores)
    for (int idx = tid; idx < 64 * 16; idx += 256) {
        int k = idx >> 4, n = idx & 15;
        Csh[k][n] = Bsh[k][n] * wk[k];
    }
    __syncthreads();

    // y_intra: 4x4 register blocking, causal-truncated k loop, float4 LDS both
    {
        int a  = tid >> 4;
        int b  = tid & 15;
        int i0 = a * 4, p0 = b * 4;
        float acc[4][4];
#pragma unroll
        for (int q = 0; q < 4; ++q)
#pragma unroll
            for (int r = 0; r < 4; ++r) acc[q][r] = 0.f;
        const int kmax = i0 + 4;          // scT[k][i] = 0 for k > i
        for (int kk = 0; kk < kmax; ++kk) {
            float4 s4 = *reinterpret_cast<const float4*>(&scT[kk][i0]);
            float4 xr = *reinterpret_cast<const float4*>(&xs[kk][p0]);
            acc[0][0] = fmaf(s4.x, xr.x, acc[0][0]);
            acc[0][1] = fmaf(s4.x, xr.y, acc[0][1]);
            acc[0][2] = fmaf(s4.x, xr.z, acc[0][2]);
            acc[0][3] = fmaf(s4.x, xr.w, acc[0][3]);
            acc[1][0] = fmaf(s4.y, xr.x, acc[1][0]);
            acc[1][1] = fmaf(s4.y, xr.y, acc[1][1]);
            acc[1][2] = fmaf(s4.y, xr.z, acc[1][2]);
            acc[1][3] = fmaf(s4.y, xr.w, acc[1][3]);
            acc[2][0] = fmaf(s4.z, xr.x, acc[2][0]);
            acc[2][1] = fmaf(s4.z, xr.y, acc[2][1]);
            acc[2][2] = fmaf(s4.z, xr.z, acc[2][2]);
            acc[2][3] = fmaf(s4.z, xr.w, acc[2][3]);
            acc[3][0] = fmaf(s4.w, xr.x, acc[3][0]);
            acc[3][1] = fmaf(s4.w, xr.y, acc[3][1]);
            acc[3][2] = fmaf(s4.w, xr.z, acc[3][2]);
            acc[3][3] = fmaf(s4.w, xr.w, acc[3][3]);
        }
#pragma unroll
        for (int q = 0; q < 4; ++q) {
            float4 v = make_float4(acc[q][0], acc[q][1], acc[q][2], acc[q][3]);
            *reinterpret_cast<float4*>(
                g_y + (size_t)(t0 + i0 + q) * DINNER + h * HDIM + p0) = v;
        }
    }

    // chunk_state[n][p] = sum_k bw[k][n] * x[k][p]
    {
        int n  = tid >> 4;
        int p0 = (tid & 15) * 4;
        float4 acc = make_float4(0.f, 0.f, 0.f, 0.f);
        for (int k = 0; k < 64; ++k) {
            float bwv = Csh[k][n];
            float4 xr = *reinterpret_cast<const float4*>(&xs[k][p0]);
            acc.x = fmaf(bwv, xr.x, acc.x);
            acc.y = fmaf(bwv, xr.y, acc.y);
            acc.z = fmaf(bwv, xr.z, acc.z);
            acc.w = fmaf(bwv, xr.w, acc.w);
        }
        *reinterpret_cast<float4*>(
            g_cs + (size_t)bid * (DSTATE * HDIM) + n * HDIM + p0) = acc;
    }
}

// ---------------------------------------------------------------------------
// Sequential scan over chunks: grid = BATCH*NHEADS*4, 1 elem/thread
// ---------------------------------------------------------------------------
__global__ void __launch_bounds__(256)
scan_kernel()
{
    const int g   = blockIdx.x;
    const int bh  = g >> 2;
    const int seg = g & 3;
    const int b   = bh >> 4;
    const int h   = bh & 15;
    const int e   = seg * 256 + threadIdx.x;

    const int    chid0  = (b * NCHUNK) * NHEADS + h;
    const size_t base   = (size_t)chid0 * (DSTATE * HDIM);
    const size_t stride = (size_t)NHEADS * DSTATE * HDIM;

    float hv  = 0.f;
    float cur = g_cs[base + e];
    float d   = g_cdecay[chid0];
    for (int c = 0; c < NCHUNK; ++c) {
        float nxt = 0.f, dn = 0.f;
        if (c + 1 < NCHUNK) {
            nxt = g_cs[base + stride * (c + 1) + e];
            dn  = g_cdecay[chid0 + (c + 1) * NHEADS];
        }
        g_hs[base + stride * c + e] = hv;
        hv = fmaf(d, hv, cur);
        cur = nxt; d = dn;
    }
}

// ---------------------------------------------------------------------------
// Cross-chunk + skip
// ---------------------------------------------------------------------------
__global__ void __launch_bounds__(256, 2)
cross_kernel(const float* __restrict__ D_param)
{
    const int bid = blockIdx.x;
    const int h   = bid & 15;
    const int bc  = bid >> 4;
    const int t0  = bc * CHUNK;
    const int tid = threadIdx.x;

    __shared__ float hs[16][68];
    __shared__ float Csh[64][20];
    __shared__ float dacs[64];

    {
        int n = tid >> 4, pg = tid & 15;
        float4 v = *reinterpret_cast<const float4*>(
            g_hs + (size_t)bid * (DSTATE * HDIM) + n * HDIM + pg * 4);
        *reinterpret_cast<float4*>(&hs[n][pg * 4]) = v;
    }
    {
        int k = tid >> 2, n4 = tid & 3;
        float4 vc = *reinterpret_cast<const float4*>(
            g_proj + (size_t)(t0 + k) * PROJ + OFF_C + h * DSTATE + n4 * 4);
        *reinterpret_cast<float4*>(&Csh[k][n4 * 4]) = vc;
    }
    if (tid < 64) dacs[tid] = g_dacs[(size_t)(t0 + tid) * NHEADS + h];
    __syncthreads();

    int i  = tid >> 2;
    int p0 = (tid & 3) * 16;
    float ci[16];
#pragma unroll
    for (int n = 0; n < 16; ++n) ci[n] = Csh[i][n];
    float e  = expf(dacs[i]);
    float dp = D_param[h];

    size_t t = (size_t)(t0 + i);
    const float* xrow = g_proj + t * PROJ + OFF_XP + h * HDIM;
    float* yrow = g_y + t * DINNER + h * HDIM;
#pragma unroll
    for (int g4 = 0; g4 < 4; ++g4) {
        int p = p0 + g4 * 4;
        float4 yv = *reinterpret_cast<const float4*>(yrow + p);
        float4 xv = *reinterpret_cast<const float4*>(xrow + p);
        float a0 = 0.f, a1 = 0.f, a2 = 0.f, a3 = 0.f;
#pragma unroll
        for (int n = 0; n < 16; ++n) {
            float c = ci[n];
            a0 = fmaf(c, hs[n][p + 0], a0);
            a1 = fmaf(c, hs[n][p + 1], a1);
            a2 = fmaf(c, hs[n][p + 2], a2);
            a3 = fmaf(c, hs[n][p + 3], a3);
        }
        float4 o;
        o.x = yv.x + e * a0 + dp * xv.x;
        o.y = yv.y + e * a1 + dp * xv.y;
        o.z = yv.z + e * a2 + dp * xv.z;
        o.w = yv.w + e * a3 + dp * xv.w;
        *reinterpret_cast<float4*>(yrow + p) = o;
    }
}

// ---------------------------------------------------------------------------
// RMS norm + SiLU gate -> yg packed (bf16 hi/lo, swizzled A-tile layout)
// ---------------------------------------------------------------------------
__global__ void __launch_bounds__(256)
norm_kernel(const float* __restrict__ norm_w)
{
    const int t   = blockIdx.x;
    const int tid = threadIdx.x;

    float4 v = reinterpret_cast<const float4*>(g_y + (size_t)t * DINNER)[tid];
    float ss = v.x * v.x + v.y * v.y + v.z * v.z + v.w * v.w;
#pragma unroll
    for (int off = 16; off > 0; off >>= 1)
        ss += __shfl_xor_sync(0xffffffffu, ss, off);

    __shared__ float red[8];
    __shared__ float s_inv;
    if ((tid & 31) == 0) red[tid >> 5] = ss;
    __syncthreads();
    if (tid == 0) {
        float s = 0.f;
#pragma unroll
        for (int i = 0; i < 8; ++i) s += red[i];
        s_inv = rsqrtf(s * (1.f / DINNER) + 1e-6f);
    }
    __syncthreads();
    float inv = s_inv;

    const float* zrow = g_proj + (size_t)t * PROJ + OFF_Z;
    int c = tid * 4;
    float4 z4 = *reinterpret_cast<const float4*>(zrow + c);
    float4 w4 = *reinterpret_cast<const float4*>(norm_w + c);
    float4 o;
    o.x = v.x * inv * w4.x * (z4.x / (1.f + expf(-z4.x)));
    o.y = v.y * inv * w4.y * (z4.y / (1.f + expf(-z4.y)));
    o.z = v.z * inv * w4.z * (z4.z / (1.f + expf(-z4.z)));
    o.w = v.w * inv * w4.w * (z4.w / (1.f + expf(-z4.w)));

    uint2 h, l;
    split4(o, h, l);
    size_t  blk = APK_BLK(t >> 8, c >> 6);
    uint32_t off = (uint32_t)((t & 255) * 128 + (c & 63) * 2);
    off = SW128(off);
    *reinterpret_cast<uint2*>(g_yghi + blk + off) = h;
    *reinterpret_cast<uint2*>(g_yglo + blk + off) = l;
}

// ---------------------------------------------------------------------------
// Launch — proj GEMM at slot #4 (profiled)
// ---------------------------------------------------------------------------
extern "C" void kernel_launch(void* const* d_in, const int* in_sizes, int n_in,
                              void* d_out, int out_size)
{
    const float* x      = (const float*)d_in[0];
    const float* W_in   = (const float*)d_in[1];
    const float* dt_W   = (const float*)d_in[2];
    const float* dt_b   = (const float*)d_in[3];
    const float* A_log  = (const float*)d_in[4];
    const float* D_par  = (const float*)d_in[5];
    const float* W_out  = (const float*)d_in[6];
    const float* norm_w = (const float*)d_in[7];
    float* out = (float*)d_out;

    float* proj_ptr = nullptr;
    uint8_t *xhi, *xlo, *winhi, *winlo, *wouthi, *woutlo, *yghi, *yglo;
    cudaGetSymbolAddress((void**)&proj_ptr, g_proj);
    cudaGetSymbolAddress((void**)&xhi, g_xhi);
    cudaGetSymbolAddress((void**)&xlo, g_xlo);
    cudaGetSymbolAddress((void**)&winhi, g_winhi);
    cudaGetSymbolAddress((void**)&winlo, g_winlo);
    cudaGetSymbolAddress((void**)&wouthi, g_wouthi);
    cudaGetSymbolAddress((void**)&woutlo, g_woutlo);
    cudaGetSymbolAddress((void**)&yghi, g_yghi);
    cudaGetSymbolAddress((void**)&yglo, g_yglo);

    cudaFuncSetAttribute(gemm_tc, cudaFuncAttributeMaxDynamicSharedMemorySize, GEMM_SMEM_BYTES);

    // 1) pack x
    {
        int n4 = TOKENS * DMODEL / 4;
        split_pack_A<<<(n4 + 255) / 256, 256>>>(x, xhi, xlo, n4);
    }
    // 2) pack W_in (padded to 2688 rows)
    {
        int n4 = PROJPAD * DMODEL / 4;
        split_pack_B<<<(n4 + 255) / 256, 256>>>(W_in, winhi, winlo, PROJ, n4);
    }
    // 3) pack W_out
    {
        int n4 = DMODEL * DINNER / 4;
        split_pack_B<<<(n4 + 255) / 256, 256>>>(W_out, wouthi, woutlo, DMODEL, n4);
    }
    // 4) proj = x @ W_in^T   [16384, 2576]   <- profiled slot
    {
        dim3 grid(PROJPAD / 128, TOKENS / 256);
        gemm_tc<<<grid, 256, GEMM_SMEM_BYTES>>>(xhi, xlo, winhi, winlo,
                                                proj_ptr, DMODEL / 64, PROJ, PROJ);
    }
    // 5) intra-chunk (+dt)
    intra_kernel<<<BATCH * NCHUNK * NHEADS, 256>>>(dt_W, dt_b, A_log);
    // 6) chunk scan
    scan_kernel<<<BATCH * NHEADS * 4, 256>>>();
    // 7) cross-chunk + skip
    cross_kernel<<<BATCH * NCHUNK * NHEADS, 256>>>(D_par);
    // 8) RMS norm + gate -> packed bf16 hi/lo
    norm_kernel<<<TOKENS, 256>>>(norm_w);
    // 9) out = yg @ W_out^T  [16384, 1024]
    {
        dim3 grid(DMODEL / 128, TOKENS / 256);
        gemm_tc<<<grid, 256, GEMM_SMEM_BYTES>>>(yghi, yglo, wouthi, woutlo,
                                                out, DINNER / 64, DMODEL, DMODEL);
    }
}

// round 8
// speedup vs baseline: 4.6772x; 1.0457x over previous
#include <cuda_runtime.h>
#include <cuda_bf16.h>
#include <cstdint>

// ---------------------------------------------------------------------------
// Problem constants
// ---------------------------------------------------------------------------
#define BATCH   4
#define SEQ     4096
#define TOKENS  (BATCH * SEQ)        // 16384
#define DMODEL  1024
#define DINNER  1024
#define NHEADS  16
#define HDIM    64
#define DSTATE  16
#define DTRANK  16
#define CHUNK   64
#define NCHUNK  (SEQ / CHUNK)        // 64
#define PROJ    2576
#define PROJPAD 2688                 // 21 * 128

#define OFF_XP   0
#define OFF_Z    1024
#define OFF_B    2048
#define OFF_C    2304
#define OFF_DT   2560

// Packed-operand block offsets (bytes). A-pack: 256-row tiles; B-pack: 128-row.
// Both GEMMs have K=1024 -> exactly 16 chunks of 64 columns.
#define APK_BLK(mt, ch) ((((size_t)(mt) * 16) + (size_t)(ch)) * 32768)
#define BPK_BLK(nt, ch) ((((size_t)(nt) * 16) + (size_t)(ch)) * 16384)
#define SW128(o) ((o) ^ (((o) >> 3) & 0x70))

// tcgen05 is an arch-SPECIFIC feature: only emit it in the sm_103a/f passes.
#if defined(__CUDA_ARCH_FEAT_SM103_ALL) || \
    (defined(__CUDA_ARCH_FAMILY_SPECIFIC__) && __CUDA_ARCH_FAMILY_SPECIFIC__ >= 1000) || \
    (defined(__CUDA_ARCH_SPECIFIC__) && __CUDA_ARCH_SPECIFIC__ >= 1000)
#define HAS_TCGEN05 1
#else
#define HAS_TCGEN05 0
#endif

// ---------------------------------------------------------------------------
// PTX helpers (guarded)
// ---------------------------------------------------------------------------
#if HAS_TCGEN05
__device__ __forceinline__ uint32_t smem_to_u32(const void* p) {
    uint32_t a;
    asm("{ .reg .u64 t; cvta.to.shared.u64 t, %1; cvt.u32.u64 %0, t; }" : "=r"(a) : "l"(p));
    return a;
}
__device__ __forceinline__ uint32_t elect_one_pred() {
    uint32_t pred;
    asm volatile("{\n\t.reg .pred p;\n\telect.sync _|p, 0xFFFFFFFF;\n\tselp.b32 %0, 1, 0, p;\n\t}" : "=r"(pred));
    return pred;
}
#define TCGEN05_ALLOC(smem_result_addr, nCols) \
    asm volatile("tcgen05.alloc.cta_group::1.sync.aligned.shared::cta.b32 [%0], %1;" \
        :: "r"((uint32_t)(smem_result_addr)), "r"((uint32_t)(nCols)) : "memory")
#define TCGEN05_DEALLOC(tmem_addr, nCols) \
    asm volatile("tcgen05.dealloc.cta_group::1.sync.aligned.b32 %0, %1;" :: "r"(tmem_addr), "r"((uint32_t)(nCols)))
#define TCGEN05_RELINQUISH() \
    asm volatile("tcgen05.relinquish_alloc_permit.cta_group::1.sync.aligned;")
#define TCGEN05_COMMIT(mbar) \
    asm volatile("tcgen05.commit.cta_group::1.mbarrier::arrive::one.shared::cluster.b64 [%0];" \
        :: "r"((uint32_t)(mbar)) : "memory")
#define TCGEN05_FENCE_AFTER()  asm volatile("tcgen05.fence::after_thread_sync;" ::: "memory")
#define TCGEN05_FENCE_BEFORE() asm volatile("tcgen05.fence::before_thread_sync;" ::: "memory")
#define TCGEN05_WAIT_LD()      asm volatile("tcgen05.wait::ld.sync.aligned;" ::: "memory")
#define MBARRIER_INIT(mbar, count) \
    asm volatile("mbarrier.init.shared.b64 [%0], %1;" :: "r"((uint32_t)(mbar)), "r"((uint32_t)(count)) : "memory")
#define FENCE_PROXY_ASYNC() asm volatile("fence.proxy.async.shared::cta;" ::: "memory")
#define CP_ASYNC16(dst, src) \
    asm volatile("cp.async.cg.shared.global [%0], [%1], 16;" \
        :: "r"((uint32_t)(dst)), "l"(src) : "memory")
#define CP_ASYNC_COMMIT() asm volatile("cp.async.commit_group;" ::: "memory")
#define CP_ASYNC_WAIT0()  asm volatile("cp.async.wait_group 0;" ::: "memory")
#define MBARRIER_WAIT_PARITY(mbar, parity) do { \
    uint32_t _m = (uint32_t)(mbar); uint32_t _p = (uint32_t)(parity); uint32_t _d; \
    asm volatile("{\n\t.reg .pred p;\n\t" \
        "mbarrier.try_wait.parity.acquire.cta.shared::cta.b64 p, [%1], %2;\n\t" \
        "selp.b32 %0, 1, 0, p;\n\t}" : "=r"(_d) : "r"(_m), "r"(_p) : "memory"); \
    if (!_d) { \
        asm volatile("{\n\t.reg .pred P1;\n\t" \
            "WL_%=:\n\t" \
            "mbarrier.try_wait.parity.acquire.cta.shared::cta.b64 P1, [%0], %1, 0x989680;\n\t" \
            "@P1 bra.uni WD_%=;\n\t" \
            "bra.uni WL_%=;\n\t" \
            "WD_%=:\n\t}" :: "r"(_m), "r"(_p) : "memory"); \
    } } while (0)
#define TCGEN05_LD_32X32B_X32(r, tmem_addr) \
    asm volatile("tcgen05.ld.sync.aligned.32x32b.x32.b32 " \
        "{%0, %1, %2, %3, %4, %5, %6, %7, %8, %9, %10, %11, %12, %13, %14, %15, " \
        " %16, %17, %18, %19, %20, %21, %22, %23, %24, %25, %26, %27, %28, %29, %30, %31}, [%32];" \
        : "=r"((r)[0]),  "=r"((r)[1]),  "=r"((r)[2]),  "=r"((r)[3]), \
          "=r"((r)[4]),  "=r"((r)[5]),  "=r"((r)[6]),  "=r"((r)[7]), \
          "=r"((r)[8]),  "=r"((r)[9]),  "=r"((r)[10]), "=r"((r)[11]), \
          "=r"((r)[12]), "=r"((r)[13]), "=r"((r)[14]), "=r"((r)[15]), \
          "=r"((r)[16]), "=r"((r)[17]), "=r"((r)[18]), "=r"((r)[19]), \
          "=r"((r)[20]), "=r"((r)[21]), "=r"((r)[22]), "=r"((r)[23]), \
          "=r"((r)[24]), "=r"((r)[25]), "=r"((r)[26]), "=r"((r)[27]), \
          "=r"((r)[28]), "=r"((r)[29]), "=r"((r)[30]), "=r"((r)[31]) \
        : "r"(tmem_addr))

static constexpr uint64_t SMEM_DESC_BASE_SW128 =
    (uint64_t(2) << 61) | (uint64_t(1) << 46) | (uint64_t(64) << 32) | (uint64_t(1) << 16);
#define MAKE_SMEM_DESC(base_addr) (SMEM_DESC_BASE_SW128 | ((uint64_t)((base_addr) >> 4) & 0x3FFF))

// idesc: dtype=F32(bit4), atype=BF16(bit7), btype=BF16(bit10), N/8 @17, M/16 @24
#define MMA_IDESC_128x128 ((1u << 4) | (1u << 7) | (1u << 10) | (16u << 17) | (8u << 24))

__device__ __forceinline__ void mma_f16_ss(uint32_t d_tmem, uint64_t a_desc, uint64_t b_desc,
                                           uint32_t idesc, uint32_t enable)
{
    asm volatile(
        "{\n\t.reg .pred p;\n\t"
        "setp.ne.u32 p, %4, 0;\n\t"
        "tcgen05.mma.cta_group::1.kind::f16 [%0], %1, %2, %3, {%5, %5, %5, %5}, p;\n\t"
        "}"
        :: "r"(d_tmem), "l"(a_desc), "l"(b_desc), "r"(idesc), "r"(enable), "r"(0u)
        : "memory");
}
#endif  // HAS_TCGEN05

// ---------------------------------------------------------------------------
// Scratch (device globals; no allocation allowed)
// ---------------------------------------------------------------------------
__device__ float g_proj[(size_t)TOKENS * PROJ];
__device__ float g_dacs[(size_t)TOKENS * NHEADS];
__device__ float g_y[(size_t)TOKENS * DINNER];
__device__ float g_cs[(size_t)BATCH * NCHUNK * NHEADS * DSTATE * HDIM];
__device__ float g_hs[(size_t)BATCH * NCHUNK * NHEADS * DSTATE * HDIM];
__device__ float g_cdecay[(size_t)BATCH * NCHUNK * NHEADS];

__device__ __align__(1024) uint8_t g_xhi[(size_t)TOKENS * DMODEL * 2];
__device__ __align__(1024) uint8_t g_xlo[(size_t)TOKENS * DMODEL * 2];
__device__ __align__(1024) uint8_t g_winhi[(size_t)PROJPAD * DMODEL * 2];
__device__ __align__(1024) uint8_t g_winlo[(size_t)PROJPAD * DMODEL * 2];
__device__ __align__(1024) uint8_t g_wouthi[(size_t)DMODEL * DINNER * 2];
__device__ __align__(1024) uint8_t g_woutlo[(size_t)DMODEL * DINNER * 2];
__device__ __align__(1024) uint8_t g_yghi[(size_t)TOKENS * DINNER * 2];
__device__ __align__(1024) uint8_t g_yglo[(size_t)TOKENS * DINNER * 2];

// ---------------------------------------------------------------------------
// hi/lo split helper
// ---------------------------------------------------------------------------
__device__ __forceinline__ void split4(float4 v, uint2& h, uint2& l)
{
    __nv_bfloat16 hx = __float2bfloat16(v.x), hy = __float2bfloat16(v.y);
    __nv_bfloat16 hz = __float2bfloat16(v.z), hw = __float2bfloat16(v.w);
    __nv_bfloat162 h01 = {hx, hy}, h23 = {hz, hw};
    __nv_bfloat162 l01 = {__float2bfloat16(v.x - __bfloat162float(hx)),
                          __float2bfloat16(v.y - __bfloat162float(hy))};
    __nv_bfloat162 l23 = {__float2bfloat16(v.z - __bfloat162float(hz)),
                          __float2bfloat16(v.w - __bfloat162float(hw))};
    h.x = *reinterpret_cast<uint32_t*>(&h01);
    h.y = *reinterpret_cast<uint32_t*>(&h23);
    l.x = *reinterpret_cast<uint32_t*>(&l01);
    l.y = *reinterpret_cast<uint32_t*>(&l23);
}

// Pack activations (256-row A tiles): src [rows][1024] fp32 -> swizzled blocks
__global__ void __launch_bounds__(256)
split_pack_A(const float* __restrict__ src, uint8_t* __restrict__ hi,
             uint8_t* __restrict__ lo, int n4)
{
    int i = blockIdx.x * 256 + threadIdx.x;
    if (i >= n4) return;
    int t  = i >> 8;
    int k0 = (i & 255) * 4;
    float4 v = reinterpret_cast<const float4*>(src)[i];
    uint2 h, l;
    split4(v, h, l);
    size_t  blk = APK_BLK(t >> 8, k0 >> 6);
    uint32_t off = (uint32_t)((t & 255) * 128 + (k0 & 63) * 2);
    off = SW128(off);
    *reinterpret_cast<uint2*>(hi + blk + off) = h;
    *reinterpret_cast<uint2*>(lo + blk + off) = l;
}

// Pack weights (128-row B tiles) with zero row padding
__global__ void __launch_bounds__(256)
split_pack_B(const float* __restrict__ src, uint8_t* __restrict__ hi,
             uint8_t* __restrict__ lo, int rows_src, int n4)
{
    int i = blockIdx.x * 256 + threadIdx.x;
    if (i >= n4) return;
    int r  = i >> 8;
    int k0 = (i & 255) * 4;
    float4 v = make_float4(0.f, 0.f, 0.f, 0.f);
    if (r < rows_src) v = reinterpret_cast<const float4*>(src)[i];
    uint2 h, l;
    split4(v, h, l);
    size_t  blk = BPK_BLK(r >> 7, k0 >> 6);
    uint32_t off = (uint32_t)((r & 127) * 128 + (k0 & 63) * 2);
    off = SW128(off);
    *reinterpret_cast<uint2*>(hi + blk + off) = h;
    *reinterpret_cast<uint2*>(lo + blk + off) = l;
}

// ---------------------------------------------------------------------------
// tcgen05 bf16-split GEMM, packed operands, cp.async (LDGSTS) staging.
// 256x128 tile, K-chunks of 64, double-buffered. 256 threads.
// Stage layout: Ahi @0 (32K), Alo @32768, Bhi @65536 (16K), Blo @81920.
// ---------------------------------------------------------------------------
#define STAGE_BYTES 98304
#define GEMM_SMEM_BYTES (2048 + 2 * STAGE_BYTES)

__global__ void __launch_bounds__(256, 1)
gemm_tc(const uint8_t* __restrict__ Ahi, const uint8_t* __restrict__ Alo,
        const uint8_t* __restrict__ Bhi, const uint8_t* __restrict__ Blo,
        float* __restrict__ C, int NC, int Nstride, int Nout)
{
#if HAS_TCGEN05
    extern __shared__ char smem[];
    const uint32_t sbase = smem_to_u32(smem);
    const int tid = threadIdx.x;
    const int wid = tid >> 5;
    const int lid = tid & 31;
    const int bm = blockIdx.y * 256;
    const int bn = blockIdx.x * 128;

    const uint32_t TMEMP = sbase;
    const uint32_t DONE0 = sbase + 8;
    const uint32_t DONE1 = sbase + 16;
    const uint32_t BUF   = (sbase + 32 + 1023) & ~1023u;

    if (wid == 0) {
        TCGEN05_ALLOC(TMEMP, 256);
        TCGEN05_RELINQUISH();
    }
    if (tid == 0) { MBARRIER_INIT(DONE0, 1); MBARRIER_INIT(DONE1, 1); }
    __syncthreads();
    uint32_t tmem;
    asm volatile("ld.shared.b32 %0, [%1];" : "=r"(tmem) : "r"(TMEMP));

    for (int c = 0; c < NC; ++c) {
        const int st = c & 1;
        const uint32_t stage = BUF + (uint32_t)st * (uint32_t)STAGE_BYTES;
        const uint32_t done  = st ? DONE1 : DONE0;
        if (c >= 2) MBARRIER_WAIT_PARITY(done, ((c >> 1) - 1) & 1);

        // async copies from packed gmem (image already swizzled) — no regs,
        // no L1 writeback, fire-and-forget
        const uint8_t* sAh = Ahi + APK_BLK(blockIdx.y, c);
        const uint8_t* sAl = Alo + APK_BLK(blockIdx.y, c);
        const uint8_t* sBh = Bhi + BPK_BLK(blockIdx.x, c);
        const uint8_t* sBl = Blo + BPK_BLK(blockIdx.x, c);
#pragma unroll
        for (int it = 0; it < 8; ++it) {
            uint32_t b = (uint32_t)(it * 256 + tid) * 16u;   // 0..32767
            CP_ASYNC16(stage + b,          sAh + b);
            CP_ASYNC16(stage + 32768u + b, sAl + b);
        }
#pragma unroll
        for (int it = 0; it < 4; ++it) {
            uint32_t b = (uint32_t)(it * 256 + tid) * 16u;   // 0..16383
            CP_ASYNC16(stage + 65536u + b, sBh + b);
            CP_ASYNC16(stage + 81920u + b, sBl + b);
        }
        CP_ASYNC_COMMIT();
        CP_ASYNC_WAIT0();
        __syncthreads();

        if (wid == 0) {
            FENCE_PROXY_ASYNC();
            if (elect_one_pred()) {
                uint64_t dA0h = MAKE_SMEM_DESC(stage);
                uint64_t dA1h = MAKE_SMEM_DESC(stage + 16384);
                uint64_t dA0l = MAKE_SMEM_DESC(stage + 32768);
                uint64_t dA1l = MAKE_SMEM_DESC(stage + 49152);
                uint64_t dBh  = MAKE_SMEM_DESC(stage + 65536);
                uint64_t dBl  = MAKE_SMEM_DESC(stage + 81920);
#pragma unroll
                for (int ks = 0; ks < 4; ++ks) {
                    uint32_t en0 = (c == 0 && ks == 0) ? 0u : 1u;
                    mma_f16_ss(tmem,       dA0h + ks * 2, dBh + ks * 2, MMA_IDESC_128x128, en0);
                    mma_f16_ss(tmem,       dA0h + ks * 2, dBl + ks * 2, MMA_IDESC_128x128, 1u);
                    mma_f16_ss(tmem,       dA0l + ks * 2, dBh + ks * 2, MMA_IDESC_128x128, 1u);
                    mma_f16_ss(tmem + 128, dA1h + ks * 2, dBh + ks * 2, MMA_IDESC_128x128, en0);
                    mma_f16_ss(tmem + 128, dA1h + ks * 2, dBl + ks * 2, MMA_IDESC_128x128, 1u);
                    mma_f16_ss(tmem + 128, dA1l + ks * 2, dBh + ks * 2, MMA_IDESC_128x128, 1u);
                }
                TCGEN05_COMMIT(done);
            }
        }
    }

    MBARRIER_WAIT_PARITY(DONE0, ((NC - 2) >> 1) & 1);
    MBARRIER_WAIT_PARITY(DONE1, ((NC - 1) >> 1) & 1);
    TCGEN05_FENCE_AFTER();

    {
        int mt  = wid >> 2;                       // 0 or 1
        int row = bm + mt * 128 + (wid & 3) * 32 + lid;
        float* crow = C + (size_t)row * Nstride + bn;
        uint32_t tcol = tmem + (uint32_t)(mt * 128);
#pragma unroll
        for (int g = 0; g < 4; ++g) {
            uint32_t r[32];
            TCGEN05_LD_32X32B_X32(r, tcol + g * 32);
            TCGEN05_WAIT_LD();
            int n0 = bn + g * 32;
            if (n0 + 32 <= Nout) {
#pragma unroll
                for (int j = 0; j < 32; j += 4) {
                    float4 v = make_float4(__uint_as_float(r[j]), __uint_as_float(r[j + 1]),
                                           __uint_as_float(r[j + 2]), __uint_as_float(r[j + 3]));
                    *reinterpret_cast<float4*>(crow + g * 32 + j) = v;
                }
            } else {
                for (int j = 0; j < 32; ++j)
                    if (n0 + j < Nout) crow[g * 32 + j] = __uint_as_float(r[j]);
            }
        }
        TCGEN05_FENCE_BEFORE();
    }
    __syncthreads();
    if (wid == 0) TCGEN05_DEALLOC(tmem, 256);

#else   // ---------------- SIMT fallback (generic PTX pass only; never runs) --
    const int tid = threadIdx.x;
    const int bm  = blockIdx.y * 256;
    const int bn  = blockIdx.x * 128;
    const int K   = NC * 64;
    for (int e = tid; e < 256 * 128; e += 256) {
        int i = e >> 7, j = e & 127;
        int m = bm + i, n = bn + j;
        if (n >= Nout) continue;
        float acc = 0.f;
        for (int k = 0; k < K; ++k) {
            size_t ablk = APK_BLK(m >> 8, k >> 6);
            uint32_t aoff = SW128((uint32_t)((m & 255) * 128 + (k & 63) * 2));
            size_t bblk = BPK_BLK(n >> 7, k >> 6);
            uint32_t boff = SW128((uint32_t)((n & 127) * 128 + (k & 63) * 2));
            float a = __bfloat162float(*(const __nv_bfloat16*)(Ahi + ablk + aoff)) +
                      __bfloat162float(*(const __nv_bfloat16*)(Alo + ablk + aoff));
            float b = __bfloat162float(*(const __nv_bfloat16*)(Bhi + bblk + boff)) +
                      __bfloat162float(*(const __nv_bfloat16*)(Blo + bblk + boff));
            acc = fmaf(a, b, acc);
        }
        C[(size_t)m * Nstride + n] = acc;
    }
#endif
}

// ---------------------------------------------------------------------------
// Intra-chunk (dt folded in): dt -> dacs -> scores(T) -> y_intra, chunk_state
// ---------------------------------------------------------------------------
__global__ void __launch_bounds__(256, 3)
intra_kernel(const float* __restrict__ dt_W, const float* __restrict__ dt_b,
             const float* __restrict__ A_log)
{
    const int bid = blockIdx.x;        // (b*NCHUNK + c)*NHEADS + h
    const int h   = bid & 15;
    const int bc  = bid >> 4;
    const int t0  = bc * CHUNK;
    const int tid = threadIdx.x;
    const int wid = tid >> 5;
    const int lid = tid & 31;

    __shared__ float xs[64][68];
    __shared__ float scT[64][68];      // scT[k][i] = scores[i][k]
    __shared__ float Bsh[64][20];
    __shared__ float Csh[64][20];      // reused as bw after scores
    __shared__ float dts[64];
    __shared__ float dacs[64];
    __shared__ float wk[64];

    for (int idx = tid; idx < 64 * 16; idx += 256) {
        int k = idx >> 4, p4 = idx & 15;
        float4 v = *reinterpret_cast<const float4*>(
            g_proj + (size_t)(t0 + k) * PROJ + OFF_XP + h * HDIM + p4 * 4);
        *reinterpret_cast<float4*>(&xs[k][p4 * 4]) = v;
    }
    {
        int k = tid >> 2, n4 = tid & 3;
        float4 vb = *reinterpret_cast<const float4*>(
            g_proj + (size_t)(t0 + k) * PROJ + OFF_B + h * DSTATE + n4 * 4);
        float4 vc = *reinterpret_cast<const float4*>(
            g_proj + (size_t)(t0 + k) * PROJ + OFF_C + h * DSTATE + n4 * 4);
        *reinterpret_cast<float4*>(&Bsh[k][n4 * 4]) = vb;
        *reinterpret_cast<float4*>(&Csh[k][n4 * 4]) = vc;
    }
    if (tid < 64) {
        const float* row = g_proj + (size_t)(t0 + tid) * PROJ + OFF_DT;
        float acc = dt_b[h];
#pragma unroll
        for (int r = 0; r < DTRANK; ++r)
            acc = fmaf(row[r], dt_W[h * DTRANK + r], acc);
        dts[tid] = (acc > 20.f) ? acc : log1pf(expf(acc));
    }
    __syncthreads();

    if (wid == 0) {
        float A  = -expf(A_log[h]);
        float v1 = dts[2 * lid + 1] * A;
        float s  = dts[2 * lid] * A + v1;
#pragma unroll
        for (int off = 1; off < 32; off <<= 1) {
            float t = __shfl_up_sync(0xffffffffu, s, off);
            if (lid >= off) s += t;
        }
        dacs[2 * lid + 1] = s;
        dacs[2 * lid]     = s - v1;
    }
    __syncthreads();

    if (tid < 64) {
        wk[tid] = dts[tid] * expf(dacs[63] - dacs[tid]);
        g_dacs[(size_t)(t0 + tid) * NHEADS + h] = dacs[tid];
    }
    if (tid == 0) g_cdecay[bid] = expf(dacs[63]);
    __syncthreads();

    // scores: thread owns row i = tid&63, columns j0..j0+15; writes transposed
    {
        int i  = tid & 63;
        int j0 = (tid >> 6) * 16;
        float ci[16];
#pragma unroll
        for (int n = 0; n < 16; ++n) ci[n] = Csh[i][n];
        float di = dacs[i];
#pragma unroll
        for (int jj = 0; jj < 16; ++jj) {
            int j = j0 + jj;
            float v = 0.f;
            if (j <= i) {
                float d = 0.f;
#pragma unroll
                for (int n = 0; n < 16; ++n)
                    d = fmaf(ci[n], Bsh[j][n], d);
                v = d * expf(di - dacs[j]) * dts[j];
            }
            scT[j][i] = v;
        }
    }
    __syncthreads();

    // bw[k][n] = B[k][n] * wk[k]  (overwrite Csh, dead after scores)
    for (int idx = tid; idx < 64 * 16; idx += 256) {
        int k = idx >> 4, n = idx & 15;
        Csh[k][n] = Bsh[k][n] * wk[k];
    }
    __syncthreads();

    // y_intra: 4x4 register blocking, causal-truncated k loop, float4 LDS both
    {
        int a  = tid >> 4;
        int b  = tid & 15;
        int i0 = a * 4, p0 = b * 4;
        float acc[4][4];
#pragma unroll
        for (int q = 0; q < 4; ++q)
#pragma unroll
            for (int r = 0; r < 4; ++r) acc[q][r] = 0.f;
        const int kmax = i0 + 4;          // scT[k][i] = 0 for k > i
        for (int kk = 0; kk < kmax; ++kk) {
            float4 s4 = *reinterpret_cast<const float4*>(&scT[kk][i0]);
            float4 xr = *reinterpret_cast<const float4*>(&xs[kk][p0]);
            acc[0][0] = fmaf(s4.x, xr.x, acc[0][0]);
            acc[0][1] = fmaf(s4.x, xr.y, acc[0][1]);
            acc[0][2] = fmaf(s4.x, xr.z, acc[0][2]);
            acc[0][3] = fmaf(s4.x, xr.w, acc[0][3]);
            acc[1][0] = fmaf(s4.y, xr.x, acc[1][0]);
            acc[1][1] = fmaf(s4.y, xr.y, acc[1][1]);
            acc[1][2] = fmaf(s4.y, xr.z, acc[1][2]);
            acc[1][3] = fmaf(s4.y, xr.w, acc[1][3]);
            acc[2][0] = fmaf(s4.z, xr.x, acc[2][0]);
            acc[2][1] = fmaf(s4.z, xr.y, acc[2][1]);
            acc[2][2] = fmaf(s4.z, xr.z, acc[2][2]);
            acc[2][3] = fmaf(s4.z, xr.w, acc[2][3]);
            acc[3][0] = fmaf(s4.w, xr.x, acc[3][0]);
            acc[3][1] = fmaf(s4.w, xr.y, acc[3][1]);
            acc[3][2] = fmaf(s4.w, xr.z, acc[3][2]);
            acc[3][3] = fmaf(s4.w, xr.w, acc[3][3]);
        }
#pragma unroll
        for (int q = 0; q < 4; ++q) {
            float4 v = make_float4(acc[q][0], acc[q][1], acc[q][2], acc[q][3]);
            *reinterpret_cast<float4*>(
                g_y + (size_t)(t0 + i0 + q) * DINNER + h * HDIM + p0) = v;
        }
    }

    // chunk_state[n][p] = sum_k bw[k][n] * x[k][p]
    {
        int n  = tid >> 4;
        int p0 = (tid & 15) * 4;
        float4 acc = make_float4(0.f, 0.f, 0.f, 0.f);
        for (int k = 0; k < 64; ++k) {
            float bwv = Csh[k][n];
            float4 xr = *reinterpret_cast<const float4*>(&xs[k][p0]);
            acc.x = fmaf(bwv, xr.x, acc.x);
            acc.y = fmaf(bwv, xr.y, acc.y);
            acc.z = fmaf(bwv, xr.z, acc.z);
            acc.w = fmaf(bwv, xr.w, acc.w);
        }
        *reinterpret_cast<float4*>(
            g_cs + (size_t)bid * (DSTATE * HDIM) + n * HDIM + p0) = acc;
    }
}

// ---------------------------------------------------------------------------
// Sequential scan over chunks: grid = BATCH*NHEADS*4, 1 elem/thread
// ---------------------------------------------------------------------------
__global__ void __launch_bounds__(256)
scan_kernel()
{
    const int g   = blockIdx.x;
    const int bh  = g >> 2;
    const int seg = g & 3;
    const int b   = bh >> 4;
    const int h   = bh & 15;
    const int e   = seg * 256 + threadIdx.x;

    const int    chid0  = (b * NCHUNK) * NHEADS + h;
    const size_t base   = (size_t)chid0 * (DSTATE * HDIM);
    const size_t stride = (size_t)NHEADS * DSTATE * HDIM;

    float hv  = 0.f;
    float cur = g_cs[base + e];
    float d   = g_cdecay[chid0];
    for (int c = 0; c < NCHUNK; ++c) {
        float nxt = 0.f, dn = 0.f;
        if (c + 1 < NCHUNK) {
            nxt = g_cs[base + stride * (c + 1) + e];
            dn  = g_cdecay[chid0 + (c + 1) * NHEADS];
        }
        g_hs[base + stride * c + e] = hv;
        hv = fmaf(d, hv, cur);
        cur = nxt; d = dn;
    }
}

// ---------------------------------------------------------------------------
// Cross-chunk + skip
// ---------------------------------------------------------------------------
__global__ void __launch_bounds__(256, 2)
cross_kernel(const float* __restrict__ D_param)
{
    const int bid = blockIdx.x;
    const int h   = bid & 15;
    const int bc  = bid >> 4;
    const int t0  = bc * CHUNK;
    const int tid = threadIdx.x;

    __shared__ float hs[16][68];
    __shared__ float Csh[64][20];
    __shared__ float dacs[64];

    {
        int n = tid >> 4, pg = tid & 15;
        float4 v = *reinterpret_cast<const float4*>(
            g_hs + (size_t)bid * (DSTATE * HDIM) + n * HDIM + pg * 4);
        *reinterpret_cast<float4*>(&hs[n][pg * 4]) = v;
    }
    {
        int k = tid >> 2, n4 = tid & 3;
        float4 vc = *reinterpret_cast<const float4*>(
            g_proj + (size_t)(t0 + k) * PROJ + OFF_C + h * DSTATE + n4 * 4);
        *reinterpret_cast<float4*>(&Csh[k][n4 * 4]) = vc;
    }
    if (tid < 64) dacs[tid] = g_dacs[(size_t)(t0 + tid) * NHEADS + h];
    __syncthreads();

    int i  = tid >> 2;
    int p0 = (tid & 3) * 16;
    float ci[16];
#pragma unroll
    for (int n = 0; n < 16; ++n) ci[n] = Csh[i][n];
    float e  = expf(dacs[i]);
    float dp = D_param[h];

    size_t t = (size_t)(t0 + i);
    const float* xrow = g_proj + t * PROJ + OFF_XP + h * HDIM;
    float* yrow = g_y + t * DINNER + h * HDIM;
#pragma unroll
    for (int g4 = 0; g4 < 4; ++g4) {
        int p = p0 + g4 * 4;
        float4 yv = *reinterpret_cast<const float4*>(yrow + p);
        float4 xv = *reinterpret_cast<const float4*>(xrow + p);
        float a0 = 0.f, a1 = 0.f, a2 = 0.f, a3 = 0.f;
#pragma unroll
        for (int n = 0; n < 16; ++n) {
            float c = ci[n];
            a0 = fmaf(c, hs[n][p + 0], a0);
            a1 = fmaf(c, hs[n][p + 1], a1);
            a2 = fmaf(c, hs[n][p + 2], a2);
            a3 = fmaf(c, hs[n][p + 3], a3);
        }
        float4 o;
        o.x = yv.x + e * a0 + dp * xv.x;
        o.y = yv.y + e * a1 + dp * xv.y;
        o.z = yv.z + e * a2 + dp * xv.z;
        o.w = yv.w + e * a3 + dp * xv.w;
        *reinterpret_cast<float4*>(yrow + p) = o;
    }
}

// ---------------------------------------------------------------------------
// RMS norm + SiLU gate -> yg packed (bf16 hi/lo, swizzled A-tile layout)
// ---------------------------------------------------------------------------
__global__ void __launch_bounds__(256)
norm_kernel(const float* __restrict__ norm_w)
{
    const int t   = blockIdx.x;
    const int tid = threadIdx.x;

    float4 v = reinterpret_cast<const float4*>(g_y + (size_t)t * DINNER)[tid];
    float ss = v.x * v.x + v.y * v.y + v.z * v.z + v.w * v.w;
#pragma unroll
    for (int off = 16; off > 0; off >>= 1)
        ss += __shfl_xor_sync(0xffffffffu, ss, off);

    __shared__ float red[8];
    __shared__ float s_inv;
    if ((tid & 31) == 0) red[tid >> 5] = ss;
    __syncthreads();
    if (tid == 0) {
        float s = 0.f;
#pragma unroll
        for (int i = 0; i < 8; ++i) s += red[i];
        s_inv = rsqrtf(s * (1.f / DINNER) + 1e-6f);
    }
    __syncthreads();
    float inv = s_inv;

    const float* zrow = g_proj + (size_t)t * PROJ + OFF_Z;
    int c = tid * 4;
    float4 z4 = *reinterpret_cast<const float4*>(zrow + c);
    float4 w4 = *reinterpret_cast<const float4*>(norm_w + c);
    float4 o;
    o.x = v.x * inv * w4.x * (z4.x / (1.f + expf(-z4.x)));
    o.y = v.y * inv * w4.y * (z4.y / (1.f + expf(-z4.y)));
    o.z = v.z * inv * w4.z * (z4.z / (1.f + expf(-z4.z)));
    o.w = v.w * inv * w4.w * (z4.w / (1.f + expf(-z4.w)));

    uint2 h, l;
    split4(o, h, l);
    size_t  blk = APK_BLK(t >> 8, c >> 6);
    uint32_t off = (uint32_t)((t & 255) * 128 + (c & 63) * 2);
    off = SW128(off);
    *reinterpret_cast<uint2*>(g_yghi + blk + off) = h;
    *reinterpret_cast<uint2*>(g_yglo + blk + off) = l;
}

// ---------------------------------------------------------------------------
// Launch — proj GEMM at slot #4 (profiled)
// ---------------------------------------------------------------------------
extern "C" void kernel_launch(void* const* d_in, const int* in_sizes, int n_in,
                              void* d_out, int out_size)
{
    const float* x      = (const float*)d_in[0];
    const float* W_in   = (const float*)d_in[1];
    const float* dt_W   = (const float*)d_in[2];
    const float* dt_b   = (const float*)d_in[3];
    const float* A_log  = (const float*)d_in[4];
    const float* D_par  = (const float*)d_in[5];
    const float* W_out  = (const float*)d_in[6];
    const float* norm_w = (const float*)d_in[7];
    float* out = (float*)d_out;

    float* proj_ptr = nullptr;
    uint8_t *xhi, *xlo, *winhi, *winlo, *wouthi, *woutlo, *yghi, *yglo;
    cudaGetSymbolAddress((void**)&proj_ptr, g_proj);
    cudaGetSymbolAddress((void**)&xhi, g_xhi);
    cudaGetSymbolAddress((void**)&xlo, g_xlo);
    cudaGetSymbolAddress((void**)&winhi, g_winhi);
    cudaGetSymbolAddress((void**)&winlo, g_winlo);
    cudaGetSymbolAddress((void**)&wouthi, g_wouthi);
    cudaGetSymbolAddress((void**)&woutlo, g_woutlo);
    cudaGetSymbolAddress((void**)&yghi, g_yghi);
    cudaGetSymbolAddress((void**)&yglo, g_yglo);

    cudaFuncSetAttribute(gemm_tc, cudaFuncAttributeMaxDynamicSharedMemorySize, GEMM_SMEM_BYTES);

    // 1) pack x
    {
        int n4 = TOKENS * DMODEL / 4;
        split_pack_A<<<(n4 + 255) / 256, 256>>>(x, xhi, xlo, n4);
    }
    // 2) pack W_in (padded to 2688 rows)
    {
        int n4 = PROJPAD * DMODEL / 4;
        split_pack_B<<<(n4 + 255) / 256, 256>>>(W_in, winhi, winlo, PROJ, n4);
    }
    // 3) pack W_out
    {
        int n4 = DMODEL * DINNER / 4;
        split_pack_B<<<(n4 + 255) / 256, 256>>>(W_out, wouthi, woutlo, DMODEL, n4);
    }
    // 4) proj = x @ W_in^T   [16384, 2576]   <- profiled slot
    {
        dim3 grid(PROJPAD / 128, TOKENS / 256);
        gemm_tc<<<grid, 256, GEMM_SMEM_BYTES>>>(xhi, xlo, winhi, winlo,
                                                proj_ptr, DMODEL / 64, PROJ, PROJ);
    }
    // 5) intra-chunk (+dt)
    intra_kernel<<<BATCH * NCHUNK * NHEADS, 256>>>(dt_W, dt_b, A_log);
    // 6) chunk scan
    scan_kernel<<<BATCH * NHEADS * 4, 256>>>();
    // 7) cross-chunk + skip
    cross_kernel<<<BATCH * NCHUNK * NHEADS, 256>>>(D_par);
    // 8) RMS norm + gate -> packed bf16 hi/lo
    norm_kernel<<<TOKENS, 256>>>(norm_w);
    // 9) out = yg @ W_out^T  [16384, 1024]
    {
        dim3 grid(DMODEL / 128, TOKENS / 256);
        gemm_tc<<<grid, 256, GEMM_SMEM_BYTES>>>(yghi, yglo, wouthi, woutlo,
                                                out, DINNER / 64, DMODEL, DMODEL);
    }
}

// round 9
// speedup vs baseline: 4.8677x; 1.0407x over previous
#include <cuda_runtime.h>
#include <cuda_bf16.h>
#include <cstdint>

// ---------------------------------------------------------------------------
// Problem constants
// ---------------------------------------------------------------------------
#define BATCH   4
#define SEQ     4096
#define TOKENS  (BATCH * SEQ)        // 16384
#define DMODEL  1024
#define DINNER  1024
#define NHEADS  16
#define HDIM    64
#define DSTATE  16
#define DTRANK  16
#define CHUNK   64
#define NCHUNK  (SEQ / CHUNK)        // 64
#define PROJ    2576
#define PROJPAD 2688                 // 21 * 128

#define OFF_XP   0
#define OFF_Z    1024
#define OFF_B    2048
#define OFF_C    2304
#define OFF_DT   2560

// Packed-operand block offsets (bytes). A-pack: 256-row tiles; B-pack: 128-row.
// Both GEMMs have K=1024 -> exactly 16 chunks of 64 columns.
#define APK_BLK(mt, ch) ((((size_t)(mt) * 16) + (size_t)(ch)) * 32768)
#define BPK_BLK(nt, ch) ((((size_t)(nt) * 16) + (size_t)(ch)) * 16384)
#define SW128(o) ((o) ^ (((o) >> 3) & 0x70))

// tcgen05 is an arch-SPECIFIC feature: only emit it in the sm_103a/f passes.
#if defined(__CUDA_ARCH_FEAT_SM103_ALL) || \
    (defined(__CUDA_ARCH_FAMILY_SPECIFIC__) && __CUDA_ARCH_FAMILY_SPECIFIC__ >= 1000) || \
    (defined(__CUDA_ARCH_SPECIFIC__) && __CUDA_ARCH_SPECIFIC__ >= 1000)
#define HAS_TCGEN05 1
#else
#define HAS_TCGEN05 0
#endif

// ---------------------------------------------------------------------------
// PTX helpers (guarded)
// ---------------------------------------------------------------------------
#if HAS_TCGEN05
__device__ __forceinline__ uint32_t smem_to_u32(const void* p) {
    uint32_t a;
    asm("{ .reg .u64 t; cvta.to.shared.u64 t, %1; cvt.u32.u64 %0, t; }" : "=r"(a) : "l"(p));
    return a;
}
__device__ __forceinline__ uint32_t elect_one_pred() {
    uint32_t pred;
    asm volatile("{\n\t.reg .pred p;\n\telect.sync _|p, 0xFFFFFFFF;\n\tselp.b32 %0, 1, 0, p;\n\t}" : "=r"(pred));
    return pred;
}
#define TCGEN05_ALLOC(smem_result_addr, nCols) \
    asm volatile("tcgen05.alloc.cta_group::1.sync.aligned.shared::cta.b32 [%0], %1;" \
        :: "r"((uint32_t)(smem_result_addr)), "r"((uint32_t)(nCols)) : "memory")
#define TCGEN05_DEALLOC(tmem_addr, nCols) \
    asm volatile("tcgen05.dealloc.cta_group::1.sync.aligned.b32 %0, %1;" :: "r"(tmem_addr), "r"((uint32_t)(nCols)))
#define TCGEN05_RELINQUISH() \
    asm volatile("tcgen05.relinquish_alloc_permit.cta_group::1.sync.aligned;")
#define TCGEN05_COMMIT(mbar) \
    asm volatile("tcgen05.commit.cta_group::1.mbarrier::arrive::one.shared::cluster.b64 [%0];" \
        :: "r"((uint32_t)(mbar)) : "memory")
#define TCGEN05_FENCE_AFTER()  asm volatile("tcgen05.fence::after_thread_sync;" ::: "memory")
#define TCGEN05_FENCE_BEFORE() asm volatile("tcgen05.fence::before_thread_sync;" ::: "memory")
#define TCGEN05_WAIT_LD()      asm volatile("tcgen05.wait::ld.sync.aligned;" ::: "memory")
#define MBARRIER_INIT(mbar, count) \
    asm volatile("mbarrier.init.shared.b64 [%0], %1;" :: "r"((uint32_t)(mbar)), "r"((uint32_t)(count)) : "memory")
#define FENCE_PROXY_ASYNC() asm volatile("fence.proxy.async.shared::cta;" ::: "memory")
#define CP_ASYNC16(dst, src) \
    asm volatile("cp.async.cg.shared.global [%0], [%1], 16;" \
        :: "r"((uint32_t)(dst)), "l"(src) : "memory")
#define CP_ASYNC_COMMIT() asm volatile("cp.async.commit_group;" ::: "memory")
#define CP_ASYNC_WAIT1()  asm volatile("cp.async.wait_group 1;" ::: "memory")
#define MBARRIER_WAIT_PARITY(mbar, parity) do { \
    uint32_t _m = (uint32_t)(mbar); uint32_t _p = (uint32_t)(parity); uint32_t _d; \
    asm volatile("{\n\t.reg .pred p;\n\t" \
        "mbarrier.try_wait.parity.acquire.cta.shared::cta.b64 p, [%1], %2;\n\t" \
        "selp.b32 %0, 1, 0, p;\n\t}" : "=r"(_d) : "r"(_m), "r"(_p) : "memory"); \
    if (!_d) { \
        asm volatile("{\n\t.reg .pred P1;\n\t" \
            "WL_%=:\n\t" \
            "mbarrier.try_wait.parity.acquire.cta.shared::cta.b64 P1, [%0], %1, 0x989680;\n\t" \
            "@P1 bra.uni WD_%=;\n\t" \
            "bra.uni WL_%=;\n\t" \
            "WD_%=:\n\t}" :: "r"(_m), "r"(_p) : "memory"); \
    } } while (0)
#define TCGEN05_LD_32X32B_X32(r, tmem_addr) \
    asm volatile("tcgen05.ld.sync.aligned.32x32b.x32.b32 " \
        "{%0, %1, %2, %3, %4, %5, %6, %7, %8, %9, %10, %11, %12, %13, %14, %15, " \
        " %16, %17, %18, %19, %20, %21, %22, %23, %24, %25, %26, %27, %28, %29, %30, %31}, [%32];" \
        : "=r"((r)[0]),  "=r"((r)[1]),  "=r"((r)[2]),  "=r"((r)[3]), \
          "=r"((r)[4]),  "=r"((r)[5]),  "=r"((r)[6]),  "=r"((r)[7]), \
          "=r"((r)[8]),  "=r"((r)[9]),  "=r"((r)[10]), "=r"((r)[11]), \
          "=r"((r)[12]), "=r"((r)[13]), "=r"((r)[14]), "=r"((r)[15]), \
          "=r"((r)[16]), "=r"((r)[17]), "=r"((r)[18]), "=r"((r)[19]), \
          "=r"((r)[20]), "=r"((r)[21]), "=r"((r)[22]), "=r"((r)[23]), \
          "=r"((r)[24]), "=r"((r)[25]), "=r"((r)[26]), "=r"((r)[27]), \
          "=r"((r)[28]), "=r"((r)[29]), "=r"((r)[30]), "=r"((r)[31]) \
        : "r"(tmem_addr))

static constexpr uint64_t SMEM_DESC_BASE_SW128 =
    (uint64_t(2) << 61) | (uint64_t(1) << 46) | (uint64_t(64) << 32) | (uint64_t(1) << 16);
#define MAKE_SMEM_DESC(base_addr) (SMEM_DESC_BASE_SW128 | ((uint64_t)((base_addr) >> 4) & 0x3FFF))

// idesc: dtype=F32(bit4), atype=BF16(bit7), btype=BF16(bit10), N/8 @17, M/16 @24
#define MMA_IDESC_128x128 ((1u << 4) | (1u << 7) | (1u << 10) | (16u << 17) | (8u << 24))

__device__ __forceinline__ void mma_f16_ss(uint32_t d_tmem, uint64_t a_desc, uint64_t b_desc,
                                           uint32_t idesc, uint32_t enable)
{
    asm volatile(
        "{\n\t.reg .pred p;\n\t"
        "setp.ne.u32 p, %4, 0;\n\t"
        "tcgen05.mma.cta_group::1.kind::f16 [%0], %1, %2, %3, {%5, %5, %5, %5}, p;\n\t"
        "}"
        :: "r"(d_tmem), "l"(a_desc), "l"(b_desc), "r"(idesc), "r"(enable), "r"(0u)
        : "memory");
}
#endif  // HAS_TCGEN05

// ---------------------------------------------------------------------------
// Scratch (device globals; no allocation allowed)
// ---------------------------------------------------------------------------
__device__ float g_proj[(size_t)TOKENS * PROJ];
__device__ float g_dacs[(size_t)TOKENS * NHEADS];
__device__ float g_y[(size_t)TOKENS * DINNER];
__device__ float g_cs[(size_t)BATCH * NCHUNK * NHEADS * DSTATE * HDIM];
__device__ float g_hs[(size_t)BATCH * NCHUNK * NHEADS * DSTATE * HDIM];
__device__ float g_cdecay[(size_t)BATCH * NCHUNK * NHEADS];

__device__ __align__(1024) uint8_t g_xhi[(size_t)TOKENS * DMODEL * 2];
__device__ __align__(1024) uint8_t g_xlo[(size_t)TOKENS * DMODEL * 2];
__device__ __align__(1024) uint8_t g_winhi[(size_t)PROJPAD * DMODEL * 2];
__device__ __align__(1024) uint8_t g_winlo[(size_t)PROJPAD * DMODEL * 2];
__device__ __align__(1024) uint8_t g_wouthi[(size_t)DMODEL * DINNER * 2];
__device__ __align__(1024) uint8_t g_woutlo[(size_t)DMODEL * DINNER * 2];
__device__ __align__(1024) uint8_t g_yghi[(size_t)TOKENS * DINNER * 2];
__device__ __align__(1024) uint8_t g_yglo[(size_t)TOKENS * DINNER * 2];

// ---------------------------------------------------------------------------
// hi/lo split helper
// ---------------------------------------------------------------------------
__device__ __forceinline__ void split4(float4 v, uint2& h, uint2& l)
{
    __nv_bfloat16 hx = __float2bfloat16(v.x), hy = __float2bfloat16(v.y);
    __nv_bfloat16 hz = __float2bfloat16(v.z), hw = __float2bfloat16(v.w);
    __nv_bfloat162 h01 = {hx, hy}, h23 = {hz, hw};
    __nv_bfloat162 l01 = {__float2bfloat16(v.x - __bfloat162float(hx)),
                          __float2bfloat16(v.y - __bfloat162float(hy))};
    __nv_bfloat162 l23 = {__float2bfloat16(v.z - __bfloat162float(hz)),
                          __float2bfloat16(v.w - __bfloat162float(hw))};
    h.x = *reinterpret_cast<uint32_t*>(&h01);
    h.y = *reinterpret_cast<uint32_t*>(&h23);
    l.x = *reinterpret_cast<uint32_t*>(&l01);
    l.y = *reinterpret_cast<uint32_t*>(&l23);
}

// Pack activations (256-row A tiles): src [rows][1024] fp32 -> swizzled blocks
__global__ void __launch_bounds__(256)
split_pack_A(const float* __restrict__ src, uint8_t* __restrict__ hi,
             uint8_t* __restrict__ lo, int n4)
{
    int i = blockIdx.x * 256 + threadIdx.x;
    if (i >= n4) return;
    int t  = i >> 8;
    int k0 = (i & 255) * 4;
    float4 v = reinterpret_cast<const float4*>(src)[i];
    uint2 h, l;
    split4(v, h, l);
    size_t  blk = APK_BLK(t >> 8, k0 >> 6);
    uint32_t off = (uint32_t)((t & 255) * 128 + (k0 & 63) * 2);
    off = SW128(off);
    *reinterpret_cast<uint2*>(hi + blk + off) = h;
    *reinterpret_cast<uint2*>(lo + blk + off) = l;
}

// Pack weights (128-row B tiles) with zero row padding
__global__ void __launch_bounds__(256)
split_pack_B(const float* __restrict__ src, uint8_t* __restrict__ hi,
             uint8_t* __restrict__ lo, int rows_src, int n4)
{
    int i = blockIdx.x * 256 + threadIdx.x;
    if (i >= n4) return;
    int r  = i >> 8;
    int k0 = (i & 255) * 4;
    float4 v = make_float4(0.f, 0.f, 0.f, 0.f);
    if (r < rows_src) v = reinterpret_cast<const float4*>(src)[i];
    uint2 h, l;
    split4(v, h, l);
    size_t  blk = BPK_BLK(r >> 7, k0 >> 6);
    uint32_t off = (uint32_t)((r & 127) * 128 + (k0 & 63) * 2);
    off = SW128(off);
    *reinterpret_cast<uint2*>(hi + blk + off) = h;
    *reinterpret_cast<uint2*>(lo + blk + off) = l;
}

// ---------------------------------------------------------------------------
// tcgen05 bf16-split GEMM, packed operands, cp.async staging, prefetch-ahead
// pipeline (copies run one chunk ahead of MMA consumption).
// 256x128 tile, K-chunks of 64, double-buffered. 256 threads.
// Stage layout: Ahi @0 (32K), Alo @32768, Bhi @65536 (16K), Blo @81920.
// ---------------------------------------------------------------------------
#define STAGE_BYTES 98304
#define GEMM_SMEM_BYTES (2048 + 2 * STAGE_BYTES)

#if HAS_TCGEN05
__device__ __forceinline__ void gemm_copy_chunk(
    uint32_t stage, int tid,
    const uint8_t* __restrict__ Ahi, const uint8_t* __restrict__ Alo,
    const uint8_t* __restrict__ Bhi, const uint8_t* __restrict__ Blo,
    int mt, int nt, int c)
{
    const uint8_t* sAh = Ahi + APK_BLK(mt, c);
    const uint8_t* sAl = Alo + APK_BLK(mt, c);
    const uint8_t* sBh = Bhi + BPK_BLK(nt, c);
    const uint8_t* sBl = Blo + BPK_BLK(nt, c);
#pragma unroll
    for (int it = 0; it < 8; ++it) {
        uint32_t b = (uint32_t)(it * 256 + tid) * 16u;   // 0..32767
        CP_ASYNC16(stage + b,          sAh + b);
        CP_ASYNC16(stage + 32768u + b, sAl + b);
    }
#pragma unroll
    for (int it = 0; it < 4; ++it) {
        uint32_t b = (uint32_t)(it * 256 + tid) * 16u;   // 0..16383
        CP_ASYNC16(stage + 65536u + b, sBh + b);
        CP_ASYNC16(stage + 81920u + b, sBl + b);
    }
    CP_ASYNC_COMMIT();
}
#endif

__global__ void __launch_bounds__(256, 1)
gemm_tc(const uint8_t* __restrict__ Ahi, const uint8_t* __restrict__ Alo,
        const uint8_t* __restrict__ Bhi, const uint8_t* __restrict__ Blo,
        float* __restrict__ C, int NC, int Nstride, int Nout)
{
#if HAS_TCGEN05
    extern __shared__ char smem[];
    const uint32_t sbase = smem_to_u32(smem);
    const int tid = threadIdx.x;
    const int wid = tid >> 5;
    const int lid = tid & 31;
    const int bm = blockIdx.y * 256;
    const int bn = blockIdx.x * 128;

    const uint32_t TMEMP = sbase;
    const uint32_t DONE0 = sbase + 8;
    const uint32_t DONE1 = sbase + 16;
    const uint32_t BUF   = (sbase + 32 + 1023) & ~1023u;

    if (wid == 0) {
        TCGEN05_ALLOC(TMEMP, 256);
        TCGEN05_RELINQUISH();
    }
    if (tid == 0) { MBARRIER_INIT(DONE0, 1); MBARRIER_INIT(DONE1, 1); }
    __syncthreads();
    uint32_t tmem;
    asm volatile("ld.shared.b32 %0, [%1];" : "=r"(tmem) : "r"(TMEMP));

    // prologue: copies for chunks 0 and 1 in flight
    gemm_copy_chunk(BUF,               tid, Ahi, Alo, Bhi, Blo, blockIdx.y, blockIdx.x, 0);
    gemm_copy_chunk(BUF + STAGE_BYTES, tid, Ahi, Alo, Bhi, Blo, blockIdx.y, blockIdx.x, 1);

    for (int c = 0; c < NC; ++c) {
        const int st = c & 1;
        const uint32_t stage = BUF + (uint32_t)st * (uint32_t)STAGE_BYTES;
        const uint32_t done  = st ? DONE1 : DONE0;

        CP_ASYNC_WAIT1();          // chunk c's copy done (c+1 may still stream)
        __syncthreads();

        if (wid == 0) {
            FENCE_PROXY_ASYNC();
            if (elect_one_pred()) {
                uint64_t dA0h = MAKE_SMEM_DESC(stage);
                uint64_t dA1h = MAKE_SMEM_DESC(stage + 16384);
                uint64_t dA0l = MAKE_SMEM_DESC(stage + 32768);
                uint64_t dA1l = MAKE_SMEM_DESC(stage + 49152);
                uint64_t dBh  = MAKE_SMEM_DESC(stage + 65536);
                uint64_t dBl  = MAKE_SMEM_DESC(stage + 81920);
#pragma unroll
                for (int ks = 0; ks < 4; ++ks) {
                    uint32_t en0 = (c == 0 && ks == 0) ? 0u : 1u;
                    mma_f16_ss(tmem,       dA0h + ks * 2, dBh + ks * 2, MMA_IDESC_128x128, en0);
                    mma_f16_ss(tmem,       dA0h + ks * 2, dBl + ks * 2, MMA_IDESC_128x128, 1u);
                    mma_f16_ss(tmem,       dA0l + ks * 2, dBh + ks * 2, MMA_IDESC_128x128, 1u);
                    mma_f16_ss(tmem + 128, dA1h + ks * 2, dBh + ks * 2, MMA_IDESC_128x128, en0);
                    mma_f16_ss(tmem + 128, dA1h + ks * 2, dBl + ks * 2, MMA_IDESC_128x128, 1u);
                    mma_f16_ss(tmem + 128, dA1l + ks * 2, dBh + ks * 2, MMA_IDESC_128x128, 1u);
                }
                TCGEN05_COMMIT(done);
            }
        }

        // refill this stage with chunk c+2 once MMA(c) has finished reading it
        if (c + 2 < NC) {
            MBARRIER_WAIT_PARITY(done, (c >> 1) & 1);
            gemm_copy_chunk(stage, tid, Ahi, Alo, Bhi, Blo, blockIdx.y, blockIdx.x, c + 2);
        }
    }

    MBARRIER_WAIT_PARITY(DONE0, ((NC - 2) >> 1) & 1);
    MBARRIER_WAIT_PARITY(DONE1, ((NC - 1) >> 1) & 1);
    TCGEN05_FENCE_AFTER();

    {
        int mt  = wid >> 2;                       // 0 or 1
        int row = bm + mt * 128 + (wid & 3) * 32 + lid;
        float* crow = C + (size_t)row * Nstride + bn;
        uint32_t tcol = tmem + (uint32_t)(mt * 128);
#pragma unroll
        for (int g = 0; g < 4; ++g) {
            uint32_t r[32];
            TCGEN05_LD_32X32B_X32(r, tcol + g * 32);
            TCGEN05_WAIT_LD();
            int n0 = bn + g * 32;
            if (n0 + 32 <= Nout) {
#pragma unroll
                for (int j = 0; j < 32; j += 4) {
                    float4 v = make_float4(__uint_as_float(r[j]), __uint_as_float(r[j + 1]),
                                           __uint_as_float(r[j + 2]), __uint_as_float(r[j + 3]));
                    *reinterpret_cast<float4*>(crow + g * 32 + j) = v;
                }
            } else {
                for (int j = 0; j < 32; ++j)
                    if (n0 + j < Nout) crow[g * 32 + j] = __uint_as_float(r[j]);
            }
        }
        TCGEN05_FENCE_BEFORE();
    }
    __syncthreads();
    if (wid == 0) TCGEN05_DEALLOC(tmem, 256);

#else   // ---------------- SIMT fallback (generic PTX pass only; never runs) --
    const int tid = threadIdx.x;
    const int bm  = blockIdx.y * 256;
    const int bn  = blockIdx.x * 128;
    const int K   = NC * 64;
    for (int e = tid; e < 256 * 128; e += 256) {
        int i = e >> 7, j = e & 127;
        int m = bm + i, n = bn + j;
        if (n >= Nout) continue;
        float acc = 0.f;
        for (int k = 0; k < K; ++k) {
            size_t ablk = APK_BLK(m >> 8, k >> 6);
            uint32_t aoff = SW128((uint32_t)((m & 255) * 128 + (k & 63) * 2));
            size_t bblk = BPK_BLK(n >> 7, k >> 6);
            uint32_t boff = SW128((uint32_t)((n & 127) * 128 + (k & 63) * 2));
            float a = __bfloat162float(*(const __nv_bfloat16*)(Ahi + ablk + aoff)) +
                      __bfloat162float(*(const __nv_bfloat16*)(Alo + ablk + aoff));
            float b = __bfloat162float(*(const __nv_bfloat16*)(Bhi + bblk + boff)) +
                      __bfloat162float(*(const __nv_bfloat16*)(Blo + bblk + boff));
            acc = fmaf(a, b, acc);
        }
        C[(size_t)m * Nstride + n] = acc;
    }
#endif
}

// ---------------------------------------------------------------------------
// Intra-chunk (dt folded in): dt -> dacs -> scores(T) -> y_intra, chunk_state
// ---------------------------------------------------------------------------
__global__ void __launch_bounds__(256, 3)
intra_kernel(const float* __restrict__ dt_W, const float* __restrict__ dt_b,
             const float* __restrict__ A_log)
{
    const int bid = blockIdx.x;        // (b*NCHUNK + c)*NHEADS + h
    const int h   = bid & 15;
    const int bc  = bid >> 4;
    const int t0  = bc * CHUNK;
    const int tid = threadIdx.x;
    const int wid = tid >> 5;
    const int lid = tid & 31;

    __shared__ float xs[64][68];
    __shared__ float scT[64][68];      // scT[k][i] = scores[i][k]
    __shared__ float Bsh[64][20];
    __shared__ float Csh[64][20];      // reused as bw after scores
    __shared__ float dts[64];
    __shared__ float dacs[64];
    __shared__ float wk[64];

    for (int idx = tid; idx < 64 * 16; idx += 256) {
        int k = idx >> 4, p4 = idx & 15;
        float4 v = *reinterpret_cast<const float4*>(
            g_proj + (size_t)(t0 + k) * PROJ + OFF_XP + h * HDIM + p4 * 4);
        *reinterpret_cast<float4*>(&xs[k][p4 * 4]) = v;
    }
    {
        int k = tid >> 2, n4 = tid & 3;
        float4 vb = *reinterpret_cast<const float4*>(
            g_proj + (size_t)(t0 + k) * PROJ + OFF_B + h * DSTATE + n4 * 4);
        float4 vc = *reinterpret_cast<const float4*>(
            g_proj + (size_t)(t0 + k) * PROJ + OFF_C + h * DSTATE + n4 * 4);
        *reinterpret_cast<float4*>(&Bsh[k][n4 * 4]) = vb;
        *reinterpret_cast<float4*>(&Csh[k][n4 * 4]) = vc;
    }
    if (tid < 64) {
        const float* row = g_proj + (size_t)(t0 + tid) * PROJ + OFF_DT;
        float acc = dt_b[h];
#pragma unroll
        for (int r = 0; r < DTRANK; ++r)
            acc = fmaf(row[r], dt_W[h * DTRANK + r], acc);
        dts[tid] = (acc > 20.f) ? acc : log1pf(expf(acc));
    }
    __syncthreads();

    if (wid == 0) {
        float A  = -expf(A_log[h]);
        float v1 = dts[2 * lid + 1] * A;
        float s  = dts[2 * lid] * A + v1;
#pragma unroll
        for (int off = 1; off < 32; off <<= 1) {
            float t = __shfl_up_sync(0xffffffffu, s, off);
            if (lid >= off) s += t;
        }
        dacs[2 * lid + 1] = s;
        dacs[2 * lid]     = s - v1;
    }
    __syncthreads();

    if (tid < 64) {
        wk[tid] = dts[tid] * expf(dacs[63] - dacs[tid]);
        g_dacs[(size_t)(t0 + tid) * NHEADS + h] = dacs[tid];
    }
    if (tid == 0) g_cdecay[bid] = expf(dacs[63]);
    __syncthreads();

    // scores: thread owns row i = tid&63, columns j0..j0+15; writes transposed
    {
        int i  = tid & 63;
        int j0 = (tid >> 6) * 16;
        float ci[16];
#pragma unroll
        for (int n = 0; n < 16; ++n) ci[n] = Csh[i][n];
        float di = dacs[i];
#pragma unroll
        for (int jj = 0; jj < 16; ++jj) {
            int j = j0 + jj;
            float v = 0.f;
            if (j <= i) {
                float d = 0.f;
#pragma unroll
                for (int n = 0; n < 16; ++n)
                    d = fmaf(ci[n], Bsh[j][n], d);
                v = d * expf(di - dacs[j]) * dts[j];
            }
            scT[j][i] = v;
        }
    }
    __syncthreads();

    // bw[k][n] = B[k][n] * wk[k]  (overwrite Csh, dead after scores)
    for (int idx = tid; idx < 64 * 16; idx += 256) {
        int k = idx >> 4, n = idx & 15;
        Csh[k][n] = Bsh[k][n] * wk[k];
    }
    __syncthreads();

    // y_intra: 4x4 register blocking, causal-truncated k loop, float4 LDS both
    {
        int a  = tid >> 4;
        int b  = tid & 15;
        int i0 = a * 4, p0 = b * 4;
        float acc[4][4];
#pragma unroll
        for (int q = 0; q < 4; ++q)
#pragma unroll
            for (int r = 0; r < 4; ++r) acc[q][r] = 0.f;
        const int kmax = i0 + 4;          // scT[k][i] = 0 for k > i
        for (int kk = 0; kk < kmax; ++kk) {
            float4 s4 = *reinterpret_cast<const float4*>(&scT[kk][i0]);
            float4 xr = *reinterpret_cast<const float4*>(&xs[kk][p0]);
            acc[0][0] = fmaf(s4.x, xr.x, acc[0][0]);
            acc[0][1] = fmaf(s4.x, xr.y, acc[0][1]);
            acc[0][2] = fmaf(s4.x, xr.z, acc[0][2]);
            acc[0][3] = fmaf(s4.x, xr.w, acc[0][3]);
            acc[1][0] = fmaf(s4.y, xr.x, acc[1][0]);
            acc[1][1] = fmaf(s4.y, xr.y, acc[1][1]);
            acc[1][2] = fmaf(s4.y, xr.z, acc[1][2]);
            acc[1][3] = fmaf(s4.y, xr.w, acc[1][3]);
            acc[2][0] = fmaf(s4.z, xr.x, acc[2][0]);
            acc[2][1] = fmaf(s4.z, xr.y, acc[2][1]);
            acc[2][2] = fmaf(s4.z, xr.z, acc[2][2]);
            acc[2][3] = fmaf(s4.z, xr.w, acc[2][3]);
            acc[3][0] = fmaf(s4.w, xr.x, acc[3][0]);
            acc[3][1] = fmaf(s4.w, xr.y, acc[3][1]);
            acc[3][2] = fmaf(s4.w, xr.z, acc[3][2]);
            acc[3][3] = fmaf(s4.w, xr.w, acc[3][3]);
        }
#pragma unroll
        for (int q = 0; q < 4; ++q) {
            float4 v = make_float4(acc[q][0], acc[q][1], acc[q][2], acc[q][3]);
            *reinterpret_cast<float4*>(
                g_y + (size_t)(t0 + i0 + q) * DINNER + h * HDIM + p0) = v;
        }
    }

    // chunk_state[n][p] = sum_k bw[k][n] * x[k][p]
    {
        int n  = tid >> 4;
        int p0 = (tid & 15) * 4;
        float4 acc = make_float4(0.f, 0.f, 0.f, 0.f);
        for (int k = 0; k < 64; ++k) {
            float bwv = Csh[k][n];
            float4 xr = *reinterpret_cast<const float4*>(&xs[k][p0]);
            acc.x = fmaf(bwv, xr.x, acc.x);
            acc.y = fmaf(bwv, xr.y, acc.y);
            acc.z = fmaf(bwv, xr.z, acc.z);
            acc.w = fmaf(bwv, xr.w, acc.w);
        }
        *reinterpret_cast<float4*>(
            g_cs + (size_t)bid * (DSTATE * HDIM) + n * HDIM + p0) = acc;
    }
}

// ---------------------------------------------------------------------------
// Sequential scan over chunks: grid = BATCH*NHEADS*4, 1 elem/thread
// ---------------------------------------------------------------------------
__global__ void __launch_bounds__(256)
scan_kernel()
{
    const int g   = blockIdx.x;
    const int bh  = g >> 2;
    const int seg = g & 3;
    const int b   = bh >> 4;
    const int h   = bh & 15;
    const int e   = seg * 256 + threadIdx.x;

    const int    chid0  = (b * NCHUNK) * NHEADS + h;
    const size_t base   = (size_t)chid0 * (DSTATE * HDIM);
    const size_t stride = (size_t)NHEADS * DSTATE * HDIM;

    float hv  = 0.f;
    float cur = g_cs[base + e];
    float d   = g_cdecay[chid0];
    for (int c = 0; c < NCHUNK; ++c) {
        float nxt = 0.f, dn = 0.f;
        if (c + 1 < NCHUNK) {
            nxt = g_cs[base + stride * (c + 1) + e];
            dn  = g_cdecay[chid0 + (c + 1) * NHEADS];
        }
        g_hs[base + stride * c + e] = hv;
        hv = fmaf(d, hv, cur);
        cur = nxt; d = dn;
    }
}

// ---------------------------------------------------------------------------
// Cross-chunk + skip
// ---------------------------------------------------------------------------
__global__ void __launch_bounds__(256, 2)
cross_kernel(const float* __restrict__ D_param)
{
    const int bid = blockIdx.x;
    const int h   = bid & 15;
    const int bc  = bid >> 4;
    const int t0  = bc * CHUNK;
    const int tid = threadIdx.x;

    __shared__ float hs[16][68];
    __shared__ float Csh[64][20];
    __shared__ float dacs[64];

    {
        int n = tid >> 4, pg = tid & 15;
        float4 v = *reinterpret_cast<const float4*>(
            g_hs + (size_t)bid * (DSTATE * HDIM) + n * HDIM + pg * 4);
        *reinterpret_cast<float4*>(&hs[n][pg * 4]) = v;
    }
    {
        int k = tid >> 2, n4 = tid & 3;
        float4 vc = *reinterpret_cast<const float4*>(
            g_proj + (size_t)(t0 + k) * PROJ + OFF_C + h * DSTATE + n4 * 4);
        *reinterpret_cast<float4*>(&Csh[k][n4 * 4]) = vc;
    }
    if (tid < 64) dacs[tid] = g_dacs[(size_t)(t0 + tid) * NHEADS + h];
    __syncthreads();

    int i  = tid >> 2;
    int p0 = (tid & 3) * 16;
    float ci[16];
#pragma unroll
    for (int n = 0; n < 16; ++n) ci[n] = Csh[i][n];
    float e  = expf(dacs[i]);
    float dp = D_param[h];

    size_t t = (size_t)(t0 + i);
    const float* xrow = g_proj + t * PROJ + OFF_XP + h * HDIM;
    float* yrow = g_y + t * DINNER + h * HDIM;
#pragma unroll
    for (int g4 = 0; g4 < 4; ++g4) {
        int p = p0 + g4 * 4;
        float4 yv = *reinterpret_cast<const float4*>(yrow + p);
        float4 xv = *reinterpret_cast<const float4*>(xrow + p);
        float a0 = 0.f, a1 = 0.f, a2 = 0.f, a3 = 0.f;
#pragma unroll
        for (int n = 0; n < 16; ++n) {
            float c = ci[n];
            a0 = fmaf(c, hs[n][p + 0], a0);
            a1 = fmaf(c, hs[n][p + 1], a1);
            a2 = fmaf(c, hs[n][p + 2], a2);
            a3 = fmaf(c, hs[n][p + 3], a3);
        }
        float4 o;
        o.x = yv.x + e * a0 + dp * xv.x;
        o.y = yv.y + e * a1 + dp * xv.y;
        o.z = yv.z + e * a2 + dp * xv.z;
        o.w = yv.w + e * a3 + dp * xv.w;
        *reinterpret_cast<float4*>(yrow + p) = o;
    }
}

// ---------------------------------------------------------------------------
// RMS norm + SiLU gate -> yg packed (bf16 hi/lo, swizzled A-tile layout)
// ---------------------------------------------------------------------------
__global__ void __launch_bounds__(256)
norm_kernel(const float* __restrict__ norm_w)
{
    const int t   = blockIdx.x;
    const int tid = threadIdx.x;

    float4 v = reinterpret_cast<const float4*>(g_y + (size_t)t * DINNER)[tid];
    float ss = v.x * v.x + v.y * v.y + v.z * v.z + v.w * v.w;
#pragma unroll
    for (int off = 16; off > 0; off >>= 1)
        ss += __shfl_xor_sync(0xffffffffu, ss, off);

    __shared__ float red[8];
    __shared__ float s_inv;
    if ((tid & 31) == 0) red[tid >> 5] = ss;
    __syncthreads();
    if (tid == 0) {
        float s = 0.f;
#pragma unroll
        for (int i = 0; i < 8; ++i) s += red[i];
        s_inv = rsqrtf(s * (1.f / DINNER) + 1e-6f);
    }
    __syncthreads();
    float inv = s_inv;

    const float* zrow = g_proj + (size_t)t * PROJ + OFF_Z;
    int c = tid * 4;
    float4 z4 = *reinterpret_cast<const float4*>(zrow + c);
    float4 w4 = *reinterpret_cast<const float4*>(norm_w + c);
    float4 o;
    o.x = v.x * inv * w4.x * (z4.x / (1.f + expf(-z4.x)));
    o.y = v.y * inv * w4.y * (z4.y / (1.f + expf(-z4.y)));
    o.z = v.z * inv * w4.z * (z4.z / (1.f + expf(-z4.z)));
    o.w = v.w * inv * w4.w * (z4.w / (1.f + expf(-z4.w)));

    uint2 h, l;
    split4(o, h, l);
    size_t  blk = APK_BLK(t >> 8, c >> 6);
    uint32_t off = (uint32_t)((t & 255) * 128 + (c & 63) * 2);
    off = SW128(off);
    *reinterpret_cast<uint2*>(g_yghi + blk + off) = h;
    *reinterpret_cast<uint2*>(g_yglo + blk + off) = l;
}

// ---------------------------------------------------------------------------
// Launch — proj GEMM at slot #4 (profiled)
// ---------------------------------------------------------------------------
extern "C" void kernel_launch(void* const* d_in, const int* in_sizes, int n_in,
                              void* d_out, int out_size)
{
    const float* x      = (const float*)d_in[0];
    const float* W_in   = (const float*)d_in[1];
    const float* dt_W   = (const float*)d_in[2];
    const float* dt_b   = (const float*)d_in[3];
    const float* A_log  = (const float*)d_in[4];
    const float* D_par  = (const float*)d_in[5];
    const float* W_out  = (const float*)d_in[6];
    const float* norm_w = (const float*)d_in[7];
    float* out = (float*)d_out;

    float* proj_ptr = nullptr;
    uint8_t *xhi, *xlo, *winhi, *winlo, *wouthi, *woutlo, *yghi, *yglo;
    cudaGetSymbolAddress((void**)&proj_ptr, g_proj);
    cudaGetSymbolAddress((void**)&xhi, g_xhi);
    cudaGetSymbolAddress((void**)&xlo, g_xlo);
    cudaGetSymbolAddress((void**)&winhi, g_winhi);
    cudaGetSymbolAddress((void**)&winlo, g_winlo);
    cudaGetSymbolAddress((void**)&wouthi, g_wouthi);
    cudaGetSymbolAddress((void**)&woutlo, g_woutlo);
    cudaGetSymbolAddress((void**)&yghi, g_yghi);
    cudaGetSymbolAddress((void**)&yglo, g_yglo);

    cudaFuncSetAttribute(gemm_tc, cudaFuncAttributeMaxDynamicSharedMemorySize, GEMM_SMEM_BYTES);

    // 1) pack x
    {
        int n4 = TOKENS * DMODEL / 4;
        split_pack_A<<<(n4 + 255) / 256, 256>>>(x, xhi, xlo, n4);
    }
    // 2) pack W_in (padded to 2688 rows)
    {
        int n4 = PROJPAD * DMODEL / 4;
        split_pack_B<<<(n4 + 255) / 256, 256>>>(W_in, winhi, winlo, PROJ, n4);
    }
    // 3) pack W_out
    {
        int n4 = DMODEL * DINNER / 4;
        split_pack_B<<<(n4 + 255) / 256, 256>>>(W_out, wouthi, woutlo, DMODEL, n4);
    }
    // 4) proj = x @ W_in^T   [16384, 2576]   <- profiled slot
    {
        dim3 grid(PROJPAD / 128, TOKENS / 256);
        gemm_tc<<<grid, 256, GEMM_SMEM_BYTES>>>(xhi, xlo, winhi, winlo,
                                                proj_ptr, DMODEL / 64, PROJ, PROJ);
    }
    // 5) intra-chunk (+dt)
    intra_kernel<<<BATCH * NCHUNK * NHEADS, 256>>>(dt_W, dt_b, A_log);
    // 6) chunk scan
    scan_kernel<<<BATCH * NHEADS * 4, 256>>>();
    // 7) cross-chunk + skip
    cross_kernel<<<BATCH * NCHUNK * NHEADS, 256>>>(D_par);
    // 8) RMS norm + gate -> packed bf16 hi/lo
    norm_kernel<<<TOKENS, 256>>>(norm_w);
    // 9) out = yg @ W_out^T  [16384, 1024]
    {
        dim3 grid(DMODEL / 128, TOKENS / 256);
        gemm_tc<<<grid, 256, GEMM_SMEM_BYTES>>>(yghi, yglo, wouthi, woutlo,
                                                out, DINNER / 64, DMODEL, DMODEL);
    }
}